// round 7
// baseline (speedup 1.0000x reference)
#include <cuda_runtime.h>
#include <cuda_bf16.h>
#include <math.h>
#include <cstdint>

using bf16 = __nv_bfloat16;
typedef unsigned long long u64;

// ---------------- problem constants ----------------
#define BB 2
#define HH 256
#define WWID 256
#define LL 65536          // H*W
#define CC 180
#define NHD 6
#define HDIM 30
#define NWIN 2048         // B * (H/8) * (W/8)
#define CFFN 360
#define C8 22             // 180 // 8
#define MROWS (BB*LL)     // 131072
#define KP1 192           // padded K for K=180
#define KP2 384           // padded K for K=360

#define FMA2(d, a, b, c) \
    asm("fma.rn.f32x2 %0, %1, %2, %3;" : "=l"(d) : "l"(a), "l"(b), "l"(c))

// ---------------- scratch (device globals, no allocation) ----------------
__device__ bf16  g_qkvb [(size_t)MROWS*540];   // qkv bf16; reused for h (stride 384)
__device__ float g_conv [(size_t)MROWS*CC];
__device__ float g_xmid [(size_t)MROWS*CC];
__device__ float g_pooled[BB*CC];
__device__ float g_cm    [BB*CC];
__device__ bf16  g_n1b[(size_t)MROWS*KP1];     // ln1 out (bf16, padded)
__device__ bf16  g_n2b[(size_t)MROWS*KP1];     // attn out, then n2 (bf16, padded)
__device__ bf16  g_hsb[(size_t)MROWS*KP2];     // ffn dwconv out (bf16, padded)
__device__ bf16  g_wb [294912];                // padded bf16 weights

#define WB_QKV  0        // 576 x 192
#define WB_PROJ 110592   // 192 x 192
#define WB_FFN1 147456   // 384 x 192
#define WB_FFN2 221184   // 192 x 384

__device__ __forceinline__ float gelu_exact(float x) {
    return 0.5f * x * (1.0f + erff(x * 0.70710678118654752f));
}

// ---------------- weight convert + pad: src[N][K] fp32 -> dst[NP][KP] bf16 ----------------
__global__ void convw_kernel(const float* __restrict__ src, bf16* __restrict__ dst,
                             int N, int K, int NP, int KP) {
    int i = blockIdx.x * 256 + threadIdx.x;
    if (i < NP * KP) {
        int n = i / KP, k = i - n * KP;
        float v = (n < N && k < K) ? src[n * K + k] : 0.f;
        dst[i] = __float2bfloat16(v);
    }
}

// ---------------- LayerNorm (emits bf16, KP1-padded) ----------------
__global__ void ln_kernel(const float* __restrict__ x,
                          const float* __restrict__ g,
                          const float* __restrict__ b,
                          bf16* __restrict__ out) {
    int row = blockIdx.x * 4 + (threadIdx.x >> 5);
    int lane = threadIdx.x & 31;
    const float* xr = x + (size_t)row * CC;
    float v[6];
    float s = 0.f;
#pragma unroll
    for (int i = 0; i < 6; i++) {
        int c = lane + 32 * i;
        v[i] = (c < CC) ? xr[c] : 0.f;
        s += v[i];
    }
#pragma unroll
    for (int o = 16; o; o >>= 1) s += __shfl_xor_sync(0xffffffffu, s, o);
    float mean = s * (1.f / CC);
    float vs = 0.f;
#pragma unroll
    for (int i = 0; i < 6; i++) {
        int c = lane + 32 * i;
        if (c < CC) { float d = v[i] - mean; vs += d * d; }
    }
#pragma unroll
    for (int o = 16; o; o >>= 1) vs += __shfl_xor_sync(0xffffffffu, vs, o);
    float rstd = rsqrtf(vs * (1.f / CC) + 1e-5f);
    bf16* orow = out + (size_t)row * KP1;
#pragma unroll
    for (int i = 0; i < 6; i++) {
        int c = lane + 32 * i;
        float val = (c < CC) ? (v[i] - mean) * rstd * g[c] + b[c] : 0.f;
        orow[c] = __float2bfloat16(val);
    }
}

// ======== A-resident persistent GEMM: A[128xKP] in smem, loop n-tiles ========
// EPI: 0=none 2=gelu 3=+residual(fp32) ; OBF: 1 -> bf16 out (stride OS), 0 -> fp32 out
template <int EPI, int OBF>
__global__ void __launch_bounds__(256) mma_gemm_p(const bf16* __restrict__ A,
                                                  const bf16* __restrict__ Wt,
                                                  const float* __restrict__ res,
                                                  float* __restrict__ Cf,
                                                  bf16* __restrict__ Cb,
                                                  int N, int KP, int OS, int NT) {
    extern __shared__ bf16 sm[];
    const int AST = KP + 8;               // row stride (bf16)
    bf16* As = sm;                        // [128][AST]
    bf16* Bs = sm + 128 * AST;            // [2][64][AST]
    const int tid  = threadIdx.x;
    const int row0 = blockIdx.x * 128;
    const int wid  = tid >> 5;
    const int lane = tid & 31;
    const int warpm = wid >> 1;
    const int warpn = wid & 1;
    const int gr = lane >> 2;
    const int cq = lane & 3;
    const int NS = KP >> 4;               // k16 steps
    const int KC = KP >> 3;               // 16B chunks per row

    uint32_t sA = (uint32_t)__cvta_generic_to_shared(As);
    uint32_t sB = (uint32_t)__cvta_generic_to_shared(Bs);

    for (int cid = tid; cid < 128 * KC; cid += 256) {
        int m = cid / KC, kc = (cid - m * KC) << 3;
        const bf16* g = A + (size_t)(row0 + m) * KP + kc;
        uint32_t sa = sA + (uint32_t)(m * AST + kc) * 2;
        asm volatile("cp.async.cg.shared.global [%0], [%1], 16;\n" :: "r"(sa), "l"(g));
    }
    auto issueB = [&](int t) {
        uint32_t bbase = sB + (t & 1) * (64 * AST * 2);
        const bf16* wt0 = Wt + (size_t)(t * 64) * KP;
        for (int cid = tid; cid < 64 * KC; cid += 256) {
            int n = cid / KC, kc = (cid - n * KC) << 3;
            uint32_t sb = bbase + (uint32_t)(n * AST + kc) * 2;
            asm volatile("cp.async.cg.shared.global [%0], [%1], 16;\n"
                         :: "r"(sb), "l"(wt0 + (size_t)n * KP + kc));
        }
        asm volatile("cp.async.commit_group;\n");
    };

    issueB(0);

    for (int t = 0; t < NT; t++) {
        if (t + 1 < NT) { issueB(t + 1); asm volatile("cp.async.wait_group 1;\n"); }
        else            { asm volatile("cp.async.wait_group 0;\n"); }
        __syncthreads();

        float acc[2][4][4];
#pragma unroll
        for (int a = 0; a < 2; a++)
#pragma unroll
            for (int b = 0; b < 4; b++)
#pragma unroll
                for (int c = 0; c < 4; c++) acc[a][b][c] = 0.f;

        const bf16* Bb = Bs + (t & 1) * (64 * AST);
        for (int ks = 0; ks < NS; ks++) {
            uint32_t afr[2][4], bfr[4][2];
#pragma unroll
            for (int mt = 0; mt < 2; mt++) {
                const bf16* p = As + (warpm * 32 + mt * 16 + gr) * AST + ks * 16 + cq * 2;
                afr[mt][0] = *(const uint32_t*)p;
                afr[mt][1] = *(const uint32_t*)(p + 8 * AST);
                afr[mt][2] = *(const uint32_t*)(p + 8);
                afr[mt][3] = *(const uint32_t*)(p + 8 * AST + 8);
            }
#pragma unroll
            for (int nt = 0; nt < 4; nt++) {
                const bf16* p = Bb + (warpn * 32 + nt * 8 + gr) * AST + ks * 16 + cq * 2;
                bfr[nt][0] = *(const uint32_t*)p;
                bfr[nt][1] = *(const uint32_t*)(p + 8);
            }
#pragma unroll
            for (int mt = 0; mt < 2; mt++)
#pragma unroll
                for (int nt = 0; nt < 4; nt++) {
                    asm volatile(
                        "mma.sync.aligned.m16n8k16.row.col.f32.bf16.bf16.f32 "
                        "{%0,%1,%2,%3},{%4,%5,%6,%7},{%8,%9},{%0,%1,%2,%3};\n"
                        : "+f"(acc[mt][nt][0]), "+f"(acc[mt][nt][1]),
                          "+f"(acc[mt][nt][2]), "+f"(acc[mt][nt][3])
                        : "r"(afr[mt][0]), "r"(afr[mt][1]), "r"(afr[mt][2]), "r"(afr[mt][3]),
                          "r"(bfr[nt][0]), "r"(bfr[nt][1]));
                }
        }

        const int col0 = t * 64;
#pragma unroll
        for (int mt = 0; mt < 2; mt++) {
            int r0 = row0 + warpm * 32 + mt * 16 + gr;
#pragma unroll
            for (int nt = 0; nt < 4; nt++) {
                int cb = col0 + warpn * 32 + nt * 8 + cq * 2;
                if (cb < N) {
                    float v00 = acc[mt][nt][0], v01 = acc[mt][nt][1];
                    float v10 = acc[mt][nt][2], v11 = acc[mt][nt][3];
                    if (EPI == 2) { v00 = gelu_exact(v00); v01 = gelu_exact(v01);
                                    v10 = gelu_exact(v10); v11 = gelu_exact(v11); }
                    if (EPI == 3) {
                        const float2 r0v = *(const float2*)&res[(size_t)r0 * OS + cb];
                        const float2 r1v = *(const float2*)&res[(size_t)(r0 + 8) * OS + cb];
                        v00 += r0v.x; v01 += r0v.y; v10 += r1v.x; v11 += r1v.y;
                    }
                    if (OBF) {
                        __nv_bfloat162 p0, p1;
                        p0.x = __float2bfloat16(v00); p0.y = __float2bfloat16(v01);
                        p1.x = __float2bfloat16(v10); p1.y = __float2bfloat16(v11);
                        *(__nv_bfloat162*)&Cb[(size_t)r0 * OS + cb]       = p0;
                        *(__nv_bfloat162*)&Cb[(size_t)(r0 + 8) * OS + cb] = p1;
                    } else {
                        *(float2*)&Cf[(size_t)r0 * OS + cb]       = make_float2(v00, v01);
                        *(float2*)&Cf[(size_t)(r0 + 8) * OS + cb] = make_float2(v10, v11);
                    }
                }
            }
        }
        __syncthreads();
    }
}

// ======== proj GEMM + fused bias + residual-combine + LayerNorm2 ========
// C = A @ Wproj^T + bias; xmid = x + C*cm + conv; n2 = bf16(LN(xmid))
__global__ void __launch_bounds__(256) mma_gemm_ln(const bf16* __restrict__ A,
                                                   const bf16* __restrict__ Wt,
                                                   const float* __restrict__ bias,
                                                   const float* __restrict__ x,
                                                   const float* __restrict__ conv,
                                                   const float* __restrict__ cm,
                                                   const float* __restrict__ lg,
                                                   const float* __restrict__ lb,
                                                   float* __restrict__ xmid,
                                                   bf16* __restrict__ n2) {
    const int AST = KP1 + 8;              // 200
    extern __shared__ bf16 sm[];
    bf16* As = sm;                        // [128][200]
    bf16* Bs = sm + 128 * AST;            // [2][64][200]
    float* rs = (float*)(sm + 128 * AST + 2 * 64 * AST);   // [128] row sums
    float* rq = rs + 128;                                  // [128] row sumsq
    const int tid  = threadIdx.x;
    const int row0 = blockIdx.x * 128;
    const int wid  = tid >> 5;
    const int lane = tid & 31;
    const int warpm = wid >> 1;
    const int warpn = wid & 1;
    const int gr = lane >> 2;
    const int cq = lane & 3;
    const int NS = KP1 >> 4;
    const int KC = KP1 >> 3;
    const int NT = 3;

    if (tid < 256) ((float*)(sm + 128 * AST + 2 * 64 * AST))[tid] = 0.f;

    uint32_t sA = (uint32_t)__cvta_generic_to_shared(As);
    uint32_t sB = (uint32_t)__cvta_generic_to_shared(Bs);

    for (int cid = tid; cid < 128 * KC; cid += 256) {
        int m = cid / KC, kc = (cid - m * KC) << 3;
        const bf16* g = A + (size_t)(row0 + m) * KP1 + kc;
        uint32_t sa = sA + (uint32_t)(m * AST + kc) * 2;
        asm volatile("cp.async.cg.shared.global [%0], [%1], 16;\n" :: "r"(sa), "l"(g));
    }
    auto issueB = [&](int t) {
        uint32_t bbase = sB + (t & 1) * (64 * AST * 2);
        const bf16* wt0 = Wt + (size_t)(t * 64) * KP1;
        for (int cid = tid; cid < 64 * KC; cid += 256) {
            int n = cid / KC, kc = (cid - n * KC) << 3;
            uint32_t sb = bbase + (uint32_t)(n * AST + kc) * 2;
            asm volatile("cp.async.cg.shared.global [%0], [%1], 16;\n"
                         :: "r"(sb), "l"(wt0 + (size_t)n * KP1 + kc));
        }
        asm volatile("cp.async.commit_group;\n");
    };

    issueB(0);

    for (int t = 0; t < NT; t++) {
        if (t + 1 < NT) { issueB(t + 1); asm volatile("cp.async.wait_group 1;\n"); }
        else            { asm volatile("cp.async.wait_group 0;\n"); }
        __syncthreads();

        float acc[2][4][4];
#pragma unroll
        for (int a = 0; a < 2; a++)
#pragma unroll
            for (int b = 0; b < 4; b++)
#pragma unroll
                for (int c = 0; c < 4; c++) acc[a][b][c] = 0.f;

        const bf16* Bb = Bs + (t & 1) * (64 * AST);
        for (int ks = 0; ks < NS; ks++) {
            uint32_t afr[2][4], bfr[4][2];
#pragma unroll
            for (int mt = 0; mt < 2; mt++) {
                const bf16* p = As + (warpm * 32 + mt * 16 + gr) * AST + ks * 16 + cq * 2;
                afr[mt][0] = *(const uint32_t*)p;
                afr[mt][1] = *(const uint32_t*)(p + 8 * AST);
                afr[mt][2] = *(const uint32_t*)(p + 8);
                afr[mt][3] = *(const uint32_t*)(p + 8 * AST + 8);
            }
#pragma unroll
            for (int nt = 0; nt < 4; nt++) {
                const bf16* p = Bb + (warpn * 32 + nt * 8 + gr) * AST + ks * 16 + cq * 2;
                bfr[nt][0] = *(const uint32_t*)p;
                bfr[nt][1] = *(const uint32_t*)(p + 8);
            }
#pragma unroll
            for (int mt = 0; mt < 2; mt++)
#pragma unroll
                for (int nt = 0; nt < 4; nt++) {
                    asm volatile(
                        "mma.sync.aligned.m16n8k16.row.col.f32.bf16.bf16.f32 "
                        "{%0,%1,%2,%3},{%4,%5,%6,%7},{%8,%9},{%0,%1,%2,%3};\n"
                        : "+f"(acc[mt][nt][0]), "+f"(acc[mt][nt][1]),
                          "+f"(acc[mt][nt][2]), "+f"(acc[mt][nt][3])
                        : "r"(afr[mt][0]), "r"(afr[mt][1]), "r"(afr[mt][2]), "r"(afr[mt][3]),
                          "r"(bfr[nt][0]), "r"(bfr[nt][1]));
                }
        }

        const int col0 = t * 64;
#pragma unroll
        for (int mt = 0; mt < 2; mt++) {
            int r0 = row0 + warpm * 32 + mt * 16 + gr;
            int bb = r0 >> 16;
            float s0 = 0.f, q0 = 0.f, s1 = 0.f, q1 = 0.f;
#pragma unroll
            for (int nt = 0; nt < 4; nt++) {
                int cb = col0 + warpn * 32 + nt * 8 + cq * 2;
                if (cb < CC) {
                    float b0 = bias[cb], b1 = bias[cb + 1];
                    float cm0 = cm[bb * CC + cb], cm1 = cm[bb * CC + cb + 1];
                    const float2 x0v = *(const float2*)&x[(size_t)r0 * CC + cb];
                    const float2 x1v = *(const float2*)&x[(size_t)(r0 + 8) * CC + cb];
                    const float2 c0v = *(const float2*)&conv[(size_t)r0 * CC + cb];
                    const float2 c1v = *(const float2*)&conv[(size_t)(r0 + 8) * CC + cb];
                    float v00 = x0v.x + (acc[mt][nt][0] + b0) * cm0 + c0v.x;
                    float v01 = x0v.y + (acc[mt][nt][1] + b1) * cm1 + c0v.y;
                    float v10 = x1v.x + (acc[mt][nt][2] + b0) * cm0 + c1v.x;
                    float v11 = x1v.y + (acc[mt][nt][3] + b1) * cm1 + c1v.y;
                    *(float2*)&xmid[(size_t)r0 * CC + cb]       = make_float2(v00, v01);
                    *(float2*)&xmid[(size_t)(r0 + 8) * CC + cb] = make_float2(v10, v11);
                    s0 += v00 + v01; q0 += v00 * v00 + v01 * v01;
                    s1 += v10 + v11; q1 += v10 * v10 + v11 * v11;
                }
            }
#pragma unroll
            for (int o = 1; o <= 2; o <<= 1) {
                s0 += __shfl_xor_sync(0xffffffffu, s0, o);
                q0 += __shfl_xor_sync(0xffffffffu, q0, o);
                s1 += __shfl_xor_sync(0xffffffffu, s1, o);
                q1 += __shfl_xor_sync(0xffffffffu, q1, o);
            }
            if (cq == 0) {
                int lr = r0 - row0;
                atomicAdd(&rs[lr], s0);     atomicAdd(&rq[lr], q0);
                atomicAdd(&rs[lr + 8], s1); atomicAdd(&rq[lr + 8], q1);
            }
        }
        __syncthreads();
    }

    // row stats
    if (tid < 128) {
        float mean = rs[tid] * (1.f / CC);
        float var  = rq[tid] * (1.f / CC) - mean * mean;
        rs[tid] = mean;
        rq[tid] = rsqrtf(var + 1e-5f);
    }
    __syncthreads();

    // LN output pass (xmid re-read hits L1/L2)
    for (int idx = tid; idx < 128 * CC; idx += 256) {
        int rr = idx / CC, c = idx - rr * CC;
        float xv = xmid[(size_t)(row0 + rr) * CC + c];
        float nv = (xv - rs[rr]) * rq[rr] * lg[c] + lb[c];
        n2[(size_t)(row0 + rr) * KP1 + c] = __float2bfloat16(nv);
    }
}

// ---------------- window attention (bf16 qkv, packed f32x2 math) ----------------
__global__ void attn_kernel(const bf16* __restrict__ qkv,
                            const float* __restrict__ b_rel,
                            bf16* __restrict__ out) {
    extern __shared__ float kv[];   // [64][360]: cols 0..179 = K, 180..359 = V
    const int w = blockIdx.x;
    const int b  = w >> 10;
    const int wy = (w & 1023) >> 5;
    const int wx = w & 31;
    const int tid = threadIdx.x;    // 384

    for (int idx = tid; idx < 64 * 180; idx += 384) {
        int t = idx / 180, c2 = idx - t * 180;
        int ty = t >> 3, tx = t & 7;
        size_t row = ((size_t)b << 16) + (size_t)(wy * 8 + ty) * 256 + (wx * 8 + tx);
        __nv_bfloat162 v = *(const __nv_bfloat162*)&qkv[row * 540 + 180 + 2 * c2];
        kv[t * 360 + 2 * c2]     = __bfloat162float(v.x);
        kv[t * 360 + 2 * c2 + 1] = __bfloat162float(v.y);
    }
    for (int idx = tid; idx < 64 * 12; idx += 384) {
        int t = idx / 12, c = idx - t * 12;
        int ty = t >> 3, tx = t & 7;
        size_t row = ((size_t)b << 16) + (size_t)(wy * 8 + ty) * 256 + (wx * 8 + tx);
        out[row * KP1 + 180 + c] = __float2bfloat16(0.f);
    }
    __syncthreads();

    const int h = tid / 64;
    const int t = tid & 63;
    const int ty = t >> 3, tx = t & 7;
    size_t row = ((size_t)b << 16) + (size_t)(wy * 8 + ty) * 256 + (wx * 8 + tx);

    u64 qp[15];
    const __nv_bfloat162* qsrc = (const __nv_bfloat162*)(qkv + row * 540 + h * HDIM);
    const float scale = 0.18257418583505536f;  // 30^-0.5
#pragma unroll
    for (int d = 0; d < 15; d++) {
        __nv_bfloat162 qv = qsrc[d];
        float qx = __bfloat162float(qv.x) * scale;
        float qy = __bfloat162float(qv.y) * scale;
        asm("mov.b64 %0, {%1, %2};" : "=l"(qp[d])
            : "r"(__float_as_uint(qx)), "r"(__float_as_uint(qy)));
    }

    const float* br = b_rel + h * 4096 + t * 64;
    float l = 0.f;
    u64 o2[15];
#pragma unroll
    for (int d = 0; d < 15; d++) o2[d] = 0ULL;

    for (int j = 0; j < 64; j++) {
        const u64* kj = (const u64*)&kv[j * 360 + h * HDIM];
        u64 acc2 = 0ULL;
#pragma unroll
        for (int d = 0; d < 15; d++) FMA2(acc2, qp[d], kj[d], acc2);
        uint32_t alo, ahi;
        asm("mov.b64 {%0, %1}, %2;" : "=r"(alo), "=r"(ahi) : "l"(acc2));
        float s = br[j] + __uint_as_float(alo) + __uint_as_float(ahi);
        float p = __expf(s);
        l += p;
        u64 pp;
        asm("mov.b64 %0, {%1, %1};" : "=l"(pp) : "r"(__float_as_uint(p)));
        const u64* vj = (const u64*)&kv[j * 360 + 180 + h * HDIM];
#pragma unroll
        for (int d = 0; d < 15; d++) FMA2(o2[d], pp, vj[d], o2[d]);
    }
    float inv = 1.f / l;
    bf16* op = out + row * KP1 + h * HDIM;
#pragma unroll
    for (int d = 0; d < 15; d++) {
        uint32_t lo, hi;
        asm("mov.b64 {%0, %1}, %2;" : "=r"(lo), "=r"(hi) : "l"(o2[d]));
        op[2 * d]     = __float2bfloat16(__uint_as_float(lo) * inv);
        op[2 * d + 1] = __float2bfloat16(__uint_as_float(hi) * inv);
    }
}

// ---------------- depthwise 3x3 SAME conv, x-tiled (TX) + rolling-y ----------------
template <typename Tin, typename Tout, int CD, int INS, int OUTS, int GELU, int POOL, int TX>
__global__ void dwconv_tile(const Tin* __restrict__ in,
                            const float* __restrict__ k9,
                            Tout* __restrict__ out,
                            float* __restrict__ pooled) {
    const int c  = threadIdx.x;
    const int x0 = blockIdx.x * TX;
    const int y0 = blockIdx.y * 64;
    const int b  = blockIdx.z;
    float w[9];
#pragma unroll
    for (int i = 0; i < 9; i++) w[i] = k9[c * 9 + i];

    const size_t base = ((size_t)b << 16);
    float r[TX + 2], s[TX + 2], t[TX + 2];

    auto loadrow = [&](int yy, float* dst) {
#pragma unroll
        for (int i = 0; i < TX + 2; i++) {
            int xx = x0 - 1 + i;
            dst[i] = (xx >= 0 && xx < WWID)
                     ? (float)in[(base + (size_t)yy * 256 + xx) * INS + c] : 0.f;
        }
    };

    if (y0 > 0) loadrow(y0 - 1, r);
    else {
#pragma unroll
        for (int i = 0; i < TX + 2; i++) r[i] = 0.f;
    }
    loadrow(y0, s);

    float psum = 0.f;
    for (int yy = y0; yy < y0 + 64; yy++) {
        if (yy + 1 < HH) loadrow(yy + 1, t);
        else {
#pragma unroll
            for (int i = 0; i < TX + 2; i++) t[i] = 0.f;
        }
#pragma unroll
        for (int j = 0; j < TX; j++) {
            float acc = r[j] * w[0] + r[j + 1] * w[1] + r[j + 2] * w[2]
                      + s[j] * w[3] + s[j + 1] * w[4] + s[j + 2] * w[5]
                      + t[j] * w[6] + t[j + 1] * w[7] + t[j + 2] * w[8];
            if (GELU) acc = gelu_exact(acc);
            if (POOL) psum += acc;
            size_t op = (base + (size_t)yy * 256 + x0 + j) * OUTS;
            out[op + c] = (Tout)acc;
            if (OUTS > CD && c < OUTS - CD) out[op + CD + c] = (Tout)0.f;
        }
#pragma unroll
        for (int i = 0; i < TX + 2; i++) { r[i] = s[i]; s[i] = t[i]; }
    }
    if (POOL) atomicAdd(&pooled[b * CD + c], psum * (1.f / (float)LL));
}

// ---------------- channel gate ----------------
__global__ void gate_kernel(const float* __restrict__ pooled,
                            const float* __restrict__ w1,
                            const float* __restrict__ w2,
                            float* __restrict__ cm) {
    const int b = blockIdx.x;
    const int tid = threadIdx.x;   // 180
    __shared__ float t1[C8];
    if (tid < C8) {
        float s = 0.f;
        for (int c = 0; c < CC; c++) s += pooled[b * CC + c] * w1[tid * CC + c];
        t1[tid] = gelu_exact(s);
    }
    __syncthreads();
    float s = 0.f;
#pragma unroll
    for (int j = 0; j < C8; j++) s += t1[j] * w2[tid * C8 + j];
    cm[b * CC + tid] = 1.f / (1.f + expf(-s));
}

// ---------------- launch ----------------
extern "C" void kernel_launch(void* const* d_in, const int* in_sizes, int n_in,
                              void* d_out, int out_size) {
    const float* x       = (const float*)d_in[0];
    const float* w_qkv   = (const float*)d_in[1];
    const float* b_rel   = (const float*)d_in[2];
    const float* w_proj  = (const float*)d_in[3];
    const float* b_proj  = (const float*)d_in[4];
    const float* conv_dw = (const float*)d_in[5];
    const float* cg_w1   = (const float*)d_in[6];
    const float* cg_w2   = (const float*)d_in[7];
    const float* ffn_w1  = (const float*)d_in[8];
    const float* ffn_dw  = (const float*)d_in[9];
    const float* ffn_w2  = (const float*)d_in[10];
    const float* n1_g    = (const float*)d_in[11];
    const float* n1_b    = (const float*)d_in[12];
    const float* n2_g    = (const float*)d_in[13];
    const float* n2_b    = (const float*)d_in[14];
    float* out = (float*)d_out;

    float *conv, *xmid, *pooled, *cm;
    bf16 *qkvb, *n1b, *n2b, *hsb, *wb;
    cudaGetSymbolAddress((void**)&qkvb,  g_qkvb);
    cudaGetSymbolAddress((void**)&conv,  g_conv);
    cudaGetSymbolAddress((void**)&xmid,  g_xmid);
    cudaGetSymbolAddress((void**)&pooled, g_pooled);
    cudaGetSymbolAddress((void**)&cm,     g_cm);
    cudaGetSymbolAddress((void**)&n1b,   g_n1b);
    cudaGetSymbolAddress((void**)&n2b,   g_n2b);
    cudaGetSymbolAddress((void**)&hsb,   g_hsb);
    cudaGetSymbolAddress((void**)&wb,    g_wb);

    const int PSMEM1   = (128 * (KP1 + 8) + 2 * 64 * (KP1 + 8)) * (int)sizeof(bf16);  // 102400
    const int PSMEM_LN = PSMEM1 + 256 * (int)sizeof(float);                            // 103424
    const int PSMEM2   = (128 * (KP2 + 8) + 2 * 64 * (KP2 + 8)) * (int)sizeof(bf16);  // 200704
    const int ATTN_SMEM = 64 * 360 * (int)sizeof(float);                               // 92160
    cudaFuncSetAttribute((const void*)mma_gemm_p<0,1>, cudaFuncAttributeMaxDynamicSharedMemorySize, PSMEM1);
    cudaFuncSetAttribute((const void*)mma_gemm_p<2,1>, cudaFuncAttributeMaxDynamicSharedMemorySize, PSMEM1);
    cudaFuncSetAttribute((const void*)mma_gemm_p<3,0>, cudaFuncAttributeMaxDynamicSharedMemorySize, PSMEM2);
    cudaFuncSetAttribute((const void*)mma_gemm_ln,     cudaFuncAttributeMaxDynamicSharedMemorySize, PSMEM_LN);
    cudaFuncSetAttribute((const void*)attn_kernel,     cudaFuncAttributeMaxDynamicSharedMemorySize, ATTN_SMEM);

    // 0) convert + pad weights to bf16
    convw_kernel<<<(576 * 192 + 255) / 256, 256>>>(w_qkv,  wb + WB_QKV,  540, 180, 576, 192);
    convw_kernel<<<(192 * 192 + 255) / 256, 256>>>(w_proj, wb + WB_PROJ, 180, 180, 192, 192);
    convw_kernel<<<(384 * 192 + 255) / 256, 256>>>(ffn_w1, wb + WB_FFN1, 360, 180, 384, 192);
    convw_kernel<<<(192 * 384 + 255) / 256, 256>>>(ffn_w2, wb + WB_FFN2, 180, 360, 192, 384);

    // 1) ln1: x -> n1b (bf16, padded)
    ln_kernel<<<MROWS / 4, 128>>>(x, n1_g, n1_b, n1b);

    // 2) conv branch: dwconv(n1b)+GELU -> conv (fp32), fused mean-pool
    cudaMemsetAsync(pooled, 0, BB * CC * sizeof(float));
    dwconv_tile<bf16, float, CC, KP1, CC, 1, 1, 4><<<dim3(WWID / 4, 4, BB), CC>>>(n1b, conv_dw, conv, pooled);

    // 3) channel gate -> cm
    gate_kernel<<<BB, CC>>>(pooled, cg_w1, cg_w2, cm);

    // 4) qkv = n1 @ w_qkv^T  (bf16 out, N=540, stride 540, 9 n-tiles)
    mma_gemm_p<0,1><<<MROWS / 128, 256, PSMEM1>>>(n1b, wb + WB_QKV, nullptr, nullptr, qkvb, 540, KP1, 540, 9);

    // 5) window attention -> n2b (bf16, padded)
    attn_kernel<<<NWIN, 384, ATTN_SMEM>>>(qkvb, b_rel, n2b);

    // 6) proj + fused residual-combine + ln2 -> xmid (fp32), n2b (bf16)
    mma_gemm_ln<<<MROWS / 128, 256, PSMEM_LN>>>(n2b, wb + WB_PROJ, b_proj,
                                                x, conv, cm, n2_g, n2_b, xmid, n2b);

    // 7) ffn1: h = gelu(n2 @ ffn_w1^T) -> qkvb buffer (bf16, stride 384, N=360)
    mma_gemm_p<2,1><<<MROWS / 128, 256, PSMEM1>>>(n2b, wb + WB_FFN1, nullptr, nullptr, qkvb, 360, KP1, 384, 6);

    // 8) ffn dwconv: hsb = dwconv(h) (bf16 in stride 384, bf16 out padded 384)
    dwconv_tile<bf16, bf16, CFFN, KP2, KP2, 0, 0, 4><<<dim3(WWID / 4, 4, BB), CFFN>>>(qkvb, ffn_dw, hsb, nullptr);

    // 9) ffn2 + residual: out = xmid + hsb @ ffn_w2^T  (persistent, KP=384)
    mma_gemm_p<3,0><<<MROWS / 128, 256, PSMEM2>>>(hsb, wb + WB_FFN2, xmid, out, nullptr, 180, KP2, 180, 3);
}

// round 8
// speedup vs baseline: 1.0082x; 1.0082x over previous
#include <cuda_runtime.h>
#include <cuda_bf16.h>
#include <math.h>
#include <cstdint>

using bf16 = __nv_bfloat16;
typedef unsigned long long u64;

// ---------------- problem constants ----------------
#define BB 2
#define HH 256
#define WWID 256
#define LL 65536          // H*W
#define CC 180
#define NHD 6
#define HDIM 30
#define NWIN 2048         // B * (H/8) * (W/8)
#define CFFN 360
#define C8 22             // 180 // 8
#define MROWS (BB*LL)     // 131072
#define KP1 192           // padded K for K=180
#define KP2 384           // padded K for K=360

#define FMA2(d, a, b, c) \
    asm("fma.rn.f32x2 %0, %1, %2, %3;" : "=l"(d) : "l"(a), "l"(b), "l"(c))

// ---------------- scratch (device globals, no allocation) ----------------
__device__ bf16  g_qkvb [(size_t)MROWS*540];   // qkv bf16; reused for h (stride 384)
__device__ float g_conv [(size_t)MROWS*CC];
__device__ float g_xmid [(size_t)MROWS*CC];
__device__ float g_pooled[BB*CC];
__device__ float g_cm    [BB*CC];
__device__ bf16  g_n1b[(size_t)MROWS*KP1];     // ln1 out (bf16, padded)
__device__ bf16  g_n2b[(size_t)MROWS*KP1];     // attn out, then n2 (bf16, padded)
__device__ bf16  g_hsb[(size_t)MROWS*KP2];     // ffn dwconv out (bf16, padded)
__device__ bf16  g_wb [294912];                // padded bf16 weights

#define WB_QKV  0        // 576 x 192
#define WB_PROJ 110592   // 192 x 192
#define WB_FFN1 147456   // 384 x 192
#define WB_FFN2 221184   // 192 x 384

__device__ __forceinline__ float gelu_exact(float x) {
    return 0.5f * x * (1.0f + erff(x * 0.70710678118654752f));
}

// ---------------- weight convert + pad: src[N][K] fp32 -> dst[NP][KP] bf16 ----------------
__global__ void convw_kernel(const float* __restrict__ src, bf16* __restrict__ dst,
                             int N, int K, int NP, int KP) {
    int i = blockIdx.x * 256 + threadIdx.x;
    if (i < NP * KP) {
        int n = i / KP, k = i - n * KP;
        float v = (n < N && k < K) ? src[n * K + k] : 0.f;
        dst[i] = __float2bfloat16(v);
    }
}

// ---------------- LayerNorm (emits bf16, KP1-padded) ----------------
__global__ void ln_kernel(const float* __restrict__ x,
                          const float* __restrict__ g,
                          const float* __restrict__ b,
                          bf16* __restrict__ out) {
    int row = blockIdx.x * 4 + (threadIdx.x >> 5);
    int lane = threadIdx.x & 31;
    const float* xr = x + (size_t)row * CC;
    float v[6];
    float s = 0.f;
#pragma unroll
    for (int i = 0; i < 6; i++) {
        int c = lane + 32 * i;
        v[i] = (c < CC) ? xr[c] : 0.f;
        s += v[i];
    }
#pragma unroll
    for (int o = 16; o; o >>= 1) s += __shfl_xor_sync(0xffffffffu, s, o);
    float mean = s * (1.f / CC);
    float vs = 0.f;
#pragma unroll
    for (int i = 0; i < 6; i++) {
        int c = lane + 32 * i;
        if (c < CC) { float d = v[i] - mean; vs += d * d; }
    }
#pragma unroll
    for (int o = 16; o; o >>= 1) vs += __shfl_xor_sync(0xffffffffu, vs, o);
    float rstd = rsqrtf(vs * (1.f / CC) + 1e-5f);
    bf16* orow = out + (size_t)row * KP1;
#pragma unroll
    for (int i = 0; i < 6; i++) {
        int c = lane + 32 * i;
        float val = (c < CC) ? (v[i] - mean) * rstd * g[c] + b[c] : 0.f;
        orow[c] = __float2bfloat16(val);
    }
}

// ======== A-resident persistent GEMM (KP1 only): A[128xKP1] in smem, loop n-tiles ========
// EPI: 0=none 2=gelu ; output bf16 with stride OS
template <int EPI>
__global__ void __launch_bounds__(256) mma_gemm_p(const bf16* __restrict__ A,
                                                  const bf16* __restrict__ Wt,
                                                  bf16* __restrict__ Cb,
                                                  int N, int KP, int OS, int NT) {
    extern __shared__ bf16 sm[];
    const int AST = KP + 8;               // row stride (bf16)
    bf16* As = sm;                        // [128][AST]
    bf16* Bs = sm + 128 * AST;            // [2][64][AST]
    const int tid  = threadIdx.x;
    const int row0 = blockIdx.x * 128;
    const int wid  = tid >> 5;
    const int lane = tid & 31;
    const int warpm = wid >> 1;
    const int warpn = wid & 1;
    const int gr = lane >> 2;
    const int cq = lane & 3;
    const int NS = KP >> 4;               // k16 steps
    const int KC = KP >> 3;               // 16B chunks per row

    uint32_t sA = (uint32_t)__cvta_generic_to_shared(As);
    uint32_t sB = (uint32_t)__cvta_generic_to_shared(Bs);

    for (int cid = tid; cid < 128 * KC; cid += 256) {
        int m = cid / KC, kc = (cid - m * KC) << 3;
        const bf16* g = A + (size_t)(row0 + m) * KP + kc;
        uint32_t sa = sA + (uint32_t)(m * AST + kc) * 2;
        asm volatile("cp.async.cg.shared.global [%0], [%1], 16;\n" :: "r"(sa), "l"(g));
    }
    auto issueB = [&](int t) {
        uint32_t bbase = sB + (t & 1) * (64 * AST * 2);
        const bf16* wt0 = Wt + (size_t)(t * 64) * KP;
        for (int cid = tid; cid < 64 * KC; cid += 256) {
            int n = cid / KC, kc = (cid - n * KC) << 3;
            uint32_t sb = bbase + (uint32_t)(n * AST + kc) * 2;
            asm volatile("cp.async.cg.shared.global [%0], [%1], 16;\n"
                         :: "r"(sb), "l"(wt0 + (size_t)n * KP + kc));
        }
        asm volatile("cp.async.commit_group;\n");
    };

    issueB(0);

    for (int t = 0; t < NT; t++) {
        if (t + 1 < NT) { issueB(t + 1); asm volatile("cp.async.wait_group 1;\n"); }
        else            { asm volatile("cp.async.wait_group 0;\n"); }
        __syncthreads();

        float acc[2][4][4];
#pragma unroll
        for (int a = 0; a < 2; a++)
#pragma unroll
            for (int b = 0; b < 4; b++)
#pragma unroll
                for (int c = 0; c < 4; c++) acc[a][b][c] = 0.f;

        const bf16* Bb = Bs + (t & 1) * (64 * AST);
        for (int ks = 0; ks < NS; ks++) {
            uint32_t afr[2][4], bfr[4][2];
#pragma unroll
            for (int mt = 0; mt < 2; mt++) {
                const bf16* p = As + (warpm * 32 + mt * 16 + gr) * AST + ks * 16 + cq * 2;
                afr[mt][0] = *(const uint32_t*)p;
                afr[mt][1] = *(const uint32_t*)(p + 8 * AST);
                afr[mt][2] = *(const uint32_t*)(p + 8);
                afr[mt][3] = *(const uint32_t*)(p + 8 * AST + 8);
            }
#pragma unroll
            for (int nt = 0; nt < 4; nt++) {
                const bf16* p = Bb + (warpn * 32 + nt * 8 + gr) * AST + ks * 16 + cq * 2;
                bfr[nt][0] = *(const uint32_t*)p;
                bfr[nt][1] = *(const uint32_t*)(p + 8);
            }
#pragma unroll
            for (int mt = 0; mt < 2; mt++)
#pragma unroll
                for (int nt = 0; nt < 4; nt++) {
                    asm volatile(
                        "mma.sync.aligned.m16n8k16.row.col.f32.bf16.bf16.f32 "
                        "{%0,%1,%2,%3},{%4,%5,%6,%7},{%8,%9},{%0,%1,%2,%3};\n"
                        : "+f"(acc[mt][nt][0]), "+f"(acc[mt][nt][1]),
                          "+f"(acc[mt][nt][2]), "+f"(acc[mt][nt][3])
                        : "r"(afr[mt][0]), "r"(afr[mt][1]), "r"(afr[mt][2]), "r"(afr[mt][3]),
                          "r"(bfr[nt][0]), "r"(bfr[nt][1]));
                }
        }

        const int col0 = t * 64;
#pragma unroll
        for (int mt = 0; mt < 2; mt++) {
            int r0 = row0 + warpm * 32 + mt * 16 + gr;
#pragma unroll
            for (int nt = 0; nt < 4; nt++) {
                int cb = col0 + warpn * 32 + nt * 8 + cq * 2;
                if (cb < N) {
                    float v00 = acc[mt][nt][0], v01 = acc[mt][nt][1];
                    float v10 = acc[mt][nt][2], v11 = acc[mt][nt][3];
                    if (EPI == 2) { v00 = gelu_exact(v00); v01 = gelu_exact(v01);
                                    v10 = gelu_exact(v10); v11 = gelu_exact(v11); }
                    __nv_bfloat162 p0, p1;
                    p0.x = __float2bfloat16(v00); p0.y = __float2bfloat16(v01);
                    p1.x = __float2bfloat16(v10); p1.y = __float2bfloat16(v11);
                    *(__nv_bfloat162*)&Cb[(size_t)r0 * OS + cb]       = p0;
                    *(__nv_bfloat162*)&Cb[(size_t)(r0 + 8) * OS + cb] = p1;
                }
            }
        }
        __syncthreads();
    }
}

// ======== proj GEMM + fused bias + residual-combine + LayerNorm2 ========
__global__ void __launch_bounds__(256) mma_gemm_ln(const bf16* __restrict__ A,
                                                   const bf16* __restrict__ Wt,
                                                   const float* __restrict__ bias,
                                                   const float* __restrict__ x,
                                                   const float* __restrict__ conv,
                                                   const float* __restrict__ cm,
                                                   const float* __restrict__ lg,
                                                   const float* __restrict__ lb,
                                                   float* __restrict__ xmid,
                                                   bf16* __restrict__ n2) {
    const int AST = KP1 + 8;              // 200
    extern __shared__ bf16 sm[];
    bf16* As = sm;                        // [128][200]
    bf16* Bs = sm + 128 * AST;            // [2][64][200]
    float* rs = (float*)(sm + 128 * AST + 2 * 64 * AST);   // [128] row sums
    float* rq = rs + 128;                                  // [128] row sumsq
    const int tid  = threadIdx.x;
    const int row0 = blockIdx.x * 128;
    const int wid  = tid >> 5;
    const int lane = tid & 31;
    const int warpm = wid >> 1;
    const int warpn = wid & 1;
    const int gr = lane >> 2;
    const int cq = lane & 3;
    const int NS = KP1 >> 4;
    const int KC = KP1 >> 3;
    const int NT = 3;

    if (tid < 256) ((float*)(sm + 128 * AST + 2 * 64 * AST))[tid] = 0.f;

    uint32_t sA = (uint32_t)__cvta_generic_to_shared(As);
    uint32_t sB = (uint32_t)__cvta_generic_to_shared(Bs);

    for (int cid = tid; cid < 128 * KC; cid += 256) {
        int m = cid / KC, kc = (cid - m * KC) << 3;
        const bf16* g = A + (size_t)(row0 + m) * KP1 + kc;
        uint32_t sa = sA + (uint32_t)(m * AST + kc) * 2;
        asm volatile("cp.async.cg.shared.global [%0], [%1], 16;\n" :: "r"(sa), "l"(g));
    }
    auto issueB = [&](int t) {
        uint32_t bbase = sB + (t & 1) * (64 * AST * 2);
        const bf16* wt0 = Wt + (size_t)(t * 64) * KP1;
        for (int cid = tid; cid < 64 * KC; cid += 256) {
            int n = cid / KC, kc = (cid - n * KC) << 3;
            uint32_t sb = bbase + (uint32_t)(n * AST + kc) * 2;
            asm volatile("cp.async.cg.shared.global [%0], [%1], 16;\n"
                         :: "r"(sb), "l"(wt0 + (size_t)n * KP1 + kc));
        }
        asm volatile("cp.async.commit_group;\n");
    };

    issueB(0);

    for (int t = 0; t < NT; t++) {
        if (t + 1 < NT) { issueB(t + 1); asm volatile("cp.async.wait_group 1;\n"); }
        else            { asm volatile("cp.async.wait_group 0;\n"); }
        __syncthreads();

        float acc[2][4][4];
#pragma unroll
        for (int a = 0; a < 2; a++)
#pragma unroll
            for (int b = 0; b < 4; b++)
#pragma unroll
                for (int c = 0; c < 4; c++) acc[a][b][c] = 0.f;

        const bf16* Bb = Bs + (t & 1) * (64 * AST);
        for (int ks = 0; ks < NS; ks++) {
            uint32_t afr[2][4], bfr[4][2];
#pragma unroll
            for (int mt = 0; mt < 2; mt++) {
                const bf16* p = As + (warpm * 32 + mt * 16 + gr) * AST + ks * 16 + cq * 2;
                afr[mt][0] = *(const uint32_t*)p;
                afr[mt][1] = *(const uint32_t*)(p + 8 * AST);
                afr[mt][2] = *(const uint32_t*)(p + 8);
                afr[mt][3] = *(const uint32_t*)(p + 8 * AST + 8);
            }
#pragma unroll
            for (int nt = 0; nt < 4; nt++) {
                const bf16* p = Bb + (warpn * 32 + nt * 8 + gr) * AST + ks * 16 + cq * 2;
                bfr[nt][0] = *(const uint32_t*)p;
                bfr[nt][1] = *(const uint32_t*)(p + 8);
            }
#pragma unroll
            for (int mt = 0; mt < 2; mt++)
#pragma unroll
                for (int nt = 0; nt < 4; nt++) {
                    asm volatile(
                        "mma.sync.aligned.m16n8k16.row.col.f32.bf16.bf16.f32 "
                        "{%0,%1,%2,%3},{%4,%5,%6,%7},{%8,%9},{%0,%1,%2,%3};\n"
                        : "+f"(acc[mt][nt][0]), "+f"(acc[mt][nt][1]),
                          "+f"(acc[mt][nt][2]), "+f"(acc[mt][nt][3])
                        : "r"(afr[mt][0]), "r"(afr[mt][1]), "r"(afr[mt][2]), "r"(afr[mt][3]),
                          "r"(bfr[nt][0]), "r"(bfr[nt][1]));
                }
        }

        const int col0 = t * 64;
#pragma unroll
        for (int mt = 0; mt < 2; mt++) {
            int r0 = row0 + warpm * 32 + mt * 16 + gr;
            int bb = r0 >> 16;
            float s0 = 0.f, q0 = 0.f, s1 = 0.f, q1 = 0.f;
#pragma unroll
            for (int nt = 0; nt < 4; nt++) {
                int cb = col0 + warpn * 32 + nt * 8 + cq * 2;
                if (cb < CC) {
                    float b0 = bias[cb], b1 = bias[cb + 1];
                    float cm0 = cm[bb * CC + cb], cm1 = cm[bb * CC + cb + 1];
                    const float2 x0v = *(const float2*)&x[(size_t)r0 * CC + cb];
                    const float2 x1v = *(const float2*)&x[(size_t)(r0 + 8) * CC + cb];
                    const float2 c0v = *(const float2*)&conv[(size_t)r0 * CC + cb];
                    const float2 c1v = *(const float2*)&conv[(size_t)(r0 + 8) * CC + cb];
                    float v00 = x0v.x + (acc[mt][nt][0] + b0) * cm0 + c0v.x;
                    float v01 = x0v.y + (acc[mt][nt][1] + b1) * cm1 + c0v.y;
                    float v10 = x1v.x + (acc[mt][nt][2] + b0) * cm0 + c1v.x;
                    float v11 = x1v.y + (acc[mt][nt][3] + b1) * cm1 + c1v.y;
                    *(float2*)&xmid[(size_t)r0 * CC + cb]       = make_float2(v00, v01);
                    *(float2*)&xmid[(size_t)(r0 + 8) * CC + cb] = make_float2(v10, v11);
                    s0 += v00 + v01; q0 += v00 * v00 + v01 * v01;
                    s1 += v10 + v11; q1 += v10 * v10 + v11 * v11;
                }
            }
#pragma unroll
            for (int o = 1; o <= 2; o <<= 1) {
                s0 += __shfl_xor_sync(0xffffffffu, s0, o);
                q0 += __shfl_xor_sync(0xffffffffu, q0, o);
                s1 += __shfl_xor_sync(0xffffffffu, s1, o);
                q1 += __shfl_xor_sync(0xffffffffu, q1, o);
            }
            if (cq == 0) {
                int lr = r0 - row0;
                atomicAdd(&rs[lr], s0);     atomicAdd(&rq[lr], q0);
                atomicAdd(&rs[lr + 8], s1); atomicAdd(&rq[lr + 8], q1);
            }
        }
        __syncthreads();
    }

    if (tid < 128) {
        float mean = rs[tid] * (1.f / CC);
        float var  = rq[tid] * (1.f / CC) - mean * mean;
        rs[tid] = mean;
        rq[tid] = rsqrtf(var + 1e-5f);
    }
    __syncthreads();

    for (int idx = tid; idx < 128 * CC; idx += 256) {
        int rr = idx / CC, c = idx - rr * CC;
        float xv = xmid[(size_t)(row0 + rr) * CC + c];
        float nv = (xv - rs[rr]) * rq[rr] * lg[c] + lb[c];
        n2[(size_t)(row0 + rr) * KP1 + c] = __float2bfloat16(nv);
    }
}

// ======== pipelined GEMM (KP=384 ffn2): C = A @ W^T + residual ========
__global__ void __launch_bounds__(256) mma_gemm_res(const bf16* __restrict__ A,
                                                    const bf16* __restrict__ Wt,
                                                    const float* __restrict__ res,
                                                    float* __restrict__ Cout,
                                                    int N, int KP) {
    extern __shared__ bf16 sm[];
    bf16* As = sm;                       // [2][128][40]
    bf16* Bs = sm + 2 * 128 * 40;        // [2][64][40]
    const int tid  = threadIdx.x;
    const int row0 = blockIdx.x * 128;
    const int col0 = blockIdx.y * 64;
    const int NS   = KP >> 5;
    const int wid  = tid >> 5;
    const int lane = tid & 31;
    const int warpm = wid >> 1;
    const int warpn = wid & 1;
    const int gr = lane >> 2;
    const int cq = lane & 3;

    uint32_t sA = (uint32_t)__cvta_generic_to_shared(As);
    uint32_t sB = (uint32_t)__cvta_generic_to_shared(Bs);

    auto issue = [&](int s) {
        const int k0  = s << 5;
        const int buf = s & 1;
        uint32_t abase = sA + buf * (128 * 40 * 2);
        uint32_t bbase = sB + buf * (64 * 40 * 2);
#pragma unroll
        for (int i = 0; i < 2; i++) {
            int cid = tid + 256 * i;
            int m = cid >> 2, kc = (cid & 3) << 3;
            const bf16* g = A + (size_t)(row0 + m) * KP + k0 + kc;
            uint32_t sa = abase + (uint32_t)(m * 40 + kc) * 2;
            asm volatile("cp.async.cg.shared.global [%0], [%1], 16;\n" :: "r"(sa), "l"(g));
        }
        {
            int n = tid >> 2, kc = (tid & 3) << 3;
            const bf16* g = Wt + (size_t)(col0 + n) * KP + k0 + kc;
            uint32_t sb = bbase + (uint32_t)(n * 40 + kc) * 2;
            asm volatile("cp.async.cg.shared.global [%0], [%1], 16;\n" :: "r"(sb), "l"(g));
        }
        asm volatile("cp.async.commit_group;\n");
    };

    float acc[2][4][4];
#pragma unroll
    for (int a = 0; a < 2; a++)
#pragma unroll
        for (int b = 0; b < 4; b++)
#pragma unroll
            for (int c = 0; c < 4; c++) acc[a][b][c] = 0.f;

    issue(0);
    for (int s = 0; s < NS; s++) {
        if (s + 1 < NS) { issue(s + 1); asm volatile("cp.async.wait_group 1;\n"); }
        else            { asm volatile("cp.async.wait_group 0;\n"); }
        __syncthreads();
        const bf16* Ab = As + (s & 1) * (128 * 40);
        const bf16* Bb = Bs + (s & 1) * (64 * 40);
#pragma unroll
        for (int kk = 0; kk < 2; kk++) {
            uint32_t afr[2][4], bfr[4][2];
#pragma unroll
            for (int mt = 0; mt < 2; mt++) {
                const bf16* p = Ab + (warpm * 32 + mt * 16 + gr) * 40 + kk * 16 + cq * 2;
                afr[mt][0] = *(const uint32_t*)p;
                afr[mt][1] = *(const uint32_t*)(p + 8 * 40);
                afr[mt][2] = *(const uint32_t*)(p + 8);
                afr[mt][3] = *(const uint32_t*)(p + 8 * 40 + 8);
            }
#pragma unroll
            for (int nt = 0; nt < 4; nt++) {
                const bf16* p = Bb + (warpn * 32 + nt * 8 + gr) * 40 + kk * 16 + cq * 2;
                bfr[nt][0] = *(const uint32_t*)p;
                bfr[nt][1] = *(const uint32_t*)(p + 8);
            }
#pragma unroll
            for (int mt = 0; mt < 2; mt++)
#pragma unroll
                for (int nt = 0; nt < 4; nt++) {
                    asm volatile(
                        "mma.sync.aligned.m16n8k16.row.col.f32.bf16.bf16.f32 "
                        "{%0,%1,%2,%3},{%4,%5,%6,%7},{%8,%9},{%0,%1,%2,%3};\n"
                        : "+f"(acc[mt][nt][0]), "+f"(acc[mt][nt][1]),
                          "+f"(acc[mt][nt][2]), "+f"(acc[mt][nt][3])
                        : "r"(afr[mt][0]), "r"(afr[mt][1]), "r"(afr[mt][2]), "r"(afr[mt][3]),
                          "r"(bfr[nt][0]), "r"(bfr[nt][1]));
                }
        }
        __syncthreads();
    }

#pragma unroll
    for (int mt = 0; mt < 2; mt++) {
        int r0 = row0 + warpm * 32 + mt * 16 + gr;
#pragma unroll
        for (int nt = 0; nt < 4; nt++) {
            int cb = col0 + warpn * 32 + nt * 8 + cq * 2;
            if (cb < N) {
                const float2 r0v = *(const float2*)&res[(size_t)r0 * N + cb];
                const float2 r1v = *(const float2*)&res[(size_t)(r0 + 8) * N + cb];
                *(float2*)&Cout[(size_t)r0 * N + cb] =
                    make_float2(acc[mt][nt][0] + r0v.x, acc[mt][nt][1] + r0v.y);
                *(float2*)&Cout[(size_t)(r0 + 8) * N + cb] =
                    make_float2(acc[mt][nt][2] + r1v.x, acc[mt][nt][3] + r1v.y);
            }
        }
    }
}

// ---------------- window attention (bf16 qkv, packed f32x2 math) ----------------
__global__ void attn_kernel(const bf16* __restrict__ qkv,
                            const float* __restrict__ b_rel,
                            bf16* __restrict__ out) {
    extern __shared__ float kv[];   // [64][360]: cols 0..179 = K, 180..359 = V
    const int w = blockIdx.x;
    const int b  = w >> 10;
    const int wy = (w & 1023) >> 5;
    const int wx = w & 31;
    const int tid = threadIdx.x;    // 384

    for (int idx = tid; idx < 64 * 180; idx += 384) {
        int t = idx / 180, c2 = idx - t * 180;
        int ty = t >> 3, tx = t & 7;
        size_t row = ((size_t)b << 16) + (size_t)(wy * 8 + ty) * 256 + (wx * 8 + tx);
        __nv_bfloat162 v = *(const __nv_bfloat162*)&qkv[row * 540 + 180 + 2 * c2];
        kv[t * 360 + 2 * c2]     = __bfloat162float(v.x);
        kv[t * 360 + 2 * c2 + 1] = __bfloat162float(v.y);
    }
    for (int idx = tid; idx < 64 * 12; idx += 384) {
        int t = idx / 12, c = idx - t * 12;
        int ty = t >> 3, tx = t & 7;
        size_t row = ((size_t)b << 16) + (size_t)(wy * 8 + ty) * 256 + (wx * 8 + tx);
        out[row * KP1 + 180 + c] = __float2bfloat16(0.f);
    }
    __syncthreads();

    const int h = tid / 64;
    const int t = tid & 63;
    const int ty = t >> 3, tx = t & 7;
    size_t row = ((size_t)b << 16) + (size_t)(wy * 8 + ty) * 256 + (wx * 8 + tx);

    u64 qp[15];
    const __nv_bfloat162* qsrc = (const __nv_bfloat162*)(qkv + row * 540 + h * HDIM);
    const float scale = 0.18257418583505536f;  // 30^-0.5
#pragma unroll
    for (int d = 0; d < 15; d++) {
        __nv_bfloat162 qv = qsrc[d];
        float qx = __bfloat162float(qv.x) * scale;
        float qy = __bfloat162float(qv.y) * scale;
        asm("mov.b64 %0, {%1, %2};" : "=l"(qp[d])
            : "r"(__float_as_uint(qx)), "r"(__float_as_uint(qy)));
    }

    const float* br = b_rel + h * 4096 + t * 64;
    float l = 0.f;
    u64 o2[15];
#pragma unroll
    for (int d = 0; d < 15; d++) o2[d] = 0ULL;

    for (int j = 0; j < 64; j++) {
        const u64* kj = (const u64*)&kv[j * 360 + h * HDIM];
        u64 acc2 = 0ULL;
#pragma unroll
        for (int d = 0; d < 15; d++) FMA2(acc2, qp[d], kj[d], acc2);
        uint32_t alo, ahi;
        asm("mov.b64 {%0, %1}, %2;" : "=r"(alo), "=r"(ahi) : "l"(acc2));
        float s = br[j] + __uint_as_float(alo) + __uint_as_float(ahi);
        float p = __expf(s);
        l += p;
        u64 pp;
        asm("mov.b64 %0, {%1, %1};" : "=l"(pp) : "r"(__float_as_uint(p)));
        const u64* vj = (const u64*)&kv[j * 360 + 180 + h * HDIM];
#pragma unroll
        for (int d = 0; d < 15; d++) FMA2(o2[d], pp, vj[d], o2[d]);
    }
    float inv = 1.f / l;
    bf16* op = out + row * KP1 + h * HDIM;
#pragma unroll
    for (int d = 0; d < 15; d++) {
        uint32_t lo, hi;
        asm("mov.b64 {%0, %1}, %2;" : "=r"(lo), "=r"(hi) : "l"(o2[d]));
        op[2 * d]     = __float2bfloat16(__uint_as_float(lo) * inv);
        op[2 * d + 1] = __float2bfloat16(__uint_as_float(hi) * inv);
    }
}

// ---------------- depthwise 3x3 SAME conv, x-tiled (TX) + rolling-y ----------------
template <typename Tin, typename Tout, int CD, int INS, int OUTS, int GELU, int POOL, int TX>
__global__ void dwconv_tile(const Tin* __restrict__ in,
                            const float* __restrict__ k9,
                            Tout* __restrict__ out,
                            float* __restrict__ pooled) {
    const int c  = threadIdx.x;
    const int x0 = blockIdx.x * TX;
    const int y0 = blockIdx.y * 64;
    const int b  = blockIdx.z;
    float w[9];
#pragma unroll
    for (int i = 0; i < 9; i++) w[i] = k9[c * 9 + i];

    const size_t base = ((size_t)b << 16);
    float r[TX + 2], s[TX + 2], t[TX + 2];

    auto loadrow = [&](int yy, float* dst) {
#pragma unroll
        for (int i = 0; i < TX + 2; i++) {
            int xx = x0 - 1 + i;
            dst[i] = (xx >= 0 && xx < WWID)
                     ? (float)in[(base + (size_t)yy * 256 + xx) * INS + c] : 0.f;
        }
    };

    if (y0 > 0) loadrow(y0 - 1, r);
    else {
#pragma unroll
        for (int i = 0; i < TX + 2; i++) r[i] = 0.f;
    }
    loadrow(y0, s);

    float psum = 0.f;
    for (int yy = y0; yy < y0 + 64; yy++) {
        if (yy + 1 < HH) loadrow(yy + 1, t);
        else {
#pragma unroll
            for (int i = 0; i < TX + 2; i++) t[i] = 0.f;
        }
#pragma unroll
        for (int j = 0; j < TX; j++) {
            float acc = r[j] * w[0] + r[j + 1] * w[1] + r[j + 2] * w[2]
                      + s[j] * w[3] + s[j + 1] * w[4] + s[j + 2] * w[5]
                      + t[j] * w[6] + t[j + 1] * w[7] + t[j + 2] * w[8];
            if (GELU) acc = gelu_exact(acc);
            if (POOL) psum += acc;
            size_t op = (base + (size_t)yy * 256 + x0 + j) * OUTS;
            out[op + c] = (Tout)acc;
            if (OUTS > CD && c < OUTS - CD) out[op + CD + c] = (Tout)0.f;
        }
#pragma unroll
        for (int i = 0; i < TX + 2; i++) { r[i] = s[i]; s[i] = t[i]; }
    }
    if (POOL) atomicAdd(&pooled[b * CD + c], psum * (1.f / (float)LL));
}

// ---------------- channel gate ----------------
__global__ void gate_kernel(const float* __restrict__ pooled,
                            const float* __restrict__ w1,
                            const float* __restrict__ w2,
                            float* __restrict__ cm) {
    const int b = blockIdx.x;
    const int tid = threadIdx.x;   // 180
    __shared__ float t1[C8];
    if (tid < C8) {
        float s = 0.f;
        for (int c = 0; c < CC; c++) s += pooled[b * CC + c] * w1[tid * CC + c];
        t1[tid] = gelu_exact(s);
    }
    __syncthreads();
    float s = 0.f;
#pragma unroll
    for (int j = 0; j < C8; j++) s += t1[j] * w2[tid * C8 + j];
    cm[b * CC + tid] = 1.f / (1.f + expf(-s));
}

// ---------------- launch ----------------
extern "C" void kernel_launch(void* const* d_in, const int* in_sizes, int n_in,
                              void* d_out, int out_size) {
    const float* x       = (const float*)d_in[0];
    const float* w_qkv   = (const float*)d_in[1];
    const float* b_rel   = (const float*)d_in[2];
    const float* w_proj  = (const float*)d_in[3];
    const float* b_proj  = (const float*)d_in[4];
    const float* conv_dw = (const float*)d_in[5];
    const float* cg_w1   = (const float*)d_in[6];
    const float* cg_w2   = (const float*)d_in[7];
    const float* ffn_w1  = (const float*)d_in[8];
    const float* ffn_dw  = (const float*)d_in[9];
    const float* ffn_w2  = (const float*)d_in[10];
    const float* n1_g    = (const float*)d_in[11];
    const float* n1_b    = (const float*)d_in[12];
    const float* n2_g    = (const float*)d_in[13];
    const float* n2_b    = (const float*)d_in[14];
    float* out = (float*)d_out;

    float *conv, *xmid, *pooled, *cm;
    bf16 *qkvb, *n1b, *n2b, *hsb, *wb;
    cudaGetSymbolAddress((void**)&qkvb,  g_qkvb);
    cudaGetSymbolAddress((void**)&conv,  g_conv);
    cudaGetSymbolAddress((void**)&xmid,  g_xmid);
    cudaGetSymbolAddress((void**)&pooled, g_pooled);
    cudaGetSymbolAddress((void**)&cm,     g_cm);
    cudaGetSymbolAddress((void**)&n1b,   g_n1b);
    cudaGetSymbolAddress((void**)&n2b,   g_n2b);
    cudaGetSymbolAddress((void**)&hsb,   g_hsb);
    cudaGetSymbolAddress((void**)&wb,    g_wb);

    const int PSMEM1   = (128 * (KP1 + 8) + 2 * 64 * (KP1 + 8)) * (int)sizeof(bf16);  // 102400
    const int PSMEM_LN = PSMEM1 + 256 * (int)sizeof(float);                            // 103424
    const int PIPE_SMEM = (2 * 128 * 40 + 2 * 64 * 40) * (int)sizeof(bf16);            // 30720
    const int ATTN_SMEM = 64 * 360 * (int)sizeof(float);                               // 92160
    cudaFuncSetAttribute((const void*)mma_gemm_p<0>, cudaFuncAttributeMaxDynamicSharedMemorySize, PSMEM1);
    cudaFuncSetAttribute((const void*)mma_gemm_p<2>, cudaFuncAttributeMaxDynamicSharedMemorySize, PSMEM1);
    cudaFuncSetAttribute((const void*)mma_gemm_ln,   cudaFuncAttributeMaxDynamicSharedMemorySize, PSMEM_LN);
    cudaFuncSetAttribute((const void*)mma_gemm_res,  cudaFuncAttributeMaxDynamicSharedMemorySize, PIPE_SMEM);
    cudaFuncSetAttribute((const void*)attn_kernel,   cudaFuncAttributeMaxDynamicSharedMemorySize, ATTN_SMEM);

    // 0) convert + pad weights to bf16
    convw_kernel<<<(576 * 192 + 255) / 256, 256>>>(w_qkv,  wb + WB_QKV,  540, 180, 576, 192);
    convw_kernel<<<(192 * 192 + 255) / 256, 256>>>(w_proj, wb + WB_PROJ, 180, 180, 192, 192);
    convw_kernel<<<(384 * 192 + 255) / 256, 256>>>(ffn_w1, wb + WB_FFN1, 360, 180, 384, 192);
    convw_kernel<<<(192 * 384 + 255) / 256, 256>>>(ffn_w2, wb + WB_FFN2, 180, 360, 192, 384);

    // 1) ln1: x -> n1b (bf16, padded)
    ln_kernel<<<MROWS / 4, 128>>>(x, n1_g, n1_b, n1b);

    // 2) conv branch: dwconv(n1b)+GELU -> conv (fp32), fused mean-pool
    cudaMemsetAsync(pooled, 0, BB * CC * sizeof(float));
    dwconv_tile<bf16, float, CC, KP1, CC, 1, 1, 8><<<dim3(WWID / 8, 4, BB), CC>>>(n1b, conv_dw, conv, pooled);

    // 3) channel gate -> cm
    gate_kernel<<<BB, CC>>>(pooled, cg_w1, cg_w2, cm);

    // 4) qkv = n1 @ w_qkv^T  (bf16 out, N=540, stride 540, 9 n-tiles)
    mma_gemm_p<0><<<MROWS / 128, 256, PSMEM1>>>(n1b, wb + WB_QKV, qkvb, 540, KP1, 540, 9);

    // 5) window attention -> n2b (bf16, padded)
    attn_kernel<<<NWIN, 384, ATTN_SMEM>>>(qkvb, b_rel, n2b);

    // 6) proj + fused residual-combine + ln2 -> xmid (fp32), n2b (bf16)
    mma_gemm_ln<<<MROWS / 128, 256, PSMEM_LN>>>(n2b, wb + WB_PROJ, b_proj,
                                                x, conv, cm, n2_g, n2_b, xmid, n2b);

    // 7) ffn1: h = gelu(n2 @ ffn_w1^T) -> qkvb buffer (bf16, stride 384, N=360)
    mma_gemm_p<2><<<MROWS / 128, 256, PSMEM1>>>(n2b, wb + WB_FFN1, qkvb, 360, KP1, 384, 6);

    // 8) ffn dwconv: hsb = dwconv(h) (bf16 in stride 384, bf16 out padded 384)
    dwconv_tile<bf16, bf16, CFFN, KP2, KP2, 0, 0, 8><<<dim3(WWID / 8, 4, BB), CFFN>>>(qkvb, ffn_dw, hsb, nullptr);

    // 9) ffn2 + residual: out = xmid + hsb @ ffn_w2^T  (pipelined, KP=384)
    mma_gemm_res<<<dim3(MROWS / 128, 3), 256, PIPE_SMEM>>>(hsb, wb + WB_FFN2, xmid, out, 180, KP2);
}

// round 13
// speedup vs baseline: 1.0863x; 1.0775x over previous
#include <cuda_runtime.h>
#include <cuda_bf16.h>
#include <math.h>
#include <cstdint>

using bf16 = __nv_bfloat16;

// ---------------- problem constants ----------------
#define BB 2
#define HH 256
#define WWID 256
#define LL 65536          // H*W
#define CC 180
#define NHD 6
#define HDIM 30
#define NWIN 2048         // B * (H/8) * (W/8)
#define CFFN 360
#define C8 22             // 180 // 8
#define MROWS (BB*LL)     // 131072
#define KP1 192           // padded K for K=180
#define KP2 384           // padded K for K=360

// ---------------- scratch (device globals, no allocation) ----------------
__device__ bf16  g_qkvb [(size_t)MROWS*540];   // qkv bf16; reused for h (stride 384)
__device__ bf16  g_attnf[(size_t)MROWS*CC];    // proj output (bf16)
__device__ bf16  g_conv [(size_t)MROWS*CC];    // conv branch (bf16)
__device__ float g_xmid [(size_t)MROWS*CC];
__device__ float g_pooled[BB*CC];
__device__ float g_cm    [BB*CC];
__device__ bf16  g_n1b[(size_t)MROWS*KP1];     // ln1 out (bf16, padded)
__device__ bf16  g_n2b[(size_t)MROWS*KP1];     // attn out, then n2 (bf16, padded)
__device__ bf16  g_hsb[(size_t)MROWS*KP2];     // ffn dwconv out (bf16, padded)
__device__ bf16  g_wb [294912];                // padded bf16 weights

#define WB_QKV  0        // 576 x 192
#define WB_PROJ 110592   // 192 x 192
#define WB_FFN1 147456   // 384 x 192
#define WB_FFN2 221184   // 192 x 384

__device__ __forceinline__ float gelu_exact(float x) {
    return 0.5f * x * (1.0f + erff(x * 0.70710678118654752f));
}

// ---------------- weight convert + pad: src[N][K] fp32 -> dst[NP][KP] bf16 ----------------
__global__ void convw_kernel(const float* __restrict__ src, bf16* __restrict__ dst,
                             int N, int K, int NP, int KP) {
    int i = blockIdx.x * 256 + threadIdx.x;
    if (i < NP * KP) {
        int n = i / KP, k = i - n * KP;
        float v = (n < N && k < K) ? src[n * K + k] : 0.f;
        dst[i] = __float2bfloat16(v);
    }
}

// ---------------- LayerNorm (emits bf16, KP1-padded) ----------------
__global__ void ln_kernel(const float* __restrict__ x,
                          const float* __restrict__ g,
                          const float* __restrict__ b,
                          bf16* __restrict__ out) {
    int row = blockIdx.x * 4 + (threadIdx.x >> 5);
    int lane = threadIdx.x & 31;
    const float* xr = x + (size_t)row * CC;
    float v[6];
    float s = 0.f;
#pragma unroll
    for (int i = 0; i < 6; i++) {
        int c = lane + 32 * i;
        v[i] = (c < CC) ? xr[c] : 0.f;
        s += v[i];
    }
#pragma unroll
    for (int o = 16; o; o >>= 1) s += __shfl_xor_sync(0xffffffffu, s, o);
    float mean = s * (1.f / CC);
    float vs = 0.f;
#pragma unroll
    for (int i = 0; i < 6; i++) {
        int c = lane + 32 * i;
        if (c < CC) { float d = v[i] - mean; vs += d * d; }
    }
#pragma unroll
    for (int o = 16; o; o >>= 1) vs += __shfl_xor_sync(0xffffffffu, vs, o);
    float rstd = rsqrtf(vs * (1.f / CC) + 1e-5f);
    bf16* orow = out + (size_t)row * KP1;
#pragma unroll
    for (int i = 0; i < 6; i++) {
        int c = lane + 32 * i;
        float val = (c < CC) ? (v[i] - mean) * rstd * g[c] + b[c] : 0.f;
        orow[c] = __float2bfloat16(val);
    }
}

// ---------------- fused: xmid = x + attnf*cm + conv; n2 = bf16(LN(xmid)) ----------------
__global__ void resid_ln_kernel(const float* __restrict__ x,
                                const bf16* __restrict__ attnf,
                                const bf16* __restrict__ conv,
                                const float* __restrict__ cm,
                                const float* __restrict__ g,
                                const float* __restrict__ b,
                                float* __restrict__ xmid,
                                bf16* __restrict__ n2) {
    int row = blockIdx.x * 4 + (threadIdx.x >> 5);
    int lane = threadIdx.x & 31;
    int bb = row >> 16;
    size_t base = (size_t)row * CC;
    float v[6];
    float s = 0.f;
#pragma unroll
    for (int i = 0; i < 6; i++) {
        int c = lane + 32 * i;
        if (c < CC) {
            float xv = x[base + c]
                     + __bfloat162float(attnf[base + c]) * cm[bb * CC + c]
                     + __bfloat162float(conv[base + c]);
            xmid[base + c] = xv;
            v[i] = xv;
        } else v[i] = 0.f;
        s += v[i];
    }
#pragma unroll
    for (int o = 16; o; o >>= 1) s += __shfl_xor_sync(0xffffffffu, s, o);
    float mean = s * (1.f / CC);
    float vs = 0.f;
#pragma unroll
    for (int i = 0; i < 6; i++) {
        int c = lane + 32 * i;
        if (c < CC) { float d = v[i] - mean; vs += d * d; }
    }
#pragma unroll
    for (int o = 16; o; o >>= 1) vs += __shfl_xor_sync(0xffffffffu, vs, o);
    float rstd = rsqrtf(vs * (1.f / CC) + 1e-5f);
    bf16* orow = n2 + (size_t)row * KP1;
#pragma unroll
    for (int i = 0; i < 6; i++) {
        int c = lane + 32 * i;
        float val = (c < CC) ? (v[i] - mean) * rstd * g[c] + b[c] : 0.f;
        orow[c] = __float2bfloat16(val);
    }
}

// ======== A-resident persistent GEMM: A[128xKP] in smem, loop n-tiles ========
// EPI: 0=none 1=+bias 2=gelu ; OBF: 1 -> bf16 output (stride OS), 0 -> fp32 output
template <int EPI, int OBF>
__global__ void __launch_bounds__(256) mma_gemm_p(const bf16* __restrict__ A,
                                                  const bf16* __restrict__ Wt,
                                                  const float* __restrict__ bias,
                                                  float* __restrict__ Cf,
                                                  bf16* __restrict__ Cb,
                                                  int N, int KP, int OS, int NT) {
    extern __shared__ bf16 sm[];
    const int AST = KP + 8;               // row stride (bf16)
    bf16* As = sm;                        // [128][AST]
    bf16* Bs = sm + 128 * AST;            // [2][64][AST]
    const int tid  = threadIdx.x;
    const int row0 = blockIdx.x * 128;
    const int wid  = tid >> 5;
    const int lane = tid & 31;
    const int warpm = wid >> 1;
    const int warpn = wid & 1;
    const int gr = lane >> 2;
    const int cq = lane & 3;
    const int NS = KP >> 4;               // k16 steps
    const int KC = KP >> 3;               // 16B chunks per row

    uint32_t sA = (uint32_t)__cvta_generic_to_shared(As);
    uint32_t sB = (uint32_t)__cvta_generic_to_shared(Bs);

    for (int cid = tid; cid < 128 * KC; cid += 256) {
        int m = cid / KC, kc = (cid - m * KC) << 3;
        const bf16* g = A + (size_t)(row0 + m) * KP + kc;
        uint32_t sa = sA + (uint32_t)(m * AST + kc) * 2;
        asm volatile("cp.async.cg.shared.global [%0], [%1], 16;\n" :: "r"(sa), "l"(g));
    }
    auto issueB = [&](int t) {
        uint32_t bbase = sB + (t & 1) * (64 * AST * 2);
        const bf16* wt0 = Wt + (size_t)(t * 64) * KP;
        for (int cid = tid; cid < 64 * KC; cid += 256) {
            int n = cid / KC, kc = (cid - n * KC) << 3;
            uint32_t sb = bbase + (uint32_t)(n * AST + kc) * 2;
            asm volatile("cp.async.cg.shared.global [%0], [%1], 16;\n"
                         :: "r"(sb), "l"(wt0 + (size_t)n * KP + kc));
        }
        asm volatile("cp.async.commit_group;\n");
    };

    issueB(0);

    for (int t = 0; t < NT; t++) {
        if (t + 1 < NT) { issueB(t + 1); asm volatile("cp.async.wait_group 1;\n"); }
        else            { asm volatile("cp.async.wait_group 0;\n"); }
        __syncthreads();

        float acc[2][4][4];
#pragma unroll
        for (int a = 0; a < 2; a++)
#pragma unroll
            for (int b = 0; b < 4; b++)
#pragma unroll
                for (int c = 0; c < 4; c++) acc[a][b][c] = 0.f;

        const bf16* Bb = Bs + (t & 1) * (64 * AST);
        for (int ks = 0; ks < NS; ks++) {
            uint32_t afr[2][4], bfr[4][2];
#pragma unroll
            for (int mt = 0; mt < 2; mt++) {
                const bf16* p = As + (warpm * 32 + mt * 16 + gr) * AST + ks * 16 + cq * 2;
                afr[mt][0] = *(const uint32_t*)p;
                afr[mt][1] = *(const uint32_t*)(p + 8 * AST);
                afr[mt][2] = *(const uint32_t*)(p + 8);
                afr[mt][3] = *(const uint32_t*)(p + 8 * AST + 8);
            }
#pragma unroll
            for (int nt = 0; nt < 4; nt++) {
                const bf16* p = Bb + (warpn * 32 + nt * 8 + gr) * AST + ks * 16 + cq * 2;
                bfr[nt][0] = *(const uint32_t*)p;
                bfr[nt][1] = *(const uint32_t*)(p + 8);
            }
#pragma unroll
            for (int mt = 0; mt < 2; mt++)
#pragma unroll
                for (int nt = 0; nt < 4; nt++) {
                    asm volatile(
                        "mma.sync.aligned.m16n8k16.row.col.f32.bf16.bf16.f32 "
                        "{%0,%1,%2,%3},{%4,%5,%6,%7},{%8,%9},{%0,%1,%2,%3};\n"
                        : "+f"(acc[mt][nt][0]), "+f"(acc[mt][nt][1]),
                          "+f"(acc[mt][nt][2]), "+f"(acc[mt][nt][3])
                        : "r"(afr[mt][0]), "r"(afr[mt][1]), "r"(afr[mt][2]), "r"(afr[mt][3]),
                          "r"(bfr[nt][0]), "r"(bfr[nt][1]));
                }
        }

        const int col0 = t * 64;
#pragma unroll
        for (int mt = 0; mt < 2; mt++) {
            int r0 = row0 + warpm * 32 + mt * 16 + gr;
#pragma unroll
            for (int nt = 0; nt < 4; nt++) {
                int cb = col0 + warpn * 32 + nt * 8 + cq * 2;
                if (cb < N) {
                    float v00 = acc[mt][nt][0], v01 = acc[mt][nt][1];
                    float v10 = acc[mt][nt][2], v11 = acc[mt][nt][3];
                    if (EPI == 1) { float b0 = bias[cb], b1 = bias[cb + 1];
                                    v00 += b0; v01 += b1; v10 += b0; v11 += b1; }
                    if (EPI == 2) { v00 = gelu_exact(v00); v01 = gelu_exact(v01);
                                    v10 = gelu_exact(v10); v11 = gelu_exact(v11); }
                    if (OBF) {
                        __nv_bfloat162 p0, p1;
                        p0.x = __float2bfloat16(v00); p0.y = __float2bfloat16(v01);
                        p1.x = __float2bfloat16(v10); p1.y = __float2bfloat16(v11);
                        *(__nv_bfloat162*)&Cb[(size_t)r0 * OS + cb]       = p0;
                        *(__nv_bfloat162*)&Cb[(size_t)(r0 + 8) * OS + cb] = p1;
                    } else {
                        *(float2*)&Cf[(size_t)r0 * OS + cb]       = make_float2(v00, v01);
                        *(float2*)&Cf[(size_t)(r0 + 8) * OS + cb] = make_float2(v10, v11);
                    }
                }
            }
        }
        __syncthreads();
    }
}

// ======== pipelined GEMM (KP=384 ffn2): C = A @ W^T + residual ========
__global__ void __launch_bounds__(256) mma_gemm_res(const bf16* __restrict__ A,
                                                    const bf16* __restrict__ Wt,
                                                    const float* __restrict__ res,
                                                    float* __restrict__ Cout,
                                                    int N, int KP) {
    extern __shared__ bf16 sm[];
    bf16* As = sm;                       // [2][128][40]
    bf16* Bs = sm + 2 * 128 * 40;        // [2][64][40]
    const int tid  = threadIdx.x;
    const int row0 = blockIdx.x * 128;
    const int col0 = blockIdx.y * 64;
    const int NS   = KP >> 5;
    const int wid  = tid >> 5;
    const int lane = tid & 31;
    const int warpm = wid >> 1;
    const int warpn = wid & 1;
    const int gr = lane >> 2;
    const int cq = lane & 3;

    uint32_t sA = (uint32_t)__cvta_generic_to_shared(As);
    uint32_t sB = (uint32_t)__cvta_generic_to_shared(Bs);

    auto issue = [&](int s) {
        const int k0  = s << 5;
        const int buf = s & 1;
        uint32_t abase = sA + buf * (128 * 40 * 2);
        uint32_t bbase = sB + buf * (64 * 40 * 2);
#pragma unroll
        for (int i = 0; i < 2; i++) {
            int cid = tid + 256 * i;
            int m = cid >> 2, kc = (cid & 3) << 3;
            const bf16* g = A + (size_t)(row0 + m) * KP + k0 + kc;
            uint32_t sa = abase + (uint32_t)(m * 40 + kc) * 2;
            asm volatile("cp.async.cg.shared.global [%0], [%1], 16;\n" :: "r"(sa), "l"(g));
        }
        {
            int n = tid >> 2, kc = (tid & 3) << 3;
            const bf16* g = Wt + (size_t)(col0 + n) * KP + k0 + kc;
            uint32_t sb = bbase + (uint32_t)(n * 40 + kc) * 2;
            asm volatile("cp.async.cg.shared.global [%0], [%1], 16;\n" :: "r"(sb), "l"(g));
        }
        asm volatile("cp.async.commit_group;\n");
    };

    float acc[2][4][4];
#pragma unroll
    for (int a = 0; a < 2; a++)
#pragma unroll
        for (int b = 0; b < 4; b++)
#pragma unroll
            for (int c = 0; c < 4; c++) acc[a][b][c] = 0.f;

    issue(0);
    for (int s = 0; s < NS; s++) {
        if (s + 1 < NS) { issue(s + 1); asm volatile("cp.async.wait_group 1;\n"); }
        else            { asm volatile("cp.async.wait_group 0;\n"); }
        __syncthreads();
        const bf16* Ab = As + (s & 1) * (128 * 40);
        const bf16* Bb = Bs + (s & 1) * (64 * 40);
#pragma unroll
        for (int kk = 0; kk < 2; kk++) {
            uint32_t afr[2][4], bfr[4][2];
#pragma unroll
            for (int mt = 0; mt < 2; mt++) {
                const bf16* p = Ab + (warpm * 32 + mt * 16 + gr) * 40 + kk * 16 + cq * 2;
                afr[mt][0] = *(const uint32_t*)p;
                afr[mt][1] = *(const uint32_t*)(p + 8 * 40);
                afr[mt][2] = *(const uint32_t*)(p + 8);
                afr[mt][3] = *(const uint32_t*)(p + 8 * 40 + 8);
            }
#pragma unroll
            for (int nt = 0; nt < 4; nt++) {
                const bf16* p = Bb + (warpn * 32 + nt * 8 + gr) * 40 + kk * 16 + cq * 2;
                bfr[nt][0] = *(const uint32_t*)p;
                bfr[nt][1] = *(const uint32_t*)(p + 8);
            }
#pragma unroll
            for (int mt = 0; mt < 2; mt++)
#pragma unroll
                for (int nt = 0; nt < 4; nt++) {
                    asm volatile(
                        "mma.sync.aligned.m16n8k16.row.col.f32.bf16.bf16.f32 "
                        "{%0,%1,%2,%3},{%4,%5,%6,%7},{%8,%9},{%0,%1,%2,%3};\n"
                        : "+f"(acc[mt][nt][0]), "+f"(acc[mt][nt][1]),
                          "+f"(acc[mt][nt][2]), "+f"(acc[mt][nt][3])
                        : "r"(afr[mt][0]), "r"(afr[mt][1]), "r"(afr[mt][2]), "r"(afr[mt][3]),
                          "r"(bfr[nt][0]), "r"(bfr[nt][1]));
                }
        }
        __syncthreads();
    }

#pragma unroll
    for (int mt = 0; mt < 2; mt++) {
        int r0 = row0 + warpm * 32 + mt * 16 + gr;
#pragma unroll
        for (int nt = 0; nt < 4; nt++) {
            int cb = col0 + warpn * 32 + nt * 8 + cq * 2;
            if (cb < N) {
                const float2 r0v = *(const float2*)&res[(size_t)r0 * N + cb];
                const float2 r1v = *(const float2*)&res[(size_t)(r0 + 8) * N + cb];
                *(float2*)&Cout[(size_t)r0 * N + cb] =
                    make_float2(acc[mt][nt][0] + r0v.x, acc[mt][nt][1] + r0v.y);
                *(float2*)&Cout[(size_t)(r0 + 8) * N + cb] =
                    make_float2(acc[mt][nt][2] + r1v.x, acc[mt][nt][3] + r1v.y);
            }
        }
    }
}

// ---------------- window attention (bf16 qkv input, no-max softmax) ----------------
__global__ void attn_kernel(const bf16* __restrict__ qkv,
                            const float* __restrict__ b_rel,
                            bf16* __restrict__ out) {
    extern __shared__ float kv[];   // [64][360]: cols 0..179 = K, 180..359 = V
    const int w = blockIdx.x;
    const int b  = w >> 10;
    const int wy = (w & 1023) >> 5;
    const int wx = w & 31;
    const int tid = threadIdx.x;    // 384

    for (int idx = tid; idx < 64 * 180; idx += 384) {
        int t = idx / 180, c2 = idx - t * 180;
        int ty = t >> 3, tx = t & 7;
        size_t row = ((size_t)b << 16) + (size_t)(wy * 8 + ty) * 256 + (wx * 8 + tx);
        __nv_bfloat162 v = *(const __nv_bfloat162*)&qkv[row * 540 + 180 + 2 * c2];
        kv[t * 360 + 2 * c2]     = __bfloat162float(v.x);
        kv[t * 360 + 2 * c2 + 1] = __bfloat162float(v.y);
    }
    for (int idx = tid; idx < 64 * 12; idx += 384) {
        int t = idx / 12, c = idx - t * 12;
        int ty = t >> 3, tx = t & 7;
        size_t row = ((size_t)b << 16) + (size_t)(wy * 8 + ty) * 256 + (wx * 8 + tx);
        out[row * KP1 + 180 + c] = __float2bfloat16(0.f);
    }
    __syncthreads();

    const int h = tid / 64;
    const int t = tid & 63;
    const int ty = t >> 3, tx = t & 7;
    size_t row = ((size_t)b << 16) + (size_t)(wy * 8 + ty) * 256 + (wx * 8 + tx);

    float2 q2[15];
    const __nv_bfloat162* qp = (const __nv_bfloat162*)(qkv + row * 540 + h * HDIM);
    const float scale = 0.18257418583505536f;  // 30^-0.5
#pragma unroll
    for (int d = 0; d < 15; d++) {
        __nv_bfloat162 qv = qp[d];
        q2[d] = make_float2(__bfloat162float(qv.x) * scale, __bfloat162float(qv.y) * scale);
    }

    const float* br = b_rel + h * 4096 + t * 64;
    float l = 0.f;
    float2 o2[15];
#pragma unroll
    for (int d = 0; d < 15; d++) o2[d] = make_float2(0.f, 0.f);

    for (int j = 0; j < 64; j++) {
        const float2* kj = (const float2*)&kv[j * 360 + h * HDIM];
        float s = br[j];
#pragma unroll
        for (int d = 0; d < 15; d++) {
            float2 kk = kj[d];
            s += q2[d].x * kk.x + q2[d].y * kk.y;
        }
        float p = __expf(s);
        l += p;
        const float2* vj = (const float2*)&kv[j * 360 + 180 + h * HDIM];
#pragma unroll
        for (int d = 0; d < 15; d++) {
            float2 vv = vj[d];
            o2[d].x += p * vv.x;
            o2[d].y += p * vv.y;
        }
    }
    float inv = 1.f / l;
    bf16* op = out + row * KP1 + h * HDIM;
#pragma unroll
    for (int d = 0; d < 15; d++) {
        op[2 * d]     = __float2bfloat16(o2[d].x * inv);
        op[2 * d + 1] = __float2bfloat16(o2[d].y * inv);
    }
}

// ---------------- depthwise 3x3 SAME conv, x-tiled (TX) + rolling-y ----------------
template <typename Tin, typename Tout, int CD, int INS, int OUTS, int GELU, int POOL, int TX>
__global__ void dwconv_tile(const Tin* __restrict__ in,
                            const float* __restrict__ k9,
                            Tout* __restrict__ out,
                            float* __restrict__ pooled) {
    const int c  = threadIdx.x;
    const int x0 = blockIdx.x * TX;
    const int y0 = blockIdx.y * 64;
    const int b  = blockIdx.z;
    float w[9];
#pragma unroll
    for (int i = 0; i < 9; i++) w[i] = k9[c * 9 + i];

    const size_t base = ((size_t)b << 16);
    float r[TX + 2], s[TX + 2], t[TX + 2];

    auto loadrow = [&](int yy, float* dst) {
#pragma unroll
        for (int i = 0; i < TX + 2; i++) {
            int xx = x0 - 1 + i;
            dst[i] = (xx >= 0 && xx < WWID)
                     ? (float)in[(base + (size_t)yy * 256 + xx) * INS + c] : 0.f;
        }
    };

    if (y0 > 0) loadrow(y0 - 1, r);
    else {
#pragma unroll
        for (int i = 0; i < TX + 2; i++) r[i] = 0.f;
    }
    loadrow(y0, s);

    float psum = 0.f;
    for (int yy = y0; yy < y0 + 64; yy++) {
        if (yy + 1 < HH) loadrow(yy + 1, t);
        else {
#pragma unroll
            for (int i = 0; i < TX + 2; i++) t[i] = 0.f;
        }
#pragma unroll
        for (int j = 0; j < TX; j++) {
            float acc = r[j] * w[0] + r[j + 1] * w[1] + r[j + 2] * w[2]
                      + s[j] * w[3] + s[j + 1] * w[4] + s[j + 2] * w[5]
                      + t[j] * w[6] + t[j + 1] * w[7] + t[j + 2] * w[8];
            if (GELU) acc = gelu_exact(acc);
            if (POOL) psum += acc;
            size_t op = (base + (size_t)yy * 256 + x0 + j) * OUTS;
            out[op + c] = (Tout)acc;
            if (OUTS > CD && c < OUTS - CD) out[op + CD + c] = (Tout)0.f;
        }
#pragma unroll
        for (int i = 0; i < TX + 2; i++) { r[i] = s[i]; s[i] = t[i]; }
    }
    if (POOL) atomicAdd(&pooled[b * CD + c], psum * (1.f / (float)LL));
}

// ---------------- channel gate ----------------
__global__ void gate_kernel(const float* __restrict__ pooled,
                            const float* __restrict__ w1,
                            const float* __restrict__ w2,
                            float* __restrict__ cm) {
    const int b = blockIdx.x;
    const int tid = threadIdx.x;   // 180
    __shared__ float t1[C8];
    if (tid < C8) {
        float s = 0.f;
        for (int c = 0; c < CC; c++) s += pooled[b * CC + c] * w1[tid * CC + c];
        t1[tid] = gelu_exact(s);
    }
    __syncthreads();
    float s = 0.f;
#pragma unroll
    for (int j = 0; j < C8; j++) s += t1[j] * w2[tid * C8 + j];
    cm[b * CC + tid] = 1.f / (1.f + expf(-s));
}

// ---------------- launch ----------------
extern "C" void kernel_launch(void* const* d_in, const int* in_sizes, int n_in,
                              void* d_out, int out_size) {
    const float* x       = (const float*)d_in[0];
    const float* w_qkv   = (const float*)d_in[1];
    const float* b_rel   = (const float*)d_in[2];
    const float* w_proj  = (const float*)d_in[3];
    const float* b_proj  = (const float*)d_in[4];
    const float* conv_dw = (const float*)d_in[5];
    const float* cg_w1   = (const float*)d_in[6];
    const float* cg_w2   = (const float*)d_in[7];
    const float* ffn_w1  = (const float*)d_in[8];
    const float* ffn_dw  = (const float*)d_in[9];
    const float* ffn_w2  = (const float*)d_in[10];
    const float* n1_g    = (const float*)d_in[11];
    const float* n1_b    = (const float*)d_in[12];
    const float* n2_g    = (const float*)d_in[13];
    const float* n2_b    = (const float*)d_in[14];
    float* out = (float*)d_out;

    float *xmid, *pooled, *cm;
    bf16 *qkvb, *attnf, *conv, *n1b, *n2b, *hsb, *wb;
    cudaGetSymbolAddress((void**)&qkvb,  g_qkvb);
    cudaGetSymbolAddress((void**)&attnf, g_attnf);
    cudaGetSymbolAddress((void**)&conv,  g_conv);
    cudaGetSymbolAddress((void**)&xmid,  g_xmid);
    cudaGetSymbolAddress((void**)&pooled, g_pooled);
    cudaGetSymbolAddress((void**)&cm,     g_cm);
    cudaGetSymbolAddress((void**)&n1b,   g_n1b);
    cudaGetSymbolAddress((void**)&n2b,   g_n2b);
    cudaGetSymbolAddress((void**)&hsb,   g_hsb);
    cudaGetSymbolAddress((void**)&wb,    g_wb);

    const int PSMEM1    = (128 * (KP1 + 8) + 2 * 64 * (KP1 + 8)) * (int)sizeof(bf16); // 102400
    const int PIPE_SMEM = (2 * 128 * 40 + 2 * 64 * 40) * (int)sizeof(bf16);           // 30720
    const int ATTN_SMEM = 64 * 360 * (int)sizeof(float);                              // 92160
    cudaFuncSetAttribute((const void*)mma_gemm_p<0,1>, cudaFuncAttributeMaxDynamicSharedMemorySize, PSMEM1);
    cudaFuncSetAttribute((const void*)mma_gemm_p<1,1>, cudaFuncAttributeMaxDynamicSharedMemorySize, PSMEM1);
    cudaFuncSetAttribute((const void*)mma_gemm_p<2,1>, cudaFuncAttributeMaxDynamicSharedMemorySize, PSMEM1);
    cudaFuncSetAttribute((const void*)mma_gemm_res,    cudaFuncAttributeMaxDynamicSharedMemorySize, PIPE_SMEM);
    cudaFuncSetAttribute((const void*)attn_kernel,     cudaFuncAttributeMaxDynamicSharedMemorySize, ATTN_SMEM);

    // 0) convert + pad weights to bf16
    convw_kernel<<<(576 * 192 + 255) / 256, 256>>>(w_qkv,  wb + WB_QKV,  540, 180, 576, 192);
    convw_kernel<<<(192 * 192 + 255) / 256, 256>>>(w_proj, wb + WB_PROJ, 180, 180, 192, 192);
    convw_kernel<<<(384 * 192 + 255) / 256, 256>>>(ffn_w1, wb + WB_FFN1, 360, 180, 384, 192);
    convw_kernel<<<(192 * 384 + 255) / 256, 256>>>(ffn_w2, wb + WB_FFN2, 180, 360, 192, 384);

    // 1) ln1: x -> n1b (bf16, padded)
    ln_kernel<<<MROWS / 4, 128>>>(x, n1_g, n1_b, n1b);

    // 2) qkv = n1 @ w_qkv^T  (bf16 out, N=540, stride 540, 9 n-tiles)
    mma_gemm_p<0,1><<<MROWS / 128, 256, PSMEM1>>>(n1b, wb + WB_QKV, nullptr, nullptr, qkvb, 540, KP1, 540, 9);

    // 3) window attention -> n2b (bf16, padded)
    attn_kernel<<<NWIN, 384, ATTN_SMEM>>>(qkvb, b_rel, n2b);

    // 4) proj: attnf = attn @ w_proj^T + b_proj  (bf16 out, stride 180)
    mma_gemm_p<1,1><<<MROWS / 128, 256, PSMEM1>>>(n2b, wb + WB_PROJ, b_proj, nullptr, attnf, 180, KP1, 180, 3);

    // 5) conv branch: dwconv(n1b)+GELU -> conv (bf16), fused mean-pool (fp32)
    cudaMemsetAsync(pooled, 0, BB * CC * sizeof(float));
    dwconv_tile<bf16, bf16, CC, KP1, CC, 1, 1, 8><<<dim3(WWID / 8, 4, BB), CC>>>(n1b, conv_dw, conv, pooled);

    // 6) channel gate -> cm
    gate_kernel<<<BB, CC>>>(pooled, cg_w1, cg_w2, cm);

    // 7) fused residual + ln2: xmid (fp32), n2 -> n2b (bf16)
    resid_ln_kernel<<<MROWS / 4, 128>>>(x, attnf, conv, cm, n2_g, n2_b, xmid, n2b);

    // 8) ffn1: h = gelu(n2 @ ffn_w1^T) -> qkvb buffer (bf16, stride 384, N=360)
    mma_gemm_p<2,1><<<MROWS / 128, 256, PSMEM1>>>(n2b, wb + WB_FFN1, nullptr, nullptr, qkvb, 360, KP1, 384, 6);

    // 9) ffn dwconv: hsb = dwconv(h) (bf16 in stride 384, bf16 out padded 384)
    dwconv_tile<bf16, bf16, CFFN, KP2, KP2, 0, 0, 8><<<dim3(WWID / 8, 4, BB), CFFN>>>(qkvb, ffn_dw, hsb, nullptr);

    // 10) ffn2 + residual: out = xmid + hsb @ ffn_w2^T  (pipelined, KP=384)
    mma_gemm_res<<<dim3(MROWS / 128, 3), 256, PIPE_SMEM>>>(hsb, wb + WB_FFN2, xmid, out, 180, KP2);
}

// round 14
// speedup vs baseline: 1.6863x; 1.5523x over previous
#include <cuda_runtime.h>
#include <cuda_bf16.h>
#include <math.h>
#include <cstdint>

using bf16 = __nv_bfloat16;

// ---------------- problem constants ----------------
#define BB 2
#define HH 256
#define WWID 256
#define LL 65536          // H*W
#define CC 180
#define NHD 6
#define HDIM 30
#define NWIN 2048         // B * (H/8) * (W/8)
#define CFFN 360
#define C8 22             // 180 // 8
#define MROWS (BB*LL)     // 131072
#define KP1 192           // padded K for K=180
#define KP2 384           // padded K for K=360

// ---------------- scratch (device globals, no allocation) ----------------
__device__ bf16  g_qkvb [(size_t)MROWS*540];   // qkv bf16; reused for h (stride 384)
__device__ float g_attnf[(size_t)MROWS*CC];
__device__ float g_conv [(size_t)MROWS*CC];
__device__ float g_xmid [(size_t)MROWS*CC];
__device__ float g_pooled[BB*CC];
__device__ float g_cm    [BB*CC];
__device__ bf16  g_n1b[(size_t)MROWS*KP1];     // ln1 out (bf16, padded)
__device__ bf16  g_n2b[(size_t)MROWS*KP1];     // attn out, then n2 (bf16, padded)
__device__ bf16  g_hsb[(size_t)MROWS*KP2];     // ffn dwconv out (bf16, padded)
__device__ bf16  g_wb [294912];                // padded bf16 weights

#define WB_QKV  0        // 576 x 192
#define WB_PROJ 110592   // 192 x 192
#define WB_FFN1 147456   // 384 x 192
#define WB_FFN2 221184   // 192 x 384

__device__ __forceinline__ float gelu_exact(float x) {
    return 0.5f * x * (1.0f + erff(x * 0.70710678118654752f));
}

__device__ __forceinline__ uint32_t pk_bf2(float a, float b) {
    __nv_bfloat162 t = __floats2bfloat162_rn(a, b);
    return *(uint32_t*)&t;
}

#define MMA16816(ACC, A0, A1, A2, A3, B0, B1)                                   \
    asm volatile(                                                               \
        "mma.sync.aligned.m16n8k16.row.col.f32.bf16.bf16.f32 "                  \
        "{%0,%1,%2,%3},{%4,%5,%6,%7},{%8,%9},{%0,%1,%2,%3};\n"                  \
        : "+f"((ACC)[0]), "+f"((ACC)[1]), "+f"((ACC)[2]), "+f"((ACC)[3])        \
        : "r"(A0), "r"(A1), "r"(A2), "r"(A3), "r"(B0), "r"(B1))

// ---------------- weight convert + pad: src[N][K] fp32 -> dst[NP][KP] bf16 ----------------
__global__ void convw_kernel(const float* __restrict__ src, bf16* __restrict__ dst,
                             int N, int K, int NP, int KP) {
    int i = blockIdx.x * 256 + threadIdx.x;
    if (i < NP * KP) {
        int n = i / KP, k = i - n * KP;
        float v = (n < N && k < K) ? src[n * K + k] : 0.f;
        dst[i] = __float2bfloat16(v);
    }
}

// ---------------- LayerNorm (emits bf16, KP1-padded) ----------------
__global__ void ln_kernel(const float* __restrict__ x,
                          const float* __restrict__ g,
                          const float* __restrict__ b,
                          bf16* __restrict__ out) {
    int row = blockIdx.x * 4 + (threadIdx.x >> 5);
    int lane = threadIdx.x & 31;
    const float* xr = x + (size_t)row * CC;
    float v[6];
    float s = 0.f;
#pragma unroll
    for (int i = 0; i < 6; i++) {
        int c = lane + 32 * i;
        v[i] = (c < CC) ? xr[c] : 0.f;
        s += v[i];
    }
#pragma unroll
    for (int o = 16; o; o >>= 1) s += __shfl_xor_sync(0xffffffffu, s, o);
    float mean = s * (1.f / CC);
    float vs = 0.f;
#pragma unroll
    for (int i = 0; i < 6; i++) {
        int c = lane + 32 * i;
        if (c < CC) { float d = v[i] - mean; vs += d * d; }
    }
#pragma unroll
    for (int o = 16; o; o >>= 1) vs += __shfl_xor_sync(0xffffffffu, vs, o);
    float rstd = rsqrtf(vs * (1.f / CC) + 1e-5f);
    bf16* orow = out + (size_t)row * KP1;
#pragma unroll
    for (int i = 0; i < 6; i++) {
        int c = lane + 32 * i;
        float val = (c < CC) ? (v[i] - mean) * rstd * g[c] + b[c] : 0.f;
        orow[c] = __float2bfloat16(val);
    }
}

// ---------------- fused: xmid = x + attnf*cm + conv; n2 = bf16(LN(xmid)) ----------------
__global__ void resid_ln_kernel(const float* __restrict__ x,
                                const float* __restrict__ attnf,
                                const float* __restrict__ conv,
                                const float* __restrict__ cm,
                                const float* __restrict__ g,
                                const float* __restrict__ b,
                                float* __restrict__ xmid,
                                bf16* __restrict__ n2) {
    int row = blockIdx.x * 4 + (threadIdx.x >> 5);
    int lane = threadIdx.x & 31;
    int bb = row >> 16;
    size_t base = (size_t)row * CC;
    float v[6];
    float s = 0.f;
#pragma unroll
    for (int i = 0; i < 6; i++) {
        int c = lane + 32 * i;
        if (c < CC) {
            float xv = x[base + c] + attnf[base + c] * cm[bb * CC + c] + conv[base + c];
            xmid[base + c] = xv;
            v[i] = xv;
        } else v[i] = 0.f;
        s += v[i];
    }
#pragma unroll
    for (int o = 16; o; o >>= 1) s += __shfl_xor_sync(0xffffffffu, s, o);
    float mean = s * (1.f / CC);
    float vs = 0.f;
#pragma unroll
    for (int i = 0; i < 6; i++) {
        int c = lane + 32 * i;
        if (c < CC) { float d = v[i] - mean; vs += d * d; }
    }
#pragma unroll
    for (int o = 16; o; o >>= 1) vs += __shfl_xor_sync(0xffffffffu, vs, o);
    float rstd = rsqrtf(vs * (1.f / CC) + 1e-5f);
    bf16* orow = n2 + (size_t)row * KP1;
#pragma unroll
    for (int i = 0; i < 6; i++) {
        int c = lane + 32 * i;
        float val = (c < CC) ? (v[i] - mean) * rstd * g[c] + b[c] : 0.f;
        orow[c] = __float2bfloat16(val);
    }
}

// ======== A-resident persistent GEMM: A[128xKP] in smem, loop n-tiles ========
// EPI: 0=none 1=+bias 2=gelu ; OBF: 1 -> bf16 output (stride OS), 0 -> fp32 output
template <int EPI, int OBF>
__global__ void __launch_bounds__(256) mma_gemm_p(const bf16* __restrict__ A,
                                                  const bf16* __restrict__ Wt,
                                                  const float* __restrict__ bias,
                                                  float* __restrict__ Cf,
                                                  bf16* __restrict__ Cb,
                                                  int N, int KP, int OS, int NT) {
    extern __shared__ bf16 sm[];
    const int AST = KP + 8;               // row stride (bf16)
    bf16* As = sm;                        // [128][AST]
    bf16* Bs = sm + 128 * AST;            // [2][64][AST]
    const int tid  = threadIdx.x;
    const int row0 = blockIdx.x * 128;
    const int wid  = tid >> 5;
    const int lane = tid & 31;
    const int warpm = wid >> 1;
    const int warpn = wid & 1;
    const int gr = lane >> 2;
    const int cq = lane & 3;
    const int NS = KP >> 4;               // k16 steps
    const int KC = KP >> 3;               // 16B chunks per row

    uint32_t sA = (uint32_t)__cvta_generic_to_shared(As);
    uint32_t sB = (uint32_t)__cvta_generic_to_shared(Bs);

    for (int cid = tid; cid < 128 * KC; cid += 256) {
        int m = cid / KC, kc = (cid - m * KC) << 3;
        const bf16* g = A + (size_t)(row0 + m) * KP + kc;
        uint32_t sa = sA + (uint32_t)(m * AST + kc) * 2;
        asm volatile("cp.async.cg.shared.global [%0], [%1], 16;\n" :: "r"(sa), "l"(g));
    }
    auto issueB = [&](int t) {
        uint32_t bbase = sB + (t & 1) * (64 * AST * 2);
        const bf16* wt0 = Wt + (size_t)(t * 64) * KP;
        for (int cid = tid; cid < 64 * KC; cid += 256) {
            int n = cid / KC, kc = (cid - n * KC) << 3;
            uint32_t sb = bbase + (uint32_t)(n * AST + kc) * 2;
            asm volatile("cp.async.cg.shared.global [%0], [%1], 16;\n"
                         :: "r"(sb), "l"(wt0 + (size_t)n * KP + kc));
        }
        asm volatile("cp.async.commit_group;\n");
    };

    issueB(0);

    for (int t = 0; t < NT; t++) {
        if (t + 1 < NT) { issueB(t + 1); asm volatile("cp.async.wait_group 1;\n"); }
        else            { asm volatile("cp.async.wait_group 0;\n"); }
        __syncthreads();

        float acc[2][4][4];
#pragma unroll
        for (int a = 0; a < 2; a++)
#pragma unroll
            for (int b = 0; b < 4; b++)
#pragma unroll
                for (int c = 0; c < 4; c++) acc[a][b][c] = 0.f;

        const bf16* Bb = Bs + (t & 1) * (64 * AST);
        for (int ks = 0; ks < NS; ks++) {
            uint32_t afr[2][4], bfr[4][2];
#pragma unroll
            for (int mt = 0; mt < 2; mt++) {
                const bf16* p = As + (warpm * 32 + mt * 16 + gr) * AST + ks * 16 + cq * 2;
                afr[mt][0] = *(const uint32_t*)p;
                afr[mt][1] = *(const uint32_t*)(p + 8 * AST);
                afr[mt][2] = *(const uint32_t*)(p + 8);
                afr[mt][3] = *(const uint32_t*)(p + 8 * AST + 8);
            }
#pragma unroll
            for (int nt = 0; nt < 4; nt++) {
                const bf16* p = Bb + (warpn * 32 + nt * 8 + gr) * AST + ks * 16 + cq * 2;
                bfr[nt][0] = *(const uint32_t*)p;
                bfr[nt][1] = *(const uint32_t*)(p + 8);
            }
#pragma unroll
            for (int mt = 0; mt < 2; mt++)
#pragma unroll
                for (int nt = 0; nt < 4; nt++)
                    MMA16816(acc[mt][nt], afr[mt][0], afr[mt][1], afr[mt][2], afr[mt][3],
                             bfr[nt][0], bfr[nt][1]);
        }

        const int col0 = t * 64;
#pragma unroll
        for (int mt = 0; mt < 2; mt++) {
            int r0 = row0 + warpm * 32 + mt * 16 + gr;
#pragma unroll
            for (int nt = 0; nt < 4; nt++) {
                int cb = col0 + warpn * 32 + nt * 8 + cq * 2;
                if (cb < N) {
                    float v00 = acc[mt][nt][0], v01 = acc[mt][nt][1];
                    float v10 = acc[mt][nt][2], v11 = acc[mt][nt][3];
                    if (EPI == 1) { float b0 = bias[cb], b1 = bias[cb + 1];
                                    v00 += b0; v01 += b1; v10 += b0; v11 += b1; }
                    if (EPI == 2) { v00 = gelu_exact(v00); v01 = gelu_exact(v01);
                                    v10 = gelu_exact(v10); v11 = gelu_exact(v11); }
                    if (OBF) {
                        __nv_bfloat162 p0, p1;
                        p0.x = __float2bfloat16(v00); p0.y = __float2bfloat16(v01);
                        p1.x = __float2bfloat16(v10); p1.y = __float2bfloat16(v11);
                        *(__nv_bfloat162*)&Cb[(size_t)r0 * OS + cb]       = p0;
                        *(__nv_bfloat162*)&Cb[(size_t)(r0 + 8) * OS + cb] = p1;
                    } else {
                        *(float2*)&Cf[(size_t)r0 * OS + cb]       = make_float2(v00, v01);
                        *(float2*)&Cf[(size_t)(r0 + 8) * OS + cb] = make_float2(v10, v11);
                    }
                }
            }
        }
        __syncthreads();
    }
}

// ======== pipelined GEMM (KP=384 ffn2): C = A @ W^T + residual ========
__global__ void __launch_bounds__(256) mma_gemm_res(const bf16* __restrict__ A,
                                                    const bf16* __restrict__ Wt,
                                                    const float* __restrict__ res,
                                                    float* __restrict__ Cout,
                                                    int N, int KP) {
    extern __shared__ bf16 sm[];
    bf16* As = sm;                       // [2][128][40]
    bf16* Bs = sm + 2 * 128 * 40;        // [2][64][40]
    const int tid  = threadIdx.x;
    const int row0 = blockIdx.x * 128;
    const int col0 = blockIdx.y * 64;
    const int NS   = KP >> 5;
    const int wid  = tid >> 5;
    const int lane = tid & 31;
    const int warpm = wid >> 1;
    const int warpn = wid & 1;
    const int gr = lane >> 2;
    const int cq = lane & 3;

    uint32_t sA = (uint32_t)__cvta_generic_to_shared(As);
    uint32_t sB = (uint32_t)__cvta_generic_to_shared(Bs);

    auto issue = [&](int s) {
        const int k0  = s << 5;
        const int buf = s & 1;
        uint32_t abase = sA + buf * (128 * 40 * 2);
        uint32_t bbase = sB + buf * (64 * 40 * 2);
#pragma unroll
        for (int i = 0; i < 2; i++) {
            int cid = tid + 256 * i;
            int m = cid >> 2, kc = (cid & 3) << 3;
            const bf16* g = A + (size_t)(row0 + m) * KP + k0 + kc;
            uint32_t sa = abase + (uint32_t)(m * 40 + kc) * 2;
            asm volatile("cp.async.cg.shared.global [%0], [%1], 16;\n" :: "r"(sa), "l"(g));
        }
        {
            int n = tid >> 2, kc = (tid & 3) << 3;
            const bf16* g = Wt + (size_t)(col0 + n) * KP + k0 + kc;
            uint32_t sb = bbase + (uint32_t)(n * 40 + kc) * 2;
            asm volatile("cp.async.cg.shared.global [%0], [%1], 16;\n" :: "r"(sb), "l"(g));
        }
        asm volatile("cp.async.commit_group;\n");
    };

    float acc[2][4][4];
#pragma unroll
    for (int a = 0; a < 2; a++)
#pragma unroll
        for (int b = 0; b < 4; b++)
#pragma unroll
            for (int c = 0; c < 4; c++) acc[a][b][c] = 0.f;

    issue(0);
    for (int s = 0; s < NS; s++) {
        if (s + 1 < NS) { issue(s + 1); asm volatile("cp.async.wait_group 1;\n"); }
        else            { asm volatile("cp.async.wait_group 0;\n"); }
        __syncthreads();
        const bf16* Ab = As + (s & 1) * (128 * 40);
        const bf16* Bb = Bs + (s & 1) * (64 * 40);
#pragma unroll
        for (int kk = 0; kk < 2; kk++) {
            uint32_t afr[2][4], bfr[4][2];
#pragma unroll
            for (int mt = 0; mt < 2; mt++) {
                const bf16* p = Ab + (warpm * 32 + mt * 16 + gr) * 40 + kk * 16 + cq * 2;
                afr[mt][0] = *(const uint32_t*)p;
                afr[mt][1] = *(const uint32_t*)(p + 8 * 40);
                afr[mt][2] = *(const uint32_t*)(p + 8);
                afr[mt][3] = *(const uint32_t*)(p + 8 * 40 + 8);
            }
#pragma unroll
            for (int nt = 0; nt < 4; nt++) {
                const bf16* p = Bb + (warpn * 32 + nt * 8 + gr) * 40 + kk * 16 + cq * 2;
                bfr[nt][0] = *(const uint32_t*)p;
                bfr[nt][1] = *(const uint32_t*)(p + 8);
            }
#pragma unroll
            for (int mt = 0; mt < 2; mt++)
#pragma unroll
                for (int nt = 0; nt < 4; nt++)
                    MMA16816(acc[mt][nt], afr[mt][0], afr[mt][1], afr[mt][2], afr[mt][3],
                             bfr[nt][0], bfr[nt][1]);
        }
        __syncthreads();
    }

#pragma unroll
    for (int mt = 0; mt < 2; mt++) {
        int r0 = row0 + warpm * 32 + mt * 16 + gr;
#pragma unroll
        for (int nt = 0; nt < 4; nt++) {
            int cb = col0 + warpn * 32 + nt * 8 + cq * 2;
            if (cb < N) {
                const float2 r0v = *(const float2*)&res[(size_t)r0 * N + cb];
                const float2 r1v = *(const float2*)&res[(size_t)(r0 + 8) * N + cb];
                *(float2*)&Cout[(size_t)r0 * N + cb] =
                    make_float2(acc[mt][nt][0] + r0v.x, acc[mt][nt][1] + r0v.y);
                *(float2*)&Cout[(size_t)(r0 + 8) * N + cb] =
                    make_float2(acc[mt][nt][2] + r1v.x, acc[mt][nt][3] + r1v.y);
            }
        }
    }
}

// ======== MMA window attention: 1 block/window, 12 warps = 2 per head ========
// S = Q K^T (fp32 acc) -> +b_rel -> exp (no max; scores provably small) -> row-sum
// -> P (bf16, normalized) -> O = P V. Output bf16, KP1-padded.
__global__ void __launch_bounds__(384) attn_mma(const bf16* __restrict__ qkv,
                                                const float* __restrict__ b_rel,
                                                bf16* __restrict__ out) {
    extern __shared__ bf16 smA[];
    bf16* Qs = smA;                    // [6*64][40]  (token-major, dims padded 32->40)
    bf16* Ks = Qs + 6 * 64 * 40;       // [6*64][40]
    bf16* Vs = Ks + 6 * 64 * 40;       // [6*32][72]  (dim-major, tokens padded 64->72)
    const int w = blockIdx.x;
    const int b  = w >> 10;
    const int wy = (w & 1023) >> 5;
    const int wx = w & 31;
    const int tid = threadIdx.x;       // 384
    const float scale = 0.18257418583505536f;  // 30^-0.5

    // stage Q (scaled), K, V^T ; zero dims 30..31
    for (int idx = tid; idx < 6 * 64 * 16; idx += 384) {
        int h   = idx >> 10;
        int rem = idx & 1023;
        int t   = rem >> 4;
        int dp  = rem & 15;            // dim pair: dims 2dp, 2dp+1
        int ty = t >> 3, tx = t & 7;
        size_t row = ((size_t)b << 16) + (size_t)(wy * 8 + ty) * 256 + (wx * 8 + tx);
        const bf16* base = qkv + row * 540 + h * HDIM + 2 * dp;
        uint32_t qv = 0, kw = 0;
        __nv_bfloat162 vp; vp.x = __float2bfloat16(0.f); vp.y = vp.x;
        if (dp < 15) {
            __nv_bfloat162 q2 = *(const __nv_bfloat162*)base;
            qv = pk_bf2(__bfloat162float(q2.x) * scale, __bfloat162float(q2.y) * scale);
            kw = *(const uint32_t*)(base + 180);
            vp = *(const __nv_bfloat162*)(base + 360);
        }
        *(uint32_t*)&Qs[(h * 64 + t) * 40 + 2 * dp] = qv;
        *(uint32_t*)&Ks[(h * 64 + t) * 40 + 2 * dp] = kw;
        Vs[(h * 32 + 2 * dp)     * 72 + t] = vp.x;
        Vs[(h * 32 + 2 * dp + 1) * 72 + t] = vp.y;
    }
    // zero padding cols 180..191 of out for this window
    for (int idx = tid; idx < 64 * 12; idx += 384) {
        int t = idx / 12, c = idx - t * 12;
        int ty = t >> 3, tx = t & 7;
        size_t row = ((size_t)b << 16) + (size_t)(wy * 8 + ty) * 256 + (wx * 8 + tx);
        out[row * KP1 + 180 + c] = __float2bfloat16(0.f);
    }
    __syncthreads();

    const int wid  = tid >> 5;
    const int lane = tid & 31;
    const int h     = wid >> 1;        // head
    const int mbase = (wid & 1) * 32;  // half: rows 0..31 or 32..63
    const int gr = lane >> 2;
    const int cq = lane & 3;

    // Q fragments (rows mbase..mbase+31, k = 32 dims in 2 chunks)
    uint32_t qf[2][2][4];
#pragma unroll
    for (int mt = 0; mt < 2; mt++)
#pragma unroll
        for (int kk = 0; kk < 2; kk++) {
            const bf16* p = Qs + (h * 64 + mbase + mt * 16 + gr) * 40 + kk * 16 + cq * 2;
            qf[mt][kk][0] = *(const uint32_t*)p;
            qf[mt][kk][1] = *(const uint32_t*)(p + 8 * 40);
            qf[mt][kk][2] = *(const uint32_t*)(p + 8);
            qf[mt][kk][3] = *(const uint32_t*)(p + 8 * 40 + 8);
        }

    // S = Q K^T : 32 x 64 per warp
    float sacc[2][8][4];
#pragma unroll
    for (int mt = 0; mt < 2; mt++)
#pragma unroll
        for (int nt = 0; nt < 8; nt++)
#pragma unroll
            for (int c = 0; c < 4; c++) sacc[mt][nt][c] = 0.f;

#pragma unroll
    for (int nt = 0; nt < 8; nt++) {
        uint32_t kf[2][2];
#pragma unroll
        for (int kk = 0; kk < 2; kk++) {
            const bf16* p = Ks + (h * 64 + nt * 8 + gr) * 40 + kk * 16 + cq * 2;
            kf[kk][0] = *(const uint32_t*)p;
            kf[kk][1] = *(const uint32_t*)(p + 8);
        }
#pragma unroll
        for (int mt = 0; mt < 2; mt++)
#pragma unroll
            for (int kk = 0; kk < 2; kk++)
                MMA16816(sacc[mt][nt], qf[mt][kk][0], qf[mt][kk][1], qf[mt][kk][2], qf[mt][kk][3],
                         kf[kk][0], kf[kk][1]);
    }

    // + b_rel, exp, row sums (no max: |s| is small by construction)
    const float* brh = b_rel + h * 4096;
    float l0[2] = {0.f, 0.f}, l1[2] = {0.f, 0.f};
#pragma unroll
    for (int mt = 0; mt < 2; mt++) {
        int r = mbase + mt * 16 + gr;
#pragma unroll
        for (int nt = 0; nt < 8; nt++) {
            int cb = nt * 8 + cq * 2;
            float2 br0 = *(const float2*)&brh[r * 64 + cb];
            float2 br1 = *(const float2*)&brh[(r + 8) * 64 + cb];
            float e0 = __expf(sacc[mt][nt][0] + br0.x);
            float e1 = __expf(sacc[mt][nt][1] + br0.y);
            float e2 = __expf(sacc[mt][nt][2] + br1.x);
            float e3 = __expf(sacc[mt][nt][3] + br1.y);
            sacc[mt][nt][0] = e0; sacc[mt][nt][1] = e1;
            sacc[mt][nt][2] = e2; sacc[mt][nt][3] = e3;
            l0[mt] += e0 + e1;
            l1[mt] += e2 + e3;
        }
    }
#pragma unroll
    for (int o = 1; o <= 2; o <<= 1) {
#pragma unroll
        for (int mt = 0; mt < 2; mt++) {
            l0[mt] += __shfl_xor_sync(0xffffffffu, l0[mt], o);
            l1[mt] += __shfl_xor_sync(0xffffffffu, l1[mt], o);
        }
    }
    float inv0[2], inv1[2];
#pragma unroll
    for (int mt = 0; mt < 2; mt++) { inv0[mt] = 1.f / l0[mt]; inv1[mt] = 1.f / l1[mt]; }

    // pack P (normalized) into A-operand fragments: k-chunk kc = tokens kc*16..+15
    uint32_t pb[2][4][4];
#pragma unroll
    for (int mt = 0; mt < 2; mt++)
#pragma unroll
        for (int kc = 0; kc < 4; kc++) {
            int n0 = 2 * kc, n1 = 2 * kc + 1;
            pb[mt][kc][0] = pk_bf2(sacc[mt][n0][0] * inv0[mt], sacc[mt][n0][1] * inv0[mt]);
            pb[mt][kc][1] = pk_bf2(sacc[mt][n0][2] * inv1[mt], sacc[mt][n0][3] * inv1[mt]);
            pb[mt][kc][2] = pk_bf2(sacc[mt][n1][0] * inv0[mt], sacc[mt][n1][1] * inv0[mt]);
            pb[mt][kc][3] = pk_bf2(sacc[mt][n1][2] * inv1[mt], sacc[mt][n1][3] * inv1[mt]);
        }

    // O = P V : 32 x 32 per warp (cols 30,31 discarded)
    float oacc[2][4][4];
#pragma unroll
    for (int mt = 0; mt < 2; mt++)
#pragma unroll
        for (int nt = 0; nt < 4; nt++)
#pragma unroll
            for (int c = 0; c < 4; c++) oacc[mt][nt][c] = 0.f;

#pragma unroll
    for (int nt = 0; nt < 4; nt++) {
        uint32_t vf[4][2];
#pragma unroll
        for (int kc = 0; kc < 4; kc++) {
            const bf16* p = Vs + (h * 32 + nt * 8 + gr) * 72 + kc * 16 + cq * 2;
            vf[kc][0] = *(const uint32_t*)p;
            vf[kc][1] = *(const uint32_t*)(p + 8);
        }
#pragma unroll
        for (int mt = 0; mt < 2; mt++)
#pragma unroll
            for (int kc = 0; kc < 4; kc++)
                MMA16816(oacc[mt][nt], pb[mt][kc][0], pb[mt][kc][1], pb[mt][kc][2], pb[mt][kc][3],
                         vf[kc][0], vf[kc][1]);
    }

    // write output (bf16, KP1-padded rows)
#pragma unroll
    for (int mt = 0; mt < 2; mt++) {
        int r = mbase + mt * 16 + gr;
        size_t rg0 = ((size_t)b << 16) + (size_t)(wy * 8 + (r >> 3)) * 256 + (wx * 8 + (r & 7));
        int r8 = r + 8;
        size_t rg1 = ((size_t)b << 16) + (size_t)(wy * 8 + (r8 >> 3)) * 256 + (wx * 8 + (r8 & 7));
#pragma unroll
        for (int nt = 0; nt < 4; nt++) {
            int cb = nt * 8 + cq * 2;
            if (cb < HDIM) {
                __nv_bfloat162 p0, p1;
                p0.x = __float2bfloat16(oacc[mt][nt][0]); p0.y = __float2bfloat16(oacc[mt][nt][1]);
                p1.x = __float2bfloat16(oacc[mt][nt][2]); p1.y = __float2bfloat16(oacc[mt][nt][3]);
                *(__nv_bfloat162*)&out[rg0 * KP1 + h * HDIM + cb] = p0;
                *(__nv_bfloat162*)&out[rg1 * KP1 + h * HDIM + cb] = p1;
            }
        }
    }
}

// ---------------- depthwise 3x3 SAME conv, x-tiled (TX) + rolling-y ----------------
template <typename Tin, typename Tout, int CD, int INS, int OUTS, int GELU, int POOL, int TX>
__global__ void dwconv_tile(const Tin* __restrict__ in,
                            const float* __restrict__ k9,
                            Tout* __restrict__ out,
                            float* __restrict__ pooled) {
    const int c  = threadIdx.x;
    const int x0 = blockIdx.x * TX;
    const int y0 = blockIdx.y * 64;
    const int b  = blockIdx.z;
    float w[9];
#pragma unroll
    for (int i = 0; i < 9; i++) w[i] = k9[c * 9 + i];

    const size_t base = ((size_t)b << 16);
    float r[TX + 2], s[TX + 2], t[TX + 2];

    auto loadrow = [&](int yy, float* dst) {
#pragma unroll
        for (int i = 0; i < TX + 2; i++) {
            int xx = x0 - 1 + i;
            dst[i] = (xx >= 0 && xx < WWID)
                     ? (float)in[(base + (size_t)yy * 256 + xx) * INS + c] : 0.f;
        }
    };

    if (y0 > 0) loadrow(y0 - 1, r);
    else {
#pragma unroll
        for (int i = 0; i < TX + 2; i++) r[i] = 0.f;
    }
    loadrow(y0, s);

    float psum = 0.f;
    for (int yy = y0; yy < y0 + 64; yy++) {
        if (yy + 1 < HH) loadrow(yy + 1, t);
        else {
#pragma unroll
            for (int i = 0; i < TX + 2; i++) t[i] = 0.f;
        }
#pragma unroll
        for (int j = 0; j < TX; j++) {
            float acc = r[j] * w[0] + r[j + 1] * w[1] + r[j + 2] * w[2]
                      + s[j] * w[3] + s[j + 1] * w[4] + s[j + 2] * w[5]
                      + t[j] * w[6] + t[j + 1] * w[7] + t[j + 2] * w[8];
            if (GELU) acc = gelu_exact(acc);
            if (POOL) psum += acc;
            size_t op = (base + (size_t)yy * 256 + x0 + j) * OUTS;
            out[op + c] = (Tout)acc;
            if (OUTS > CD && c < OUTS - CD) out[op + CD + c] = (Tout)0.f;
        }
#pragma unroll
        for (int i = 0; i < TX + 2; i++) { r[i] = s[i]; s[i] = t[i]; }
    }
    if (POOL) atomicAdd(&pooled[b * CD + c], psum * (1.f / (float)LL));
}

// ---------------- channel gate ----------------
__global__ void gate_kernel(const float* __restrict__ pooled,
                            const float* __restrict__ w1,
                            const float* __restrict__ w2,
                            float* __restrict__ cm) {
    const int b = blockIdx.x;
    const int tid = threadIdx.x;   // 180
    __shared__ float t1[C8];
    if (tid < C8) {
        float s = 0.f;
        for (int c = 0; c < CC; c++) s += pooled[b * CC + c] * w1[tid * CC + c];
        t1[tid] = gelu_exact(s);
    }
    __syncthreads();
    float s = 0.f;
#pragma unroll
    for (int j = 0; j < C8; j++) s += t1[j] * w2[tid * C8 + j];
    cm[b * CC + tid] = 1.f / (1.f + expf(-s));
}

// ---------------- launch ----------------
extern "C" void kernel_launch(void* const* d_in, const int* in_sizes, int n_in,
                              void* d_out, int out_size) {
    const float* x       = (const float*)d_in[0];
    const float* w_qkv   = (const float*)d_in[1];
    const float* b_rel   = (const float*)d_in[2];
    const float* w_proj  = (const float*)d_in[3];
    const float* b_proj  = (const float*)d_in[4];
    const float* conv_dw = (const float*)d_in[5];
    const float* cg_w1   = (const float*)d_in[6];
    const float* cg_w2   = (const float*)d_in[7];
    const float* ffn_w1  = (const float*)d_in[8];
    const float* ffn_dw  = (const float*)d_in[9];
    const float* ffn_w2  = (const float*)d_in[10];
    const float* n1_g    = (const float*)d_in[11];
    const float* n1_b    = (const float*)d_in[12];
    const float* n2_g    = (const float*)d_in[13];
    const float* n2_b    = (const float*)d_in[14];
    float* out = (float*)d_out;

    float *attnf, *conv, *xmid, *pooled, *cm;
    bf16 *qkvb, *n1b, *n2b, *hsb, *wb;
    cudaGetSymbolAddress((void**)&qkvb,  g_qkvb);
    cudaGetSymbolAddress((void**)&attnf, g_attnf);
    cudaGetSymbolAddress((void**)&conv,  g_conv);
    cudaGetSymbolAddress((void**)&xmid,  g_xmid);
    cudaGetSymbolAddress((void**)&pooled, g_pooled);
    cudaGetSymbolAddress((void**)&cm,     g_cm);
    cudaGetSymbolAddress((void**)&n1b,   g_n1b);
    cudaGetSymbolAddress((void**)&n2b,   g_n2b);
    cudaGetSymbolAddress((void**)&hsb,   g_hsb);
    cudaGetSymbolAddress((void**)&wb,    g_wb);

    const int PSMEM1    = (128 * (KP1 + 8) + 2 * 64 * (KP1 + 8)) * (int)sizeof(bf16); // 102400
    const int PIPE_SMEM = (2 * 128 * 40 + 2 * 64 * 40) * (int)sizeof(bf16);           // 30720
    const int ATTN_SMEM = (2 * 6 * 64 * 40 + 6 * 32 * 72) * (int)sizeof(bf16);        // 89088
    cudaFuncSetAttribute((const void*)mma_gemm_p<0,1>, cudaFuncAttributeMaxDynamicSharedMemorySize, PSMEM1);
    cudaFuncSetAttribute((const void*)mma_gemm_p<1,0>, cudaFuncAttributeMaxDynamicSharedMemorySize, PSMEM1);
    cudaFuncSetAttribute((const void*)mma_gemm_p<2,1>, cudaFuncAttributeMaxDynamicSharedMemorySize, PSMEM1);
    cudaFuncSetAttribute((const void*)mma_gemm_res,    cudaFuncAttributeMaxDynamicSharedMemorySize, PIPE_SMEM);
    cudaFuncSetAttribute((const void*)attn_mma,        cudaFuncAttributeMaxDynamicSharedMemorySize, ATTN_SMEM);

    // 0) convert + pad weights to bf16
    convw_kernel<<<(576 * 192 + 255) / 256, 256>>>(w_qkv,  wb + WB_QKV,  540, 180, 576, 192);
    convw_kernel<<<(192 * 192 + 255) / 256, 256>>>(w_proj, wb + WB_PROJ, 180, 180, 192, 192);
    convw_kernel<<<(384 * 192 + 255) / 256, 256>>>(ffn_w1, wb + WB_FFN1, 360, 180, 384, 192);
    convw_kernel<<<(192 * 384 + 255) / 256, 256>>>(ffn_w2, wb + WB_FFN2, 180, 360, 192, 384);

    // 1) ln1: x -> n1b (bf16, padded)
    ln_kernel<<<MROWS / 4, 128>>>(x, n1_g, n1_b, n1b);

    // 2) qkv = n1 @ w_qkv^T  (bf16 out, N=540, stride 540, 9 n-tiles)
    mma_gemm_p<0,1><<<MROWS / 128, 256, PSMEM1>>>(n1b, wb + WB_QKV, nullptr, nullptr, qkvb, 540, KP1, 540, 9);

    // 3) MMA window attention -> n2b (bf16, padded)
    attn_mma<<<NWIN, 384, ATTN_SMEM>>>(qkvb, b_rel, n2b);

    // 4) proj: attnf = attn @ w_proj^T + b_proj  (fp32 out)
    mma_gemm_p<1,0><<<MROWS / 128, 256, PSMEM1>>>(n2b, wb + WB_PROJ, b_proj, attnf, nullptr, 180, KP1, 180, 3);

    // 5) conv branch: dwconv(n1b)+GELU -> conv (fp32), fused mean-pool
    cudaMemsetAsync(pooled, 0, BB * CC * sizeof(float));
    dwconv_tile<bf16, float, CC, KP1, CC, 1, 1, 4><<<dim3(WWID / 4, 4, BB), CC>>>(n1b, conv_dw, conv, pooled);

    // 6) channel gate -> cm
    gate_kernel<<<BB, CC>>>(pooled, cg_w1, cg_w2, cm);

    // 7) fused residual + ln2: xmid (fp32), n2 -> n2b (bf16)
    resid_ln_kernel<<<MROWS / 4, 128>>>(x, attnf, conv, cm, n2_g, n2_b, xmid, n2b);

    // 8) ffn1: h = gelu(n2 @ ffn_w1^T) -> qkvb buffer (bf16, stride 384, N=360)
    mma_gemm_p<2,1><<<MROWS / 128, 256, PSMEM1>>>(n2b, wb + WB_FFN1, nullptr, nullptr, qkvb, 360, KP1, 384, 6);

    // 9) ffn dwconv: hsb = dwconv(h) (bf16 in stride 384, bf16 out padded 384)
    dwconv_tile<bf16, bf16, CFFN, KP2, KP2, 0, 0, 4><<<dim3(WWID / 4, 4, BB), CFFN>>>(qkvb, ffn_dw, hsb, nullptr);

    // 10) ffn2 + residual: out = xmid + hsb @ ffn_w2^T  (pipelined, KP=384)
    mma_gemm_res<<<dim3(MROWS / 128, 3), 256, PIPE_SMEM>>>(hsb, wb + WB_FFN2, xmid, out, 180, KP2);
}

// round 16
// speedup vs baseline: 1.6903x; 1.0024x over previous
#include <cuda_runtime.h>
#include <cuda_bf16.h>
#include <math.h>
#include <cstdint>

using bf16 = __nv_bfloat16;

// ---------------- problem constants ----------------
#define BB 2
#define HH 256
#define WWID 256
#define LL 65536          // H*W
#define CC 180
#define NHD 6
#define HDIM 30
#define NWIN 2048         // B * (H/8) * (W/8)
#define CFFN 360
#define C8 22             // 180 // 8
#define MROWS (BB*LL)     // 131072
#define KP1 192           // padded K for K=180
#define KP2 384           // padded K for K=360

// ---------------- scratch (device globals, no allocation) ----------------
__device__ bf16  g_qkvb [(size_t)MROWS*540];   // qkv bf16; reused for h (stride 384)
__device__ float g_attnf[(size_t)MROWS*CC];
__device__ float g_conv [(size_t)MROWS*CC];
__device__ float g_xmid [(size_t)MROWS*CC];
__device__ float g_pooled[BB*CC];
__device__ float g_cm    [BB*CC];
__device__ bf16  g_n1b[(size_t)MROWS*KP1];     // ln1 out (bf16, padded)
__device__ bf16  g_n2b[(size_t)MROWS*KP1];     // attn out, then n2 (bf16, padded)
__device__ bf16  g_hsb[(size_t)MROWS*KP2];     // ffn dwconv out (bf16, padded)
__device__ bf16  g_wb [294912];                // padded bf16 weights

#define WB_QKV  0        // 576 x 192
#define WB_PROJ 110592   // 192 x 192
#define WB_FFN1 147456   // 384 x 192
#define WB_FFN2 221184   // 192 x 384

__device__ __forceinline__ float gelu_exact(float x) {
    return 0.5f * x * (1.0f + erff(x * 0.70710678118654752f));
}

__device__ __forceinline__ uint32_t pk_bf2(float a, float b) {
    __nv_bfloat162 t = __floats2bfloat162_rn(a, b);
    return *(uint32_t*)&t;
}

#define MMA16816(ACC, A0, A1, A2, A3, B0, B1)                                   \
    asm volatile(                                                               \
        "mma.sync.aligned.m16n8k16.row.col.f32.bf16.bf16.f32 "                  \
        "{%0,%1,%2,%3},{%4,%5,%6,%7},{%8,%9},{%0,%1,%2,%3};\n"                  \
        : "+f"((ACC)[0]), "+f"((ACC)[1]), "+f"((ACC)[2]), "+f"((ACC)[3])        \
        : "r"(A0), "r"(A1), "r"(A2), "r"(A3), "r"(B0), "r"(B1))

// ldmatrix: A fragment (16x16) in one x4, B fragment (8x16) in one x2.
// Address mapping reproduces the scalar loads bit-exactly:
//   x4 matrices: M0=(r0-7,c0-7)->a0, M1=(r8-15,c0-7)->a1, M2=(r0-7,c8-15)->a2, M3=(r8-15,c8-15)->a3
#define LDSM4(R, ADDR)                                                          \
    asm volatile("ldmatrix.sync.aligned.m8n8.x4.shared.b16 {%0,%1,%2,%3}, [%4];"\
        : "=r"((R)[0]), "=r"((R)[1]), "=r"((R)[2]), "=r"((R)[3]) : "r"(ADDR))
#define LDSM2(R, ADDR)                                                          \
    asm volatile("ldmatrix.sync.aligned.m8n8.x2.shared.b16 {%0,%1}, [%2];"      \
        : "=r"((R)[0]), "=r"((R)[1]) : "r"(ADDR))

// ---------------- weight convert + pad: src[N][K] fp32 -> dst[NP][KP] bf16 ----------------
__global__ void convw_kernel(const float* __restrict__ src, bf16* __restrict__ dst,
                             int N, int K, int NP, int KP) {
    int i = blockIdx.x * 256 + threadIdx.x;
    if (i < NP * KP) {
        int n = i / KP, k = i - n * KP;
        float v = (n < N && k < K) ? src[n * K + k] : 0.f;
        dst[i] = __float2bfloat16(v);
    }
}

// ---------------- LayerNorm (emits bf16, KP1-padded) ----------------
__global__ void ln_kernel(const float* __restrict__ x,
                          const float* __restrict__ g,
                          const float* __restrict__ b,
                          bf16* __restrict__ out) {
    int row = blockIdx.x * 4 + (threadIdx.x >> 5);
    int lane = threadIdx.x & 31;
    const float* xr = x + (size_t)row * CC;
    float v[6];
    float s = 0.f;
#pragma unroll
    for (int i = 0; i < 6; i++) {
        int c = lane + 32 * i;
        v[i] = (c < CC) ? xr[c] : 0.f;
        s += v[i];
    }
#pragma unroll
    for (int o = 16; o; o >>= 1) s += __shfl_xor_sync(0xffffffffu, s, o);
    float mean = s * (1.f / CC);
    float vs = 0.f;
#pragma unroll
    for (int i = 0; i < 6; i++) {
        int c = lane + 32 * i;
        if (c < CC) { float d = v[i] - mean; vs += d * d; }
    }
#pragma unroll
    for (int o = 16; o; o >>= 1) vs += __shfl_xor_sync(0xffffffffu, vs, o);
    float rstd = rsqrtf(vs * (1.f / CC) + 1e-5f);
    bf16* orow = out + (size_t)row * KP1;
#pragma unroll
    for (int i = 0; i < 6; i++) {
        int c = lane + 32 * i;
        float val = (c < CC) ? (v[i] - mean) * rstd * g[c] + b[c] : 0.f;
        orow[c] = __float2bfloat16(val);
    }
}

// ---------------- fused: xmid = x + attnf*cm + conv; n2 = bf16(LN(xmid)) ----------------
__global__ void resid_ln_kernel(const float* __restrict__ x,
                                const float* __restrict__ attnf,
                                const float* __restrict__ conv,
                                const float* __restrict__ cm,
                                const float* __restrict__ g,
                                const float* __restrict__ b,
                                float* __restrict__ xmid,
                                bf16* __restrict__ n2) {
    int row = blockIdx.x * 4 + (threadIdx.x >> 5);
    int lane = threadIdx.x & 31;
    int bb = row >> 16;
    size_t base = (size_t)row * CC;
    float v[6];
    float s = 0.f;
#pragma unroll
    for (int i = 0; i < 6; i++) {
        int c = lane + 32 * i;
        if (c < CC) {
            float xv = x[base + c] + attnf[base + c] * cm[bb * CC + c] + conv[base + c];
            xmid[base + c] = xv;
            v[i] = xv;
        } else v[i] = 0.f;
        s += v[i];
    }
#pragma unroll
    for (int o = 16; o; o >>= 1) s += __shfl_xor_sync(0xffffffffu, s, o);
    float mean = s * (1.f / CC);
    float vs = 0.f;
#pragma unroll
    for (int i = 0; i < 6; i++) {
        int c = lane + 32 * i;
        if (c < CC) { float d = v[i] - mean; vs += d * d; }
    }
#pragma unroll
    for (int o = 16; o; o >>= 1) vs += __shfl_xor_sync(0xffffffffu, vs, o);
    float rstd = rsqrtf(vs * (1.f / CC) + 1e-5f);
    bf16* orow = n2 + (size_t)row * KP1;
#pragma unroll
    for (int i = 0; i < 6; i++) {
        int c = lane + 32 * i;
        float val = (c < CC) ? (v[i] - mean) * rstd * g[c] + b[c] : 0.f;
        orow[c] = __float2bfloat16(val);
    }
}

// ======== A-resident persistent GEMM: A[128xKP] in smem, loop n-tiles ========
// EPI: 0=none 1=+bias 2=gelu ; OBF: 1 -> bf16 output (stride OS), 0 -> fp32 output
template <int EPI, int OBF>
__global__ void __launch_bounds__(256) mma_gemm_p(const bf16* __restrict__ A,
                                                  const bf16* __restrict__ Wt,
                                                  const float* __restrict__ bias,
                                                  float* __restrict__ Cf,
                                                  bf16* __restrict__ Cb,
                                                  int N, int KP, int OS, int NT) {
    extern __shared__ bf16 sm[];
    const int AST = KP + 8;               // row stride (bf16)
    bf16* As = sm;                        // [128][AST]
    bf16* Bs = sm + 128 * AST;            // [2][64][AST]
    const int tid  = threadIdx.x;
    const int row0 = blockIdx.x * 128;
    const int wid  = tid >> 5;
    const int lane = tid & 31;
    const int warpm = wid >> 1;
    const int warpn = wid & 1;
    const int gr = lane >> 2;
    const int cq = lane & 3;
    const int NS = KP >> 4;               // k16 steps
    const int KC = KP >> 3;               // 16B chunks per row

    // ldmatrix lane address components
    const int li = lane >> 3, lj = lane & 7;
    const int arow = (li & 1) * 8 + lj;   // 0..15
    const int acol = (li >> 1) * 8;       // 0 or 8
    const int brow = lj;
    const int bcol = (li & 1) * 8;

    uint32_t sA = (uint32_t)__cvta_generic_to_shared(As);
    uint32_t sB = (uint32_t)__cvta_generic_to_shared(Bs);

    for (int cid = tid; cid < 128 * KC; cid += 256) {
        int m = cid / KC, kc = (cid - m * KC) << 3;
        const bf16* g = A + (size_t)(row0 + m) * KP + kc;
        uint32_t sa = sA + (uint32_t)(m * AST + kc) * 2;
        asm volatile("cp.async.cg.shared.global [%0], [%1], 16;\n" :: "r"(sa), "l"(g));
    }
    auto issueB = [&](int t) {
        uint32_t bbase = sB + (t & 1) * (64 * AST * 2);
        const bf16* wt0 = Wt + (size_t)(t * 64) * KP;
        for (int cid = tid; cid < 64 * KC; cid += 256) {
            int n = cid / KC, kc = (cid - n * KC) << 3;
            uint32_t sb = bbase + (uint32_t)(n * AST + kc) * 2;
            asm volatile("cp.async.cg.shared.global [%0], [%1], 16;\n"
                         :: "r"(sb), "l"(wt0 + (size_t)n * KP + kc));
        }
        asm volatile("cp.async.commit_group;\n");
    };

    issueB(0);

    // A fragment LDSM base addresses (fixed across tiles)
    uint32_t aAddr[2];
#pragma unroll
    for (int mt = 0; mt < 2; mt++)
        aAddr[mt] = sA + (uint32_t)((warpm * 32 + mt * 16 + arow) * AST + acol) * 2;

    for (int t = 0; t < NT; t++) {
        if (t + 1 < NT) { issueB(t + 1); asm volatile("cp.async.wait_group 1;\n"); }
        else            { asm volatile("cp.async.wait_group 0;\n"); }
        __syncthreads();

        float acc[2][4][4];
#pragma unroll
        for (int a = 0; a < 2; a++)
#pragma unroll
            for (int b = 0; b < 4; b++)
#pragma unroll
                for (int c = 0; c < 4; c++) acc[a][b][c] = 0.f;

        uint32_t bb32 = sB + (uint32_t)((t & 1) * (64 * AST * 2));
        uint32_t bAddr[4];
#pragma unroll
        for (int nt = 0; nt < 4; nt++)
            bAddr[nt] = bb32 + (uint32_t)((warpn * 32 + nt * 8 + brow) * AST + bcol) * 2;

        for (int ks = 0; ks < NS; ks++) {
            uint32_t afr[2][4], bfr[4][2];
#pragma unroll
            for (int mt = 0; mt < 2; mt++) LDSM4(afr[mt], aAddr[mt] + ks * 32);
#pragma unroll
            for (int nt = 0; nt < 4; nt++) LDSM2(bfr[nt], bAddr[nt] + ks * 32);
#pragma unroll
            for (int mt = 0; mt < 2; mt++)
#pragma unroll
                for (int nt = 0; nt < 4; nt++)
                    MMA16816(acc[mt][nt], afr[mt][0], afr[mt][1], afr[mt][2], afr[mt][3],
                             bfr[nt][0], bfr[nt][1]);
        }

        const int col0 = t * 64;
#pragma unroll
        for (int mt = 0; mt < 2; mt++) {
            int r0 = row0 + warpm * 32 + mt * 16 + gr;
#pragma unroll
            for (int nt = 0; nt < 4; nt++) {
                int cb = col0 + warpn * 32 + nt * 8 + cq * 2;
                if (cb < N) {
                    float v00 = acc[mt][nt][0], v01 = acc[mt][nt][1];
                    float v10 = acc[mt][nt][2], v11 = acc[mt][nt][3];
                    if (EPI == 1) { float b0 = bias[cb], b1 = bias[cb + 1];
                                    v00 += b0; v01 += b1; v10 += b0; v11 += b1; }
                    if (EPI == 2) { v00 = gelu_exact(v00); v01 = gelu_exact(v01);
                                    v10 = gelu_exact(v10); v11 = gelu_exact(v11); }
                    if (OBF) {
                        __nv_bfloat162 p0, p1;
                        p0.x = __float2bfloat16(v00); p0.y = __float2bfloat16(v01);
                        p1.x = __float2bfloat16(v10); p1.y = __float2bfloat16(v11);
                        *(__nv_bfloat162*)&Cb[(size_t)r0 * OS + cb]       = p0;
                        *(__nv_bfloat162*)&Cb[(size_t)(r0 + 8) * OS + cb] = p1;
                    } else {
                        *(float2*)&Cf[(size_t)r0 * OS + cb]       = make_float2(v00, v01);
                        *(float2*)&Cf[(size_t)(r0 + 8) * OS + cb] = make_float2(v10, v11);
                    }
                }
            }
        }
        __syncthreads();
    }
}

// ======== pipelined GEMM (KP=384 ffn2): C = A @ W^T + residual ========
__global__ void __launch_bounds__(256) mma_gemm_res(const bf16* __restrict__ A,
                                                    const bf16* __restrict__ Wt,
                                                    const float* __restrict__ res,
                                                    float* __restrict__ Cout,
                                                    int N, int KP) {
    extern __shared__ bf16 sm[];
    bf16* As = sm;                       // [2][128][40]
    bf16* Bs = sm + 2 * 128 * 40;        // [2][64][40]
    const int tid  = threadIdx.x;
    const int row0 = blockIdx.x * 128;
    const int col0 = blockIdx.y * 64;
    const int NS   = KP >> 5;
    const int wid  = tid >> 5;
    const int lane = tid & 31;
    const int warpm = wid >> 1;
    const int warpn = wid & 1;
    const int gr = lane >> 2;
    const int cq = lane & 3;

    const int li = lane >> 3, lj = lane & 7;
    const int arow = (li & 1) * 8 + lj;
    const int acol = (li >> 1) * 8;
    const int brow = lj;
    const int bcol = (li & 1) * 8;

    uint32_t sA = (uint32_t)__cvta_generic_to_shared(As);
    uint32_t sB = (uint32_t)__cvta_generic_to_shared(Bs);

    auto issue = [&](int s) {
        const int k0  = s << 5;
        const int buf = s & 1;
        uint32_t abase = sA + buf * (128 * 40 * 2);
        uint32_t bbase = sB + buf * (64 * 40 * 2);
#pragma unroll
        for (int i = 0; i < 2; i++) {
            int cid = tid + 256 * i;
            int m = cid >> 2, kc = (cid & 3) << 3;
            const bf16* g = A + (size_t)(row0 + m) * KP + k0 + kc;
            uint32_t sa = abase + (uint32_t)(m * 40 + kc) * 2;
            asm volatile("cp.async.cg.shared.global [%0], [%1], 16;\n" :: "r"(sa), "l"(g));
        }
        {
            int n = tid >> 2, kc = (tid & 3) << 3;
            const bf16* g = Wt + (size_t)(col0 + n) * KP + k0 + kc;
            uint32_t sb = bbase + (uint32_t)(n * 40 + kc) * 2;
            asm volatile("cp.async.cg.shared.global [%0], [%1], 16;\n" :: "r"(sb), "l"(g));
        }
        asm volatile("cp.async.commit_group;\n");
    };

    float acc[2][4][4];
#pragma unroll
    for (int a = 0; a < 2; a++)
#pragma unroll
        for (int b = 0; b < 4; b++)
#pragma unroll
            for (int c = 0; c < 4; c++) acc[a][b][c] = 0.f;

    uint32_t aW[2], bW[4];
#pragma unroll
    for (int mt = 0; mt < 2; mt++)
        aW[mt] = (uint32_t)((warpm * 32 + mt * 16 + arow) * 40 + acol) * 2;
#pragma unroll
    for (int nt = 0; nt < 4; nt++)
        bW[nt] = (uint32_t)((warpn * 32 + nt * 8 + brow) * 40 + bcol) * 2;

    issue(0);
    for (int s = 0; s < NS; s++) {
        if (s + 1 < NS) { issue(s + 1); asm volatile("cp.async.wait_group 1;\n"); }
        else            { asm volatile("cp.async.wait_group 0;\n"); }
        __syncthreads();
        uint32_t abuf = sA + (s & 1) * (128 * 40 * 2);
        uint32_t bbuf = sB + (s & 1) * (64 * 40 * 2);
#pragma unroll
        for (int kk = 0; kk < 2; kk++) {
            uint32_t afr[2][4], bfr[4][2];
#pragma unroll
            for (int mt = 0; mt < 2; mt++) LDSM4(afr[mt], abuf + aW[mt] + kk * 32);
#pragma unroll
            for (int nt = 0; nt < 4; nt++) LDSM2(bfr[nt], bbuf + bW[nt] + kk * 32);
#pragma unroll
            for (int mt = 0; mt < 2; mt++)
#pragma unroll
                for (int nt = 0; nt < 4; nt++)
                    MMA16816(acc[mt][nt], afr[mt][0], afr[mt][1], afr[mt][2], afr[mt][3],
                             bfr[nt][0], bfr[nt][1]);
        }
        __syncthreads();
    }

#pragma unroll
    for (int mt = 0; mt < 2; mt++) {
        int r0 = row0 + warpm * 32 + mt * 16 + gr;
#pragma unroll
        for (int nt = 0; nt < 4; nt++) {
            int cb = col0 + warpn * 32 + nt * 8 + cq * 2;
            if (cb < N) {
                const float2 r0v = *(const float2*)&res[(size_t)r0 * N + cb];
                const float2 r1v = *(const float2*)&res[(size_t)(r0 + 8) * N + cb];
                *(float2*)&Cout[(size_t)r0 * N + cb] =
                    make_float2(acc[mt][nt][0] + r0v.x, acc[mt][nt][1] + r0v.y);
                *(float2*)&Cout[(size_t)(r0 + 8) * N + cb] =
                    make_float2(acc[mt][nt][2] + r1v.x, acc[mt][nt][3] + r1v.y);
            }
        }
    }
}

// ======== MMA window attention: 1 block/window, 12 warps = 2 per head ========
__global__ void __launch_bounds__(384) attn_mma(const bf16* __restrict__ qkv,
                                                const float* __restrict__ b_rel,
                                                bf16* __restrict__ out) {
    extern __shared__ bf16 smA[];
    bf16* Qs = smA;                    // [6*64][40]
    bf16* Ks = Qs + 6 * 64 * 40;       // [6*64][40]
    bf16* Vs = Ks + 6 * 64 * 40;       // [6*32][72]
    const int w = blockIdx.x;
    const int b  = w >> 10;
    const int wy = (w & 1023) >> 5;
    const int wx = w & 31;
    const int tid = threadIdx.x;       // 384
    const float scale = 0.18257418583505536f;  // 30^-0.5

    for (int idx = tid; idx < 6 * 64 * 16; idx += 384) {
        int h   = idx >> 10;
        int rem = idx & 1023;
        int t   = rem >> 4;
        int dp  = rem & 15;
        int ty = t >> 3, tx = t & 7;
        size_t row = ((size_t)b << 16) + (size_t)(wy * 8 + ty) * 256 + (wx * 8 + tx);
        const bf16* base = qkv + row * 540 + h * HDIM + 2 * dp;
        uint32_t qv = 0, kw = 0;
        __nv_bfloat162 vp; vp.x = __float2bfloat16(0.f); vp.y = vp.x;
        if (dp < 15) {
            __nv_bfloat162 q2 = *(const __nv_bfloat162*)base;
            qv = pk_bf2(__bfloat162float(q2.x) * scale, __bfloat162float(q2.y) * scale);
            kw = *(const uint32_t*)(base + 180);
            vp = *(const __nv_bfloat162*)(base + 360);
        }
        *(uint32_t*)&Qs[(h * 64 + t) * 40 + 2 * dp] = qv;
        *(uint32_t*)&Ks[(h * 64 + t) * 40 + 2 * dp] = kw;
        Vs[(h * 32 + 2 * dp)     * 72 + t] = vp.x;
        Vs[(h * 32 + 2 * dp + 1) * 72 + t] = vp.y;
    }
    for (int idx = tid; idx < 64 * 12; idx += 384) {
        int t = idx / 12, c = idx - t * 12;
        int ty = t >> 3, tx = t & 7;
        size_t row = ((size_t)b << 16) + (size_t)(wy * 8 + ty) * 256 + (wx * 8 + tx);
        out[row * KP1 + 180 + c] = __float2bfloat16(0.f);
    }
    __syncthreads();

    const int wid  = tid >> 5;
    const int lane = tid & 31;
    const int h     = wid >> 1;
    const int mbase = (wid & 1) * 32;
    const int gr = lane >> 2;
    const int cq = lane & 3;

    const int li = lane >> 3, lj = lane & 7;
    const int arow = (li & 1) * 8 + lj;
    const int acol = (li >> 1) * 8;
    const int brow = lj;
    const int bcol = (li & 1) * 8;

    uint32_t sQ = (uint32_t)__cvta_generic_to_shared(Qs);
    uint32_t sK = (uint32_t)__cvta_generic_to_shared(Ks);
    uint32_t sV = (uint32_t)__cvta_generic_to_shared(Vs);

    // Q fragments
    uint32_t qf[2][2][4];
#pragma unroll
    for (int mt = 0; mt < 2; mt++)
#pragma unroll
        for (int kk = 0; kk < 2; kk++) {
            uint32_t ad = sQ + (uint32_t)((h * 64 + mbase + mt * 16 + arow) * 40 + kk * 16 + acol) * 2;
            LDSM4(qf[mt][kk], ad);
        }

    // S = Q K^T
    float sacc[2][8][4];
#pragma unroll
    for (int mt = 0; mt < 2; mt++)
#pragma unroll
        for (int nt = 0; nt < 8; nt++)
#pragma unroll
            for (int c = 0; c < 4; c++) sacc[mt][nt][c] = 0.f;

#pragma unroll
    for (int nt = 0; nt < 8; nt++) {
        uint32_t kf[2][2];
#pragma unroll
        for (int kk = 0; kk < 2; kk++) {
            uint32_t ad = sK + (uint32_t)((h * 64 + nt * 8 + brow) * 40 + kk * 16 + bcol) * 2;
            LDSM2(kf[kk], ad);
        }
#pragma unroll
        for (int mt = 0; mt < 2; mt++)
#pragma unroll
            for (int kk = 0; kk < 2; kk++)
                MMA16816(sacc[mt][nt], qf[mt][kk][0], qf[mt][kk][1], qf[mt][kk][2], qf[mt][kk][3],
                         kf[kk][0], kf[kk][1]);
    }

    // + b_rel, exp, row sums
    const float* brh = b_rel + h * 4096;
    float l0[2] = {0.f, 0.f}, l1[2] = {0.f, 0.f};
#pragma unroll
    for (int mt = 0; mt < 2; mt++) {
        int r = mbase + mt * 16 + gr;
#pragma unroll
        for (int nt = 0; nt < 8; nt++) {
            int cb = nt * 8 + cq * 2;
            float2 br0 = *(const float2*)&brh[r * 64 + cb];
            float2 br1 = *(const float2*)&brh[(r + 8) * 64 + cb];
            float e0 = __expf(sacc[mt][nt][0] + br0.x);
            float e1 = __expf(sacc[mt][nt][1] + br0.y);
            float e2 = __expf(sacc[mt][nt][2] + br1.x);
            float e3 = __expf(sacc[mt][nt][3] + br1.y);
            sacc[mt][nt][0] = e0; sacc[mt][nt][1] = e1;
            sacc[mt][nt][2] = e2; sacc[mt][nt][3] = e3;
            l0[mt] += e0 + e1;
            l1[mt] += e2 + e3;
        }
    }
#pragma unroll
    for (int o = 1; o <= 2; o <<= 1) {
#pragma unroll
        for (int mt = 0; mt < 2; mt++) {
            l0[mt] += __shfl_xor_sync(0xffffffffu, l0[mt], o);
            l1[mt] += __shfl_xor_sync(0xffffffffu, l1[mt], o);
        }
    }
    float inv0[2], inv1[2];
#pragma unroll
    for (int mt = 0; mt < 2; mt++) { inv0[mt] = 1.f / l0[mt]; inv1[mt] = 1.f / l1[mt]; }

    // pack P
    uint32_t pb[2][4][4];
#pragma unroll
    for (int mt = 0; mt < 2; mt++)
#pragma unroll
        for (int kc = 0; kc < 4; kc++) {
            int n0 = 2 * kc, n1 = 2 * kc + 1;
            pb[mt][kc][0] = pk_bf2(sacc[mt][n0][0] * inv0[mt], sacc[mt][n0][1] * inv0[mt]);
            pb[mt][kc][1] = pk_bf2(sacc[mt][n0][2] * inv1[mt], sacc[mt][n0][3] * inv1[mt]);
            pb[mt][kc][2] = pk_bf2(sacc[mt][n1][0] * inv0[mt], sacc[mt][n1][1] * inv0[mt]);
            pb[mt][kc][3] = pk_bf2(sacc[mt][n1][2] * inv1[mt], sacc[mt][n1][3] * inv1[mt]);
        }

    // O = P V
    float oacc[2][4][4];
#pragma unroll
    for (int mt = 0; mt < 2; mt++)
#pragma unroll
        for (int nt = 0; nt < 4; nt++)
#pragma unroll
            for (int c = 0; c < 4; c++) oacc[mt][nt][c] = 0.f;

#pragma unroll
    for (int nt = 0; nt < 4; nt++) {
        uint32_t vf[4][2];
#pragma unroll
        for (int kc = 0; kc < 4; kc++) {
            uint32_t ad = sV + (uint32_t)((h * 32 + nt * 8 + brow) * 72 + kc * 16 + bcol) * 2;
            LDSM2(vf[kc], ad);
        }
#pragma unroll
        for (int mt = 0; mt < 2; mt++)
#pragma unroll
            for (int kc = 0; kc < 4; kc++)
                MMA16816(oacc[mt][nt], pb[mt][kc][0], pb[mt][kc][1], pb[mt][kc][2], pb[mt][kc][3],
                         vf[kc][0], vf[kc][1]);
    }

    // write output
#pragma unroll
    for (int mt = 0; mt < 2; mt++) {
        int r = mbase + mt * 16 + gr;
        size_t rg0 = ((size_t)b << 16) + (size_t)(wy * 8 + (r >> 3)) * 256 + (wx * 8 + (r & 7));
        int r8 = r + 8;
        size_t rg1 = ((size_t)b << 16) + (size_t)(wy * 8 + (r8 >> 3)) * 256 + (wx * 8 + (r8 & 7));
#pragma unroll
        for (int nt = 0; nt < 4; nt++) {
            int cb = nt * 8 + cq * 2;
            if (cb < HDIM) {
                __nv_bfloat162 p0, p1;
                p0.x = __float2bfloat16(oacc[mt][nt][0]); p0.y = __float2bfloat16(oacc[mt][nt][1]);
                p1.x = __float2bfloat16(oacc[mt][nt][2]); p1.y = __float2bfloat16(oacc[mt][nt][3]);
                *(__nv_bfloat162*)&out[rg0 * KP1 + h * HDIM + cb] = p0;
                *(__nv_bfloat162*)&out[rg1 * KP1 + h * HDIM + cb] = p1;
            }
        }
    }
}

// ---------------- depthwise 3x3 SAME conv, x-tiled (TX) + rolling-y ----------------
template <typename Tin, typename Tout, int CD, int INS, int OUTS, int GELU, int POOL, int TX>
__global__ void dwconv_tile(const Tin* __restrict__ in,
                            const float* __restrict__ k9,
                            Tout* __restrict__ out,
                            float* __restrict__ pooled) {
    const int c  = threadIdx.x;
    const int x0 = blockIdx.x * TX;
    const int y0 = blockIdx.y * 64;
    const int b  = blockIdx.z;
    float w[9];
#pragma unroll
    for (int i = 0; i < 9; i++) w[i] = k9[c * 9 + i];

    const size_t base = ((size_t)b << 16);
    float r[TX + 2], s[TX + 2], t[TX + 2];

    auto loadrow = [&](int yy, float* dst) {
#pragma unroll
        for (int i = 0; i < TX + 2; i++) {
            int xx = x0 - 1 + i;
            dst[i] = (xx >= 0 && xx < WWID)
                     ? (float)in[(base + (size_t)yy * 256 + xx) * INS + c] : 0.f;
        }
    };

    if (y0 > 0) loadrow(y0 - 1, r);
    else {
#pragma unroll
        for (int i = 0; i < TX + 2; i++) r[i] = 0.f;
    }
    loadrow(y0, s);

    float psum = 0.f;
    for (int yy = y0; yy < y0 + 64; yy++) {
        if (yy + 1 < HH) loadrow(yy + 1, t);
        else {
#pragma unroll
            for (int i = 0; i < TX + 2; i++) t[i] = 0.f;
        }
#pragma unroll
        for (int j = 0; j < TX; j++) {
            float acc = r[j] * w[0] + r[j + 1] * w[1] + r[j + 2] * w[2]
                      + s[j] * w[3] + s[j + 1] * w[4] + s[j + 2] * w[5]
                      + t[j] * w[6] + t[j + 1] * w[7] + t[j + 2] * w[8];
            if (GELU) acc = gelu_exact(acc);
            if (POOL) psum += acc;
            size_t op = (base + (size_t)yy * 256 + x0 + j) * OUTS;
            out[op + c] = (Tout)acc;
            if (OUTS > CD && c < OUTS - CD) out[op + CD + c] = (Tout)0.f;
        }
#pragma unroll
        for (int i = 0; i < TX + 2; i++) { r[i] = s[i]; s[i] = t[i]; }
    }
    if (POOL) atomicAdd(&pooled[b * CD + c], psum * (1.f / (float)LL));
}

// ---------------- channel gate ----------------
__global__ void gate_kernel(const float* __restrict__ pooled,
                            const float* __restrict__ w1,
                            const float* __restrict__ w2,
                            float* __restrict__ cm) {
    const int b = blockIdx.x;
    const int tid = threadIdx.x;   // 180
    __shared__ float t1[C8];
    if (tid < C8) {
        float s = 0.f;
        for (int c = 0; c < CC; c++) s += pooled[b * CC + c] * w1[tid * CC + c];
        t1[tid] = gelu_exact(s);
    }
    __syncthreads();
    float s = 0.f;
#pragma unroll
    for (int j = 0; j < C8; j++) s += t1[j] * w2[tid * C8 + j];
    cm[b * CC + tid] = 1.f / (1.f + expf(-s));
}

// ---------------- launch ----------------
extern "C" void kernel_launch(void* const* d_in, const int* in_sizes, int n_in,
                              void* d_out, int out_size) {
    const float* x       = (const float*)d_in[0];
    const float* w_qkv   = (const float*)d_in[1];
    const float* b_rel   = (const float*)d_in[2];
    const float* w_proj  = (const float*)d_in[3];
    const float* b_proj  = (const float*)d_in[4];
    const float* conv_dw = (const float*)d_in[5];
    const float* cg_w1   = (const float*)d_in[6];
    const float* cg_w2   = (const float*)d_in[7];
    const float* ffn_w1  = (const float*)d_in[8];
    const float* ffn_dw  = (const float*)d_in[9];
    const float* ffn_w2  = (const float*)d_in[10];
    const float* n1_g    = (const float*)d_in[11];
    const float* n1_b    = (const float*)d_in[12];
    const float* n2_g    = (const float*)d_in[13];
    const float* n2_b    = (const float*)d_in[14];
    float* out = (float*)d_out;

    float *attnf, *conv, *xmid, *pooled, *cm;
    bf16 *qkvb, *n1b, *n2b, *hsb, *wb;
    cudaGetSymbolAddress((void**)&qkvb,  g_qkvb);
    cudaGetSymbolAddress((void**)&attnf, g_attnf);
    cudaGetSymbolAddress((void**)&conv,  g_conv);
    cudaGetSymbolAddress((void**)&xmid,  g_xmid);
    cudaGetSymbolAddress((void**)&pooled, g_pooled);
    cudaGetSymbolAddress((void**)&cm,     g_cm);
    cudaGetSymbolAddress((void**)&n1b,   g_n1b);
    cudaGetSymbolAddress((void**)&n2b,   g_n2b);
    cudaGetSymbolAddress((void**)&hsb,   g_hsb);
    cudaGetSymbolAddress((void**)&wb,    g_wb);

    const int PSMEM1    = (128 * (KP1 + 8) + 2 * 64 * (KP1 + 8)) * (int)sizeof(bf16); // 102400
    const int PIPE_SMEM = (2 * 128 * 40 + 2 * 64 * 40) * (int)sizeof(bf16);           // 30720
    const int ATTN_SMEM = (2 * 6 * 64 * 40 + 6 * 32 * 72) * (int)sizeof(bf16);        // 89088
    cudaFuncSetAttribute((const void*)mma_gemm_p<0,1>, cudaFuncAttributeMaxDynamicSharedMemorySize, PSMEM1);
    cudaFuncSetAttribute((const void*)mma_gemm_p<1,0>, cudaFuncAttributeMaxDynamicSharedMemorySize, PSMEM1);
    cudaFuncSetAttribute((const void*)mma_gemm_p<2,1>, cudaFuncAttributeMaxDynamicSharedMemorySize, PSMEM1);
    cudaFuncSetAttribute((const void*)mma_gemm_res,    cudaFuncAttributeMaxDynamicSharedMemorySize, PIPE_SMEM);
    cudaFuncSetAttribute((const void*)attn_mma,        cudaFuncAttributeMaxDynamicSharedMemorySize, ATTN_SMEM);

    // 0) convert + pad weights to bf16
    convw_kernel<<<(576 * 192 + 255) / 256, 256>>>(w_qkv,  wb + WB_QKV,  540, 180, 576, 192);
    convw_kernel<<<(192 * 192 + 255) / 256, 256>>>(w_proj, wb + WB_PROJ, 180, 180, 192, 192);
    convw_kernel<<<(384 * 192 + 255) / 256, 256>>>(ffn_w1, wb + WB_FFN1, 360, 180, 384, 192);
    convw_kernel<<<(192 * 384 + 255) / 256, 256>>>(ffn_w2, wb + WB_FFN2, 180, 360, 192, 384);

    // 1) ln1: x -> n1b (bf16, padded)
    ln_kernel<<<MROWS / 4, 128>>>(x, n1_g, n1_b, n1b);

    // 2) qkv = n1 @ w_qkv^T  (bf16 out, N=540, stride 540, 9 n-tiles)
    mma_gemm_p<0,1><<<MROWS / 128, 256, PSMEM1>>>(n1b, wb + WB_QKV, nullptr, nullptr, qkvb, 540, KP1, 540, 9);

    // 3) MMA window attention -> n2b (bf16, padded)
    attn_mma<<<NWIN, 384, ATTN_SMEM>>>(qkvb, b_rel, n2b);

    // 4) proj: attnf = attn @ w_proj^T + b_proj  (fp32 out)
    mma_gemm_p<1,0><<<MROWS / 128, 256, PSMEM1>>>(n2b, wb + WB_PROJ, b_proj, attnf, nullptr, 180, KP1, 180, 3);

    // 5) conv branch: dwconv(n1b)+GELU -> conv (fp32), fused mean-pool
    cudaMemsetAsync(pooled, 0, BB * CC * sizeof(float));
    dwconv_tile<bf16, float, CC, KP1, CC, 1, 1, 4><<<dim3(WWID / 4, 4, BB), CC>>>(n1b, conv_dw, conv, pooled);

    // 6) channel gate -> cm
    gate_kernel<<<BB, CC>>>(pooled, cg_w1, cg_w2, cm);

    // 7) fused residual + ln2: xmid (fp32), n2 -> n2b (bf16)
    resid_ln_kernel<<<MROWS / 4, 128>>>(x, attnf, conv, cm, n2_g, n2_b, xmid, n2b);

    // 8) ffn1: h = gelu(n2 @ ffn_w1^T) -> qkvb buffer (bf16, stride 384, N=360)
    mma_gemm_p<2,1><<<MROWS / 128, 256, PSMEM1>>>(n2b, wb + WB_FFN1, nullptr, nullptr, qkvb, 360, KP1, 384, 6);

    // 9) ffn dwconv: hsb = dwconv(h) (bf16 in stride 384, bf16 out padded 384)
    dwconv_tile<bf16, bf16, CFFN, KP2, KP2, 0, 0, 4><<<dim3(WWID / 4, 4, BB), CFFN>>>(qkvb, ffn_dw, hsb, nullptr);

    // 10) ffn2 + residual: out = xmid + hsb @ ffn_w2^T  (pipelined, KP=384)
    mma_gemm_res<<<dim3(MROWS / 128, 3), 256, PIPE_SMEM>>>(hsb, wb + WB_FFN2, xmid, out, 180, KP2);
}

// round 17
// speedup vs baseline: 1.7911x; 1.0596x over previous
#include <cuda_runtime.h>
#include <cuda_bf16.h>
#include <math.h>
#include <cstdint>

using bf16 = __nv_bfloat16;

// ---------------- problem constants ----------------
#define BB 2
#define HH 256
#define WWID 256
#define LL 65536          // H*W
#define CC 180
#define NHD 6
#define HDIM 30
#define NWIN 2048         // B * (H/8) * (W/8)
#define CFFN 360
#define C8 22             // 180 // 8
#define MROWS (BB*LL)     // 131072
#define KP1 192           // padded K for K=180
#define KP2 384           // padded K for K=360

// ---------------- scratch (device globals, no allocation) ----------------
__device__ bf16  g_qkvb [(size_t)MROWS*540];   // qkv bf16; reused for h (stride 384)
__device__ bf16  g_attnf[(size_t)MROWS*CC];    // proj output (bf16)
__device__ bf16  g_conv [(size_t)MROWS*CC];    // conv branch (bf16)
__device__ float g_xmid [(size_t)MROWS*CC];
__device__ float g_pooled[BB*CC];
__device__ float g_cm    [BB*CC];
__device__ bf16  g_n1b[(size_t)MROWS*KP1];     // ln1 out (bf16, padded)
__device__ bf16  g_n2b[(size_t)MROWS*KP1];     // attn out, then n2 (bf16, padded)
__device__ bf16  g_hsb[(size_t)MROWS*KP2];     // ffn dwconv out (bf16, padded)
__device__ bf16  g_wb [294912];                // padded bf16 weights

#define WB_QKV  0        // 576 x 192
#define WB_PROJ 110592   // 192 x 192
#define WB_FFN1 147456   // 384 x 192
#define WB_FFN2 221184   // 192 x 384

__device__ __forceinline__ float gelu_exact(float x) {
    return 0.5f * x * (1.0f + erff(x * 0.70710678118654752f));
}

__device__ __forceinline__ uint32_t pk_bf2(float a, float b) {
    __nv_bfloat162 t = __floats2bfloat162_rn(a, b);
    return *(uint32_t*)&t;
}

#define MMA16816(ACC, A0, A1, A2, A3, B0, B1)                                   \
    asm volatile(                                                               \
        "mma.sync.aligned.m16n8k16.row.col.f32.bf16.bf16.f32 "                  \
        "{%0,%1,%2,%3},{%4,%5,%6,%7},{%8,%9},{%0,%1,%2,%3};\n"                  \
        : "+f"((ACC)[0]), "+f"((ACC)[1]), "+f"((ACC)[2]), "+f"((ACC)[3])        \
        : "r"(A0), "r"(A1), "r"(A2), "r"(A3), "r"(B0), "r"(B1))

#define LDSM4(R, ADDR)                                                          \
    asm volatile("ldmatrix.sync.aligned.m8n8.x4.shared.b16 {%0,%1,%2,%3}, [%4];"\
        : "=r"((R)[0]), "=r"((R)[1]), "=r"((R)[2]), "=r"((R)[3]) : "r"(ADDR))
#define LDSM2(R, ADDR)                                                          \
    asm volatile("ldmatrix.sync.aligned.m8n8.x2.shared.b16 {%0,%1}, [%2];"      \
        : "=r"((R)[0]), "=r"((R)[1]) : "r"(ADDR))

// ---------------- weight convert + pad: src[N][K] fp32 -> dst[NP][KP] bf16 ----------------
__global__ void convw_kernel(const float* __restrict__ src, bf16* __restrict__ dst,
                             int N, int K, int NP, int KP) {
    int i = blockIdx.x * 256 + threadIdx.x;
    if (i < NP * KP) {
        int n = i / KP, k = i - n * KP;
        float v = (n < N && k < K) ? src[n * K + k] : 0.f;
        dst[i] = __float2bfloat16(v);
    }
}

// ---------------- LayerNorm (emits bf16, KP1-padded) ----------------
__global__ void ln_kernel(const float* __restrict__ x,
                          const float* __restrict__ g,
                          const float* __restrict__ b,
                          bf16* __restrict__ out) {
    int row = blockIdx.x * 4 + (threadIdx.x >> 5);
    int lane = threadIdx.x & 31;
    const float* xr = x + (size_t)row * CC;
    float v[6];
    float s = 0.f;
#pragma unroll
    for (int i = 0; i < 6; i++) {
        int c = lane + 32 * i;
        v[i] = (c < CC) ? xr[c] : 0.f;
        s += v[i];
    }
#pragma unroll
    for (int o = 16; o; o >>= 1) s += __shfl_xor_sync(0xffffffffu, s, o);
    float mean = s * (1.f / CC);
    float vs = 0.f;
#pragma unroll
    for (int i = 0; i < 6; i++) {
        int c = lane + 32 * i;
        if (c < CC) { float d = v[i] - mean; vs += d * d; }
    }
#pragma unroll
    for (int o = 16; o; o >>= 1) vs += __shfl_xor_sync(0xffffffffu, vs, o);
    float rstd = rsqrtf(vs * (1.f / CC) + 1e-5f);
    bf16* orow = out + (size_t)row * KP1;
#pragma unroll
    for (int i = 0; i < 6; i++) {
        int c = lane + 32 * i;
        float val = (c < CC) ? (v[i] - mean) * rstd * g[c] + b[c] : 0.f;
        orow[c] = __float2bfloat16(val);
    }
}

// ---------------- fused: xmid = x + attnf*cm + conv; n2 = bf16(LN(xmid)) ----------------
__global__ void resid_ln_kernel(const float* __restrict__ x,
                                const bf16* __restrict__ attnf,
                                const bf16* __restrict__ conv,
                                const float* __restrict__ cm,
                                const float* __restrict__ g,
                                const float* __restrict__ b,
                                float* __restrict__ xmid,
                                bf16* __restrict__ n2) {
    int row = blockIdx.x * 4 + (threadIdx.x >> 5);
    int lane = threadIdx.x & 31;
    int bb = row >> 16;
    size_t base = (size_t)row * CC;
    float v[6];
    float s = 0.f;
#pragma unroll
    for (int i = 0; i < 6; i++) {
        int c = lane + 32 * i;
        if (c < CC) {
            float xv = x[base + c]
                     + __bfloat162float(attnf[base + c]) * cm[bb * CC + c]
                     + __bfloat162float(conv[base + c]);
            xmid[base + c] = xv;
            v[i] = xv;
        } else v[i] = 0.f;
        s += v[i];
    }
#pragma unroll
    for (int o = 16; o; o >>= 1) s += __shfl_xor_sync(0xffffffffu, s, o);
    float mean = s * (1.f / CC);
    float vs = 0.f;
#pragma unroll
    for (int i = 0; i < 6; i++) {
        int c = lane + 32 * i;
        if (c < CC) { float d = v[i] - mean; vs += d * d; }
    }
#pragma unroll
    for (int o = 16; o; o >>= 1) vs += __shfl_xor_sync(0xffffffffu, vs, o);
    float rstd = rsqrtf(vs * (1.f / CC) + 1e-5f);
    bf16* orow = n2 + (size_t)row * KP1;
#pragma unroll
    for (int i = 0; i < 6; i++) {
        int c = lane + 32 * i;
        float val = (c < CC) ? (v[i] - mean) * rstd * g[c] + b[c] : 0.f;
        orow[c] = __float2bfloat16(val);
    }
}

// ======== A-resident persistent GEMM: A[128xKP] in smem, loop n-tiles ========
// EPI: 0=none 1=+bias 2=gelu ; OBF: 1 -> bf16 output (stride OS), 0 -> fp32 output
template <int EPI, int OBF>
__global__ void __launch_bounds__(256) mma_gemm_p(const bf16* __restrict__ A,
                                                  const bf16* __restrict__ Wt,
                                                  const float* __restrict__ bias,
                                                  float* __restrict__ Cf,
                                                  bf16* __restrict__ Cb,
                                                  int N, int KP, int OS, int NT) {
    extern __shared__ bf16 sm[];
    const int AST = KP + 8;               // row stride (bf16)
    bf16* As = sm;                        // [128][AST]
    bf16* Bs = sm + 128 * AST;            // [2][64][AST]
    const int tid  = threadIdx.x;
    const int row0 = blockIdx.x * 128;
    const int wid  = tid >> 5;
    const int lane = tid & 31;
    const int warpm = wid >> 1;
    const int warpn = wid & 1;
    const int gr = lane >> 2;
    const int cq = lane & 3;
    const int NS = KP >> 4;               // k16 steps
    const int KC = KP >> 3;               // 16B chunks per row

    const int li = lane >> 3, lj = lane & 7;
    const int arow = (li & 1) * 8 + lj;
    const int acol = (li >> 1) * 8;
    const int brow = lj;
    const int bcol = (li & 1) * 8;

    uint32_t sA = (uint32_t)__cvta_generic_to_shared(As);
    uint32_t sB = (uint32_t)__cvta_generic_to_shared(Bs);

    for (int cid = tid; cid < 128 * KC; cid += 256) {
        int m = cid / KC, kc = (cid - m * KC) << 3;
        const bf16* g = A + (size_t)(row0 + m) * KP + kc;
        uint32_t sa = sA + (uint32_t)(m * AST + kc) * 2;
        asm volatile("cp.async.cg.shared.global [%0], [%1], 16;\n" :: "r"(sa), "l"(g));
    }
    auto issueB = [&](int t) {
        uint32_t bbase = sB + (t & 1) * (64 * AST * 2);
        const bf16* wt0 = Wt + (size_t)(t * 64) * KP;
        for (int cid = tid; cid < 64 * KC; cid += 256) {
            int n = cid / KC, kc = (cid - n * KC) << 3;
            uint32_t sb = bbase + (uint32_t)(n * AST + kc) * 2;
            asm volatile("cp.async.cg.shared.global [%0], [%1], 16;\n"
                         :: "r"(sb), "l"(wt0 + (size_t)n * KP + kc));
        }
        asm volatile("cp.async.commit_group;\n");
    };

    issueB(0);

    uint32_t aAddr[2];
#pragma unroll
    for (int mt = 0; mt < 2; mt++)
        aAddr[mt] = sA + (uint32_t)((warpm * 32 + mt * 16 + arow) * AST + acol) * 2;

    for (int t = 0; t < NT; t++) {
        if (t + 1 < NT) { issueB(t + 1); asm volatile("cp.async.wait_group 1;\n"); }
        else            { asm volatile("cp.async.wait_group 0;\n"); }
        __syncthreads();

        float acc[2][4][4];
#pragma unroll
        for (int a = 0; a < 2; a++)
#pragma unroll
            for (int b = 0; b < 4; b++)
#pragma unroll
                for (int c = 0; c < 4; c++) acc[a][b][c] = 0.f;

        uint32_t bb32 = sB + (uint32_t)((t & 1) * (64 * AST * 2));
        uint32_t bAddr[4];
#pragma unroll
        for (int nt = 0; nt < 4; nt++)
            bAddr[nt] = bb32 + (uint32_t)((warpn * 32 + nt * 8 + brow) * AST + bcol) * 2;

        for (int ks = 0; ks < NS; ks++) {
            uint32_t afr[2][4], bfr[4][2];
#pragma unroll
            for (int mt = 0; mt < 2; mt++) LDSM4(afr[mt], aAddr[mt] + ks * 32);
#pragma unroll
            for (int nt = 0; nt < 4; nt++) LDSM2(bfr[nt], bAddr[nt] + ks * 32);
#pragma unroll
            for (int mt = 0; mt < 2; mt++)
#pragma unroll
                for (int nt = 0; nt < 4; nt++)
                    MMA16816(acc[mt][nt], afr[mt][0], afr[mt][1], afr[mt][2], afr[mt][3],
                             bfr[nt][0], bfr[nt][1]);
        }

        const int col0 = t * 64;
#pragma unroll
        for (int mt = 0; mt < 2; mt++) {
            int r0 = row0 + warpm * 32 + mt * 16 + gr;
#pragma unroll
            for (int nt = 0; nt < 4; nt++) {
                int cb = col0 + warpn * 32 + nt * 8 + cq * 2;
                if (cb < N) {
                    float v00 = acc[mt][nt][0], v01 = acc[mt][nt][1];
                    float v10 = acc[mt][nt][2], v11 = acc[mt][nt][3];
                    if (EPI == 1) { float b0 = bias[cb], b1 = bias[cb + 1];
                                    v00 += b0; v01 += b1; v10 += b0; v11 += b1; }
                    if (EPI == 2) { v00 = gelu_exact(v00); v01 = gelu_exact(v01);
                                    v10 = gelu_exact(v10); v11 = gelu_exact(v11); }
                    if (OBF) {
                        __nv_bfloat162 p0, p1;
                        p0.x = __float2bfloat16(v00); p0.y = __float2bfloat16(v01);
                        p1.x = __float2bfloat16(v10); p1.y = __float2bfloat16(v11);
                        *(__nv_bfloat162*)&Cb[(size_t)r0 * OS + cb]       = p0;
                        *(__nv_bfloat162*)&Cb[(size_t)(r0 + 8) * OS + cb] = p1;
                    } else {
                        *(float2*)&Cf[(size_t)r0 * OS + cb]       = make_float2(v00, v01);
                        *(float2*)&Cf[(size_t)(r0 + 8) * OS + cb] = make_float2(v10, v11);
                    }
                }
            }
        }
        __syncthreads();
    }
}

// ======== pipelined GEMM ffn2, FULL N=192 per block: out = res + A @ W^T ========
// grid = MROWS/128 (A read exactly once). smem 51200 B -> 4 CTAs/SM.
__global__ void __launch_bounds__(256) mma_gemm_res2(const bf16* __restrict__ A,
                                                     const bf16* __restrict__ Wt,
                                                     const float* __restrict__ res,
                                                     float* __restrict__ Cout) {
    extern __shared__ bf16 sm[];
    bf16* As = sm;                       // [2][128][40]
    bf16* Bs = sm + 2 * 128 * 40;        // [2][192][40]
    const int tid  = threadIdx.x;
    const int row0 = blockIdx.x * 128;
    const int NS   = KP2 >> 5;           // 12
    const int wid  = tid >> 5;
    const int lane = tid & 31;
    const int warpm = wid >> 1;          // 0..3 (32 rows each)
    const int warpn = wid & 1;           // 0..1 (96 cols each)
    const int gr = lane >> 2;
    const int cq = lane & 3;

    const int li = lane >> 3, lj = lane & 7;
    const int arow = (li & 1) * 8 + lj;
    const int acol = (li >> 1) * 8;
    const int brow = lj;
    const int bcol = (li & 1) * 8;

    uint32_t sA = (uint32_t)__cvta_generic_to_shared(As);
    uint32_t sB = (uint32_t)__cvta_generic_to_shared(Bs);

    auto issue = [&](int s) {
        const int k0  = s << 5;
        const int buf = s & 1;
        uint32_t abase = sA + buf * (128 * 40 * 2);
        uint32_t bbase = sB + buf * (192 * 40 * 2);
#pragma unroll
        for (int i = 0; i < 2; i++) {
            int cid = tid + 256 * i;
            int m = cid >> 2, kc = (cid & 3) << 3;
            const bf16* g = A + (size_t)(row0 + m) * KP2 + k0 + kc;
            uint32_t sa = abase + (uint32_t)(m * 40 + kc) * 2;
            asm volatile("cp.async.cg.shared.global [%0], [%1], 16;\n" :: "r"(sa), "l"(g));
        }
#pragma unroll
        for (int i = 0; i < 3; i++) {
            int cid = tid + 256 * i;
            int n = cid >> 2, kc = (cid & 3) << 3;
            const bf16* g = Wt + (size_t)n * KP2 + k0 + kc;
            uint32_t sb = bbase + (uint32_t)(n * 40 + kc) * 2;
            asm volatile("cp.async.cg.shared.global [%0], [%1], 16;\n" :: "r"(sb), "l"(g));
        }
        asm volatile("cp.async.commit_group;\n");
    };

    float acc[2][12][4];
#pragma unroll
    for (int a = 0; a < 2; a++)
#pragma unroll
        for (int b = 0; b < 12; b++)
#pragma unroll
            for (int c = 0; c < 4; c++) acc[a][b][c] = 0.f;

    uint32_t aW[2], bW[12];
#pragma unroll
    for (int mt = 0; mt < 2; mt++)
        aW[mt] = (uint32_t)((warpm * 32 + mt * 16 + arow) * 40 + acol) * 2;
#pragma unroll
    for (int nt = 0; nt < 12; nt++)
        bW[nt] = (uint32_t)((warpn * 96 + nt * 8 + brow) * 40 + bcol) * 2;

    issue(0);
    for (int s = 0; s < NS; s++) {
        if (s + 1 < NS) { issue(s + 1); asm volatile("cp.async.wait_group 1;\n"); }
        else            { asm volatile("cp.async.wait_group 0;\n"); }
        __syncthreads();
        uint32_t abuf = sA + (s & 1) * (128 * 40 * 2);
        uint32_t bbuf = sB + (s & 1) * (192 * 40 * 2);
#pragma unroll
        for (int kk = 0; kk < 2; kk++) {
            uint32_t afr[2][4];
#pragma unroll
            for (int mt = 0; mt < 2; mt++) LDSM4(afr[mt], abuf + aW[mt] + kk * 32);
#pragma unroll
            for (int nt = 0; nt < 12; nt++) {
                uint32_t bfr[2];
                LDSM2(bfr, bbuf + bW[nt] + kk * 32);
#pragma unroll
                for (int mt = 0; mt < 2; mt++)
                    MMA16816(acc[mt][nt], afr[mt][0], afr[mt][1], afr[mt][2], afr[mt][3],
                             bfr[0], bfr[1]);
            }
        }
        __syncthreads();
    }

#pragma unroll
    for (int mt = 0; mt < 2; mt++) {
        int r0 = row0 + warpm * 32 + mt * 16 + gr;
#pragma unroll
        for (int nt = 0; nt < 12; nt++) {
            int cb = warpn * 96 + nt * 8 + cq * 2;
            if (cb < CC) {
                const float2 r0v = *(const float2*)&res[(size_t)r0 * CC + cb];
                const float2 r1v = *(const float2*)&res[(size_t)(r0 + 8) * CC + cb];
                *(float2*)&Cout[(size_t)r0 * CC + cb] =
                    make_float2(acc[mt][nt][0] + r0v.x, acc[mt][nt][1] + r0v.y);
                *(float2*)&Cout[(size_t)(r0 + 8) * CC + cb] =
                    make_float2(acc[mt][nt][2] + r1v.x, acc[mt][nt][3] + r1v.y);
            }
        }
    }
}

// ======== MMA window attention: 1 block/window, 12 warps = 2 per head ========
__global__ void __launch_bounds__(384) attn_mma(const bf16* __restrict__ qkv,
                                                const float* __restrict__ b_rel,
                                                bf16* __restrict__ out) {
    extern __shared__ bf16 smA[];
    bf16* Qs = smA;                    // [6*64][40]
    bf16* Ks = Qs + 6 * 64 * 40;       // [6*64][40]
    bf16* Vs = Ks + 6 * 64 * 40;       // [6*32][72]
    const int w = blockIdx.x;
    const int b  = w >> 10;
    const int wy = (w & 1023) >> 5;
    const int wx = w & 31;
    const int tid = threadIdx.x;       // 384
    const float scale = 0.18257418583505536f;  // 30^-0.5

    for (int idx = tid; idx < 6 * 64 * 16; idx += 384) {
        int h   = idx >> 10;
        int rem = idx & 1023;
        int t   = rem >> 4;
        int dp  = rem & 15;
        int ty = t >> 3, tx = t & 7;
        size_t row = ((size_t)b << 16) + (size_t)(wy * 8 + ty) * 256 + (wx * 8 + tx);
        const bf16* base = qkv + row * 540 + h * HDIM + 2 * dp;
        uint32_t qv = 0, kw = 0;
        __nv_bfloat162 vp; vp.x = __float2bfloat16(0.f); vp.y = vp.x;
        if (dp < 15) {
            __nv_bfloat162 q2 = *(const __nv_bfloat162*)base;
            qv = pk_bf2(__bfloat162float(q2.x) * scale, __bfloat162float(q2.y) * scale);
            kw = *(const uint32_t*)(base + 180);
            vp = *(const __nv_bfloat162*)(base + 360);
        }
        *(uint32_t*)&Qs[(h * 64 + t) * 40 + 2 * dp] = qv;
        *(uint32_t*)&Ks[(h * 64 + t) * 40 + 2 * dp] = kw;
        Vs[(h * 32 + 2 * dp)     * 72 + t] = vp.x;
        Vs[(h * 32 + 2 * dp + 1) * 72 + t] = vp.y;
    }
    for (int idx = tid; idx < 64 * 12; idx += 384) {
        int t = idx / 12, c = idx - t * 12;
        int ty = t >> 3, tx = t & 7;
        size_t row = ((size_t)b << 16) + (size_t)(wy * 8 + ty) * 256 + (wx * 8 + tx);
        out[row * KP1 + 180 + c] = __float2bfloat16(0.f);
    }
    __syncthreads();

    const int wid  = tid >> 5;
    const int lane = tid & 31;
    const int h     = wid >> 1;
    const int mbase = (wid & 1) * 32;
    const int gr = lane >> 2;
    const int cq = lane & 3;

    const int li = lane >> 3, lj = lane & 7;
    const int arow = (li & 1) * 8 + lj;
    const int acol = (li >> 1) * 8;
    const int brow = lj;
    const int bcol = (li & 1) * 8;

    uint32_t sQ = (uint32_t)__cvta_generic_to_shared(Qs);
    uint32_t sK = (uint32_t)__cvta_generic_to_shared(Ks);
    uint32_t sV = (uint32_t)__cvta_generic_to_shared(Vs);

    uint32_t qf[2][2][4];
#pragma unroll
    for (int mt = 0; mt < 2; mt++)
#pragma unroll
        for (int kk = 0; kk < 2; kk++) {
            uint32_t ad = sQ + (uint32_t)((h * 64 + mbase + mt * 16 + arow) * 40 + kk * 16 + acol) * 2;
            LDSM4(qf[mt][kk], ad);
        }

    float sacc[2][8][4];
#pragma unroll
    for (int mt = 0; mt < 2; mt++)
#pragma unroll
        for (int nt = 0; nt < 8; nt++)
#pragma unroll
            for (int c = 0; c < 4; c++) sacc[mt][nt][c] = 0.f;

#pragma unroll
    for (int nt = 0; nt < 8; nt++) {
        uint32_t kf[2][2];
#pragma unroll
        for (int kk = 0; kk < 2; kk++) {
            uint32_t ad = sK + (uint32_t)((h * 64 + nt * 8 + brow) * 40 + kk * 16 + bcol) * 2;
            LDSM2(kf[kk], ad);
        }
#pragma unroll
        for (int mt = 0; mt < 2; mt++)
#pragma unroll
            for (int kk = 0; kk < 2; kk++)
                MMA16816(sacc[mt][nt], qf[mt][kk][0], qf[mt][kk][1], qf[mt][kk][2], qf[mt][kk][3],
                         kf[kk][0], kf[kk][1]);
    }

    const float* brh = b_rel + h * 4096;
    float l0[2] = {0.f, 0.f}, l1[2] = {0.f, 0.f};
#pragma unroll
    for (int mt = 0; mt < 2; mt++) {
        int r = mbase + mt * 16 + gr;
#pragma unroll
        for (int nt = 0; nt < 8; nt++) {
            int cb = nt * 8 + cq * 2;
            float2 br0 = *(const float2*)&brh[r * 64 + cb];
            float2 br1 = *(const float2*)&brh[(r + 8) * 64 + cb];
            float e0 = __expf(sacc[mt][nt][0] + br0.x);
            float e1 = __expf(sacc[mt][nt][1] + br0.y);
            float e2 = __expf(sacc[mt][nt][2] + br1.x);
            float e3 = __expf(sacc[mt][nt][3] + br1.y);
            sacc[mt][nt][0] = e0; sacc[mt][nt][1] = e1;
            sacc[mt][nt][2] = e2; sacc[mt][nt][3] = e3;
            l0[mt] += e0 + e1;
            l1[mt] += e2 + e3;
        }
    }
#pragma unroll
    for (int o = 1; o <= 2; o <<= 1) {
#pragma unroll
        for (int mt = 0; mt < 2; mt++) {
            l0[mt] += __shfl_xor_sync(0xffffffffu, l0[mt], o);
            l1[mt] += __shfl_xor_sync(0xffffffffu, l1[mt], o);
        }
    }
    float inv0[2], inv1[2];
#pragma unroll
    for (int mt = 0; mt < 2; mt++) { inv0[mt] = 1.f / l0[mt]; inv1[mt] = 1.f / l1[mt]; }

    uint32_t pb[2][4][4];
#pragma unroll
    for (int mt = 0; mt < 2; mt++)
#pragma unroll
        for (int kc = 0; kc < 4; kc++) {
            int n0 = 2 * kc, n1 = 2 * kc + 1;
            pb[mt][kc][0] = pk_bf2(sacc[mt][n0][0] * inv0[mt], sacc[mt][n0][1] * inv0[mt]);
            pb[mt][kc][1] = pk_bf2(sacc[mt][n0][2] * inv1[mt], sacc[mt][n0][3] * inv1[mt]);
            pb[mt][kc][2] = pk_bf2(sacc[mt][n1][0] * inv0[mt], sacc[mt][n1][1] * inv0[mt]);
            pb[mt][kc][3] = pk_bf2(sacc[mt][n1][2] * inv1[mt], sacc[mt][n1][3] * inv1[mt]);
        }

    float oacc[2][4][4];
#pragma unroll
    for (int mt = 0; mt < 2; mt++)
#pragma unroll
        for (int nt = 0; nt < 4; nt++)
#pragma unroll
            for (int c = 0; c < 4; c++) oacc[mt][nt][c] = 0.f;

#pragma unroll
    for (int nt = 0; nt < 4; nt++) {
        uint32_t vf[4][2];
#pragma unroll
        for (int kc = 0; kc < 4; kc++) {
            uint32_t ad = sV + (uint32_t)((h * 32 + nt * 8 + brow) * 72 + kc * 16 + bcol) * 2;
            LDSM2(vf[kc], ad);
        }
#pragma unroll
        for (int mt = 0; mt < 2; mt++)
#pragma unroll
            for (int kc = 0; kc < 4; kc++)
                MMA16816(oacc[mt][nt], pb[mt][kc][0], pb[mt][kc][1], pb[mt][kc][2], pb[mt][kc][3],
                         vf[kc][0], vf[kc][1]);
    }

#pragma unroll
    for (int mt = 0; mt < 2; mt++) {
        int r = mbase + mt * 16 + gr;
        size_t rg0 = ((size_t)b << 16) + (size_t)(wy * 8 + (r >> 3)) * 256 + (wx * 8 + (r & 7));
        int r8 = r + 8;
        size_t rg1 = ((size_t)b << 16) + (size_t)(wy * 8 + (r8 >> 3)) * 256 + (wx * 8 + (r8 & 7));
#pragma unroll
        for (int nt = 0; nt < 4; nt++) {
            int cb = nt * 8 + cq * 2;
            if (cb < HDIM) {
                __nv_bfloat162 p0, p1;
                p0.x = __float2bfloat16(oacc[mt][nt][0]); p0.y = __float2bfloat16(oacc[mt][nt][1]);
                p1.x = __float2bfloat16(oacc[mt][nt][2]); p1.y = __float2bfloat16(oacc[mt][nt][3]);
                *(__nv_bfloat162*)&out[rg0 * KP1 + h * HDIM + cb] = p0;
                *(__nv_bfloat162*)&out[rg1 * KP1 + h * HDIM + cb] = p1;
            }
        }
    }
}

// ---------------- depthwise 3x3 SAME conv, x-tiled (TX) + rolling-y ----------------
template <typename Tin, typename Tout, int CD, int INS, int OUTS, int GELU, int POOL, int TX>
__global__ void dwconv_tile(const Tin* __restrict__ in,
                            const float* __restrict__ k9,
                            Tout* __restrict__ out,
                            float* __restrict__ pooled) {
    const int c  = threadIdx.x;
    const int x0 = blockIdx.x * TX;
    const int y0 = blockIdx.y * 64;
    const int b  = blockIdx.z;
    float w[9];
#pragma unroll
    for (int i = 0; i < 9; i++) w[i] = k9[c * 9 + i];

    const size_t base = ((size_t)b << 16);
    float r[TX + 2], s[TX + 2], t[TX + 2];

    auto loadrow = [&](int yy, float* dst) {
#pragma unroll
        for (int i = 0; i < TX + 2; i++) {
            int xx = x0 - 1 + i;
            dst[i] = (xx >= 0 && xx < WWID)
                     ? (float)in[(base + (size_t)yy * 256 + xx) * INS + c] : 0.f;
        }
    };

    if (y0 > 0) loadrow(y0 - 1, r);
    else {
#pragma unroll
        for (int i = 0; i < TX + 2; i++) r[i] = 0.f;
    }
    loadrow(y0, s);

    float psum = 0.f;
    for (int yy = y0; yy < y0 + 64; yy++) {
        if (yy + 1 < HH) loadrow(yy + 1, t);
        else {
#pragma unroll
            for (int i = 0; i < TX + 2; i++) t[i] = 0.f;
        }
#pragma unroll
        for (int j = 0; j < TX; j++) {
            float acc = r[j] * w[0] + r[j + 1] * w[1] + r[j + 2] * w[2]
                      + s[j] * w[3] + s[j + 1] * w[4] + s[j + 2] * w[5]
                      + t[j] * w[6] + t[j + 1] * w[7] + t[j + 2] * w[8];
            if (GELU) acc = gelu_exact(acc);
            if (POOL) psum += acc;
            size_t op = (base + (size_t)yy * 256 + x0 + j) * OUTS;
            out[op + c] = (Tout)acc;
            if (OUTS > CD && c < OUTS - CD) out[op + CD + c] = (Tout)0.f;
        }
#pragma unroll
        for (int i = 0; i < TX + 2; i++) { r[i] = s[i]; s[i] = t[i]; }
    }
    if (POOL) atomicAdd(&pooled[b * CD + c], psum * (1.f / (float)LL));
}

// ---------------- channel gate ----------------
__global__ void gate_kernel(const float* __restrict__ pooled,
                            const float* __restrict__ w1,
                            const float* __restrict__ w2,
                            float* __restrict__ cm) {
    const int b = blockIdx.x;
    const int tid = threadIdx.x;   // 180
    __shared__ float t1[C8];
    if (tid < C8) {
        float s = 0.f;
        for (int c = 0; c < CC; c++) s += pooled[b * CC + c] * w1[tid * CC + c];
        t1[tid] = gelu_exact(s);
    }
    __syncthreads();
    float s = 0.f;
#pragma unroll
    for (int j = 0; j < C8; j++) s += t1[j] * w2[tid * C8 + j];
    cm[b * CC + tid] = 1.f / (1.f + expf(-s));
}

// ---------------- launch ----------------
extern "C" void kernel_launch(void* const* d_in, const int* in_sizes, int n_in,
                              void* d_out, int out_size) {
    const float* x       = (const float*)d_in[0];
    const float* w_qkv   = (const float*)d_in[1];
    const float* b_rel   = (const float*)d_in[2];
    const float* w_proj  = (const float*)d_in[3];
    const float* b_proj  = (const float*)d_in[4];
    const float* conv_dw = (const float*)d_in[5];
    const float* cg_w1   = (const float*)d_in[6];
    const float* cg_w2   = (const float*)d_in[7];
    const float* ffn_w1  = (const float*)d_in[8];
    const float* ffn_dw  = (const float*)d_in[9];
    const float* ffn_w2  = (const float*)d_in[10];
    const float* n1_g    = (const float*)d_in[11];
    const float* n1_b    = (const float*)d_in[12];
    const float* n2_g    = (const float*)d_in[13];
    const float* n2_b    = (const float*)d_in[14];
    float* out = (float*)d_out;

    float *xmid, *pooled, *cm;
    bf16 *qkvb, *attnf, *conv, *n1b, *n2b, *hsb, *wb;
    cudaGetSymbolAddress((void**)&qkvb,  g_qkvb);
    cudaGetSymbolAddress((void**)&attnf, g_attnf);
    cudaGetSymbolAddress((void**)&conv,  g_conv);
    cudaGetSymbolAddress((void**)&xmid,  g_xmid);
    cudaGetSymbolAddress((void**)&pooled, g_pooled);
    cudaGetSymbolAddress((void**)&cm,     g_cm);
    cudaGetSymbolAddress((void**)&n1b,   g_n1b);
    cudaGetSymbolAddress((void**)&n2b,   g_n2b);
    cudaGetSymbolAddress((void**)&hsb,   g_hsb);
    cudaGetSymbolAddress((void**)&wb,    g_wb);

    const int PSMEM1    = (128 * (KP1 + 8) + 2 * 64 * (KP1 + 8)) * (int)sizeof(bf16); // 102400
    const int RES2_SMEM = (2 * 128 * 40 + 2 * 192 * 40) * (int)sizeof(bf16);          // 51200
    const int ATTN_SMEM = (2 * 6 * 64 * 40 + 6 * 32 * 72) * (int)sizeof(bf16);        // 89088
    cudaFuncSetAttribute((const void*)mma_gemm_p<0,1>, cudaFuncAttributeMaxDynamicSharedMemorySize, PSMEM1);
    cudaFuncSetAttribute((const void*)mma_gemm_p<1,1>, cudaFuncAttributeMaxDynamicSharedMemorySize, PSMEM1);
    cudaFuncSetAttribute((const void*)mma_gemm_p<2,1>, cudaFuncAttributeMaxDynamicSharedMemorySize, PSMEM1);
    cudaFuncSetAttribute((const void*)mma_gemm_res2,   cudaFuncAttributeMaxDynamicSharedMemorySize, RES2_SMEM);
    cudaFuncSetAttribute((const void*)attn_mma,        cudaFuncAttributeMaxDynamicSharedMemorySize, ATTN_SMEM);

    // 0) convert + pad weights to bf16
    convw_kernel<<<(576 * 192 + 255) / 256, 256>>>(w_qkv,  wb + WB_QKV,  540, 180, 576, 192);
    convw_kernel<<<(192 * 192 + 255) / 256, 256>>>(w_proj, wb + WB_PROJ, 180, 180, 192, 192);
    convw_kernel<<<(384 * 192 + 255) / 256, 256>>>(ffn_w1, wb + WB_FFN1, 360, 180, 384, 192);
    convw_kernel<<<(192 * 384 + 255) / 256, 256>>>(ffn_w2, wb + WB_FFN2, 180, 360, 192, 384);

    // 1) ln1: x -> n1b (bf16, padded)
    ln_kernel<<<MROWS / 4, 128>>>(x, n1_g, n1_b, n1b);

    // 2) qkv = n1 @ w_qkv^T  (bf16 out, N=540, stride 540, 9 n-tiles)
    mma_gemm_p<0,1><<<MROWS / 128, 256, PSMEM1>>>(n1b, wb + WB_QKV, nullptr, nullptr, qkvb, 540, KP1, 540, 9);

    // 3) MMA window attention -> n2b (bf16, padded)
    attn_mma<<<NWIN, 384, ATTN_SMEM>>>(qkvb, b_rel, n2b);

    // 4) proj: attnf = attn @ w_proj^T + b_proj  (bf16 out, stride 180)
    mma_gemm_p<1,1><<<MROWS / 128, 256, PSMEM1>>>(n2b, wb + WB_PROJ, b_proj, nullptr, attnf, 180, KP1, 180, 3);

    // 5) conv branch: dwconv(n1b)+GELU -> conv (bf16), fused mean-pool (fp32)
    cudaMemsetAsync(pooled, 0, BB * CC * sizeof(float));
    dwconv_tile<bf16, bf16, CC, KP1, CC, 1, 1, 4><<<dim3(WWID / 4, 4, BB), CC>>>(n1b, conv_dw, conv, pooled);

    // 6) channel gate -> cm
    gate_kernel<<<BB, CC>>>(pooled, cg_w1, cg_w2, cm);

    // 7) fused residual + ln2: xmid (fp32), n2 -> n2b (bf16)
    resid_ln_kernel<<<MROWS / 4, 128>>>(x, attnf, conv, cm, n2_g, n2_b, xmid, n2b);

    // 8) ffn1: h = gelu(n2 @ ffn_w1^T) -> qkvb buffer (bf16, stride 384, N=360)
    mma_gemm_p<2,1><<<MROWS / 128, 256, PSMEM1>>>(n2b, wb + WB_FFN1, nullptr, nullptr, qkvb, 360, KP1, 384, 6);

    // 9) ffn dwconv: hsb = dwconv(h) (bf16 in stride 384, bf16 out padded 384)
    dwconv_tile<bf16, bf16, CFFN, KP2, KP2, 0, 0, 4><<<dim3(WWID / 4, 4, BB), CFFN>>>(qkvb, ffn_dw, hsb, nullptr);

    // 10) ffn2 + residual: out = xmid + hsb @ ffn_w2^T  (full-N pipelined, A read once)
    mma_gemm_res2<<<MROWS / 128, 256, RES2_SMEM>>>(hsb, wb + WB_FFN2, xmid, out);
}